// round 11
// baseline (speedup 1.0000x reference)
#include <cuda_runtime.h>
#include <cuda_bf16.h>
#include <math.h>

#define HW 65536
#define IMG 256
#define CB 96
#define BATCH 4

// ---------------- device scratch ----------------
__device__ float g_mean[BATCH], g_istd[BATCH];
__device__ float g_rescale[BATCH][CB], g_rebias[BATCH][CB];
__device__ float g_partial[BATCH][192][2];
__device__ float g_bias_tab[3][64][64];

__device__ __nv_bfloat16 g_y  [(size_t)BATCH*CB*HW];
__device__ __nv_bfloat16 g_qkv[(size_t)BATCH*3*CB*HW];
__device__ __nv_bfloat16 g_co [(size_t)BATCH*CB*HW];
__device__ __nv_bfloat16 g_attn[(size_t)BATCH*HW*CB];
__device__ float         g_x2 [(size_t)BATCH*CB*HW];
__device__ __nv_bfloat16 g_hid[(size_t)BATCH*4*CB*HW];

#define SCALEV 0.17677669529663687f
#define LOGIT_MAXV 4.605170185988091f

// ---------------- f32x2 helpers ----------------
__device__ __forceinline__ unsigned long long pack2(float w){
  unsigned long long r; asm("mov.b64 %0, {%1, %1};" : "=l"(r) : "f"(w)); return r;
}
__device__ __forceinline__ float2 u2f(unsigned long long v){
  float2 f; asm("mov.b64 {%0, %1}, %2;" : "=f"(f.x), "=f"(f.y) : "l"(v)); return f;
}
__device__ __forceinline__ void ffma2(unsigned long long &d, unsigned long long a, unsigned long long b){
  asm("fma.rn.f32x2 %0, %1, %2, %0;" : "+l"(d) : "l"(a), "l"(b));
}

// ---------------- mma helpers ----------------
__device__ __forceinline__ void ldsm_x4(unsigned addr, unsigned &r0, unsigned &r1, unsigned &r2, unsigned &r3){
  asm volatile("ldmatrix.sync.aligned.m8n8.x4.shared.b16 {%0,%1,%2,%3}, [%4];"
    : "=r"(r0),"=r"(r1),"=r"(r2),"=r"(r3) : "r"(addr));
}
__device__ __forceinline__ void ldsm_x4_t(unsigned addr, unsigned &r0, unsigned &r1, unsigned &r2, unsigned &r3){
  asm volatile("ldmatrix.sync.aligned.m8n8.x4.trans.shared.b16 {%0,%1,%2,%3}, [%4];"
    : "=r"(r0),"=r"(r1),"=r"(r2),"=r"(r3) : "r"(addr));
}
__device__ __forceinline__ void ldsm_x2(unsigned addr, unsigned &r0, unsigned &r1){
  asm volatile("ldmatrix.sync.aligned.m8n8.x2.shared.b16 {%0,%1}, [%2];"
    : "=r"(r0),"=r"(r1) : "r"(addr));
}
__device__ __forceinline__ void mma16816(float* c, const unsigned* a, const unsigned* b){
  asm volatile("mma.sync.aligned.m16n8k16.row.col.f32.bf16.bf16.f32 "
    "{%0,%1,%2,%3},{%4,%5,%6,%7},{%8,%9},{%0,%1,%2,%3};"
    : "+f"(c[0]),"+f"(c[1]),"+f"(c[2]),"+f"(c[3])
    : "r"(a[0]),"r"(a[1]),"r"(a[2]),"r"(a[3]),"r"(b[0]),"r"(b[1]));
}
__device__ __forceinline__ unsigned bf2u(float x, float y){
  __nv_bfloat162 t = __floats2bfloat162_rn(x, y);
  return reinterpret_cast<unsigned&>(t);
}

// ---------------- K1: per-sample partial sums ----------------
__global__ void k_reduce_partial(const float* __restrict__ x){
  int b = blockIdx.y, blk = blockIdx.x, tid = threadIdx.x;
  const float4* xb = (const float4*)(x + (size_t)b*CB*HW);
  size_t base = (size_t)blk*8192;
  float s=0.f, s2=0.f;
  for (int i=tid;i<8192;i+=256){
    float4 v = xb[base+i];
    s  += v.x+v.y+v.z+v.w;
    s2 += v.x*v.x+v.y*v.y+v.z*v.z+v.w*v.w;
  }
  __shared__ float rs[256], rq[256];
  rs[tid]=s; rq[tid]=s2; __syncthreads();
  for (int st=128;st>0;st>>=1){
    if (tid<st){ rs[tid]+=rs[tid+st]; rq[tid]+=rq[tid+st]; }
    __syncthreads();
  }
  if (tid==0){ g_partial[b][blk][0]=rs[0]; g_partial[b][blk][1]=rq[0]; }
}

// ---------------- K2: finalize ----------------
__global__ void k_finalize(const float* __restrict__ m1w, const float* __restrict__ m1b,
                           const float* __restrict__ m2w, const float* __restrict__ m2b){
  int b = blockIdx.x, tid = threadIdx.x;
  __shared__ float rs[256], rq[256];
  rs[tid] = (tid<192)? g_partial[b][tid][0] : 0.f;
  rq[tid] = (tid<192)? g_partial[b][tid][1] : 0.f;
  __syncthreads();
  for (int st=128;st>0;st>>=1){
    if (tid<st){ rs[tid]+=rs[tid+st]; rq[tid]+=rq[tid+st]; }
    __syncthreads();
  }
  __shared__ float sh_mean, sh_std;
  if (tid==0){
    float M = (float)((size_t)CB*HW);
    float mean = rs[0]/M;
    float var  = rq[0]/M - mean*mean;
    float sd   = sqrtf(var + 1e-5f);
    g_mean[b]=mean; g_istd[b]=1.f/sd;
    sh_mean=mean; sh_std=sd;
  }
  __syncthreads();
  if (tid<CB){
    g_rescale[b][tid] = sh_std *m1w[tid] + m1b[tid];
    g_rebias [b][tid] = sh_mean*m2w[tid] + m2b[tid];
  }
}

// ---------------- K3: relative-position bias table ----------------
__global__ void k_bias(const float* __restrict__ w1, const float* __restrict__ b1,
                       const float* __restrict__ w2, const float* __restrict__ b2){
  int n = blockIdx.x, m = threadIdx.x;
  float di = (float)((n>>3) - (m>>3));
  float dj = (float)((n&7) - (m&7));
  float a0l = log1pf(fabsf(di)); float r0 = di<0.f ? -a0l : (di>0.f ? a0l : 0.f);
  float a1l = log1pf(fabsf(dj)); float r1 = dj<0.f ? -a1l : (dj>0.f ? a1l : 0.f);
  float a0=0.f,a1=0.f,a2=0.f;
  for (int k=0;k<256;k++){
    float h = fmaxf(r0*w1[2*k]+r1*w1[2*k+1]+b1[k], 0.f);
    a0 += h*w2[k]; a1 += h*w2[256+k]; a2 += h*w2[512+k];
  }
  g_bias_tab[0][n][m]=a0+b2[0];
  g_bias_tab[1][n][m]=a1+b2[1];
  g_bias_tab[2][n][m]=a2+b2[2];
}

// ---------------- K4: fused AGN (kept from R5/R6) ----------------
__global__ void __launch_bounds__(256) k_agn_fused(const float* __restrict__ x,
    const float* __restrict__ agnw, const float* __restrict__ agnb,
    const float* __restrict__ la1w, const float* __restrict__ la1b,
    const float* __restrict__ la2w, const float* __restrict__ la2b,
    const float* __restrict__ ta1w, const float* __restrict__ ta1b,
    const float* __restrict__ ta2w, const float* __restrict__ ta2b){
  __shared__ float xt[12*136];
  __shared__ __align__(8) float2 tb[10*136];
  int bc = blockIdx.z; int b = bc/CB, c = bc - b*CB;
  const float* xb = x + (size_t)bc*HW;
  float mean = g_mean[b], istd = g_istd[b];
  int x0 = blockIdx.x*128, y0 = blockIdx.y*8;
  int tid = threadIdx.x;

  for (int i=tid; i<12*136; i+=256){
    int ry = i/136, cc = i-ry*136;
    int gy = y0+ry-2, gx = x0+cc-2;
    float v = 0.f;
    if ((unsigned)gy<256u && (unsigned)gx<256u) v = (xb[gy*256+gx]-mean)*istd;
    xt[ry*136 + ((cc&3)*34 + (cc>>2))] = v;
  }
  float w1l[9], w1t[9];
  #pragma unroll
  for (int k=0;k<9;k++){ w1l[k]=la1w[c*9+k]; w1t[k]=ta1w[c*9+k]; }
  float b1l=la1b[c], b1t=ta1b[c];
  __syncthreads();

  for (int run=tid; run<330; run+=256){
    int r = run/33, rn = run - r*33;
    float al[4], at[4];
    #pragma unroll
    for (int o=0;o<4;o++){ al[o]=b1l; at[o]=b1t; }
    #pragma unroll
    for (int dy=0;dy<3;dy++){
      const float* xr = xt + (r+dy)*136;
      float v[6];
      v[0]=xr[rn]; v[1]=xr[34+rn]; v[2]=xr[68+rn]; v[3]=xr[102+rn];
      v[4]=xr[rn+1]; v[5]=xr[34+rn+1];
      #pragma unroll
      for (int o=0;o<4;o++){
        al[o] += v[o]*w1l[dy*3] + v[o+1]*w1l[dy*3+1] + v[o+2]*w1l[dy*3+2];
        at[o] += v[o]*w1t[dy*3] + v[o+1]*w1t[dy*3+1] + v[o+2]*w1t[dy*3+2];
      }
    }
    float2* tr = tb + r*136;
    #pragma unroll
    for (int o=0;o<4;o++)
      tr[o*34+rn] = make_float2(fmaxf(al[o],0.f), fmaxf(at[o],0.f));
  }
  __syncthreads();

  float w2l[9], w2t[9];
  #pragma unroll
  for (int k=0;k<9;k++){ w2l[k]=la2w[c*9+k]; w2t[k]=ta2w[c*9+k]; }
  int tx = tid&31, ty = tid>>5;
  float acc[4];
  float base2 = la2b[c] + ta2b[c];
  #pragma unroll
  for (int o=0;o<4;o++) acc[o]=base2;
  #pragma unroll
  for (int dy=0;dy<3;dy++){
    const float2* tr = tb + (ty+dy)*136;
    float2 t0=tr[tx], t1=tr[34+tx], t2=tr[68+tx], t3=tr[102+tx];
    float2 t4=tr[tx+1], t5=tr[34+tx+1];
    float2 tv[6] = {t0,t1,t2,t3,t4,t5};
    #pragma unroll
    for (int o=0;o<4;o++){
      #pragma unroll
      for (int dx=0;dx<3;dx++){
        float2 v = tv[o+dx];
        acc[o] += v.x*w2l[dy*3+dx] + v.y*w2t[dy*3+dx];
      }
    }
  }
  float sc = agnw[c]*g_rescale[b][c];
  float sb = agnb[c]+g_rebias[b][c];
  const float* xnr = xt + (ty+2)*136;
  float xn0 = xnr[68+tx], xn1 = xnr[102+tx], xn2 = xnr[tx+1], xn3 = xnr[34+tx+1];
  float r0 = xn0*sc + sb + acc[0];
  float r1 = xn1*sc + sb + acc[1];
  float r2 = xn2*sc + sb + acc[2];
  float r3 = xn3*sc + sb + acc[3];
  uint2 u; u.x = bf2u(r0,r1); u.y = bf2u(r2,r3);
  *(uint2*)(g_y + (size_t)bc*HW + (size_t)(y0+ty)*256 + x0 + 4*tx) = u;
}

// ---------------- K6: 5x5 reflect dwconv on Q ----------------
__global__ void k_co5(const float* __restrict__ dww, const float* __restrict__ dwb){
  int bc=blockIdx.z; int b=bc/CB, c=bc-b*CB;
  const __nv_bfloat16* Q = g_qkv + ((size_t)b*3*CB + c)*HW;
  __shared__ float tile[12][36];
  int x0=blockIdx.x*32, y0=blockIdx.y*8;
  int tid=threadIdx.y*32+threadIdx.x;
  for (int i=tid;i<432;i+=256){
    int ry=i/36, rx=i-ry*36;
    int gy=y0+ry-2, gx=x0+rx-2;
    gy = gy<0 ? -gy : (gy>255 ? 510-gy : gy);
    gx = gx<0 ? -gx : (gx>255 ? 510-gx : gx);
    tile[ry][rx] = __bfloat162float(Q[gy*256+gx]);
  }
  __syncthreads();
  float w[25];
  #pragma unroll
  for (int k=0;k<25;k++) w[k]=dww[c*25+k];
  float acc = dwb[c];
  #pragma unroll
  for (int ky=0;ky<5;ky++)
    #pragma unroll
    for (int kx=0;kx<5;kx++)
      acc += tile[threadIdx.y+ky][threadIdx.x+kx]*w[ky*5+kx];
  g_co[(size_t)bc*HW + (size_t)(y0+threadIdx.y)*256 + x0+threadIdx.x] = __float2bfloat16(acc);
}

// =====================================================================
// Tensor-core GEMM bodies
// =====================================================================
#define SMEM_MMA 50688

// ---- single-group body (staged epilogue) — proj, m2 ----
template<int LOAD, int EPI>
__device__ __forceinline__ void mma_body(
    const void* actb, const float* W, const float* bias,
    int CinTot, int wrow0, void* outv,
    const float* xinb, int bIdx)
{
  extern __shared__ char smem_raw[];
  __nv_bfloat16* sA = (__nv_bfloat16*)smem_raw;
  __nv_bfloat16* sW = (__nv_bfloat16*)(smem_raw + (LOAD==2 ? 26624 : 24576));
  float* sStage = (float*)smem_raw;
  const int tid = threadIdx.x;
  const int px0 = blockIdx.x * 128;
  const int warp = tid >> 5, t = tid & 31;
  const int m0w = (warp>>1)*32, n0w = (warp&1)*48;
  unsigned sAb = (unsigned)__cvta_generic_to_shared(sA);
  unsigned sWb = (unsigned)__cvta_generic_to_shared(sW);

  float acc[2][6][4];
  #pragma unroll
  for (int mi=0;mi<2;mi++)
    #pragma unroll
    for (int nj=0;nj<6;nj++)
      #pragma unroll
      for (int e=0;e<4;e++) acc[mi][nj][e]=0.f;

  const int g = t>>3, gi = t&7;
  const int t15 = t&15;

  for (int k0g=0; k0g<CinTot; k0g+=96){
    if (LOAD==0){
      const float* a = (const float*)actb;
      #pragma unroll
      for (int j=0;j<12;j++){
        int i = tid + 256*j;
        int c = i>>5, px = (i&31)*4;
        float4 v = *(const float4*)(a + (size_t)(k0g+c)*HW + px0 + px);
        uint2 u; u.x = bf2u(v.x,v.y); u.y = bf2u(v.z,v.w);
        *(uint2*)(sA + c*128 + ((((px>>3)^(c&7))<<3) + (px&7))) = u;
      }
    } else if (LOAD==1){
      const __nv_bfloat16* a = (const __nv_bfloat16*)actb;
      #pragma unroll
      for (int j=0;j<6;j++){
        int i = tid + 256*j;
        int c = i>>4, s8 = (i&15)*8;
        uint4 v = *(const uint4*)(a + (size_t)(k0g+c)*HW + px0 + s8);
        *(uint4*)(sA + c*128 + ((((s8>>3)^(c&7))<<3))) = v;
      }
    } else {
      const __nv_bfloat16* a = (const __nv_bfloat16*)actb + (size_t)px0*96;
      #pragma unroll
      for (int j=0;j<6;j++){
        int i = tid + 256*j;
        int px = i/12, c0 = (i%12)*8;
        uint4 v = *(const uint4*)(a + (size_t)px*96 + c0);
        *(uint4*)(sA + px*104 + c0) = v;
      }
    }
    #pragma unroll
    for (int j=0;j<9;j++){
      int i = tid + 256*j;
      int r = i/24, c4 = (i%24)*4;
      float4 v = *(const float4*)(W + (size_t)(wrow0+r)*CinTot + k0g + c4);
      uint2 u; u.x = bf2u(v.x,v.y); u.y = bf2u(v.z,v.w);
      *(uint2*)(sW + r*104 + c4) = u;
    }
    __syncthreads();

    unsigned addrA[2], addrB[6];
    if (LOAD==2){
      int row0 = m0w + (g&1)*8 + gi;
      int kc = (g>=2)?16:0;
      addrA[0] = sAb + (row0     )*208 + kc;
      addrA[1] = sAb + (row0 + 16)*208 + kc;
    } else {
      int kb = ((g>=2)?8:0) + gi;
      int px_a0 = m0w + (g&1)*8;
      int px_a1 = px_a0 + 16;
      addrA[0] = sAb + kb*256 + ((((px_a0>>3) ^ gi)<<4));
      addrA[1] = sAb + kb*256 + ((((px_a1>>3) ^ gi)<<4));
    }
    {
      int n = n0w + (t15&7);
      int kc = (t15>>3)*8;
      #pragma unroll
      for (int nj=0;nj<6;nj++) addrB[nj] = sWb + (n + nj*8)*208 + kc*2;
    }

    #pragma unroll
    for (int ks=0; ks<6; ks++){
      unsigned a[2][4], bfr[6][2];
      if (LOAD==2){ ldsm_x4(addrA[0], a[0][0],a[0][1],a[0][2],a[0][3]);
                    ldsm_x4(addrA[1], a[1][0],a[1][1],a[1][2],a[1][3]); }
      else        { ldsm_x4_t(addrA[0], a[0][0],a[0][1],a[0][2],a[0][3]);
                    ldsm_x4_t(addrA[1], a[1][0],a[1][1],a[1][2],a[1][3]); }
      #pragma unroll
      for (int nj=0;nj<6;nj++) ldsm_x2(addrB[nj], bfr[nj][0], bfr[nj][1]);
      #pragma unroll
      for (int mi=0;mi<2;mi++)
        #pragma unroll
        for (int nj=0;nj<6;nj++)
          mma16816(acc[mi][nj], a[mi], bfr[nj]);
      if (LOAD==2){ addrA[0]+=32; addrA[1]+=32; }
      else        { addrA[0]+=4096; addrA[1]+=4096; }
      #pragma unroll
      for (int nj=0;nj<6;nj++) addrB[nj]+=32;
    }
    __syncthreads();
  }

  #pragma unroll
  for (int mi=0;mi<2;mi++)
    #pragma unroll
    for (int nj=0;nj<6;nj++){
      int m = m0w + mi*16 + (t>>2);
      int n = n0w + nj*8 + (t&3)*2;
      sStage[(n  )*132 + m  ] = acc[mi][nj][0];
      sStage[(n+1)*132 + m  ] = acc[mi][nj][1];
      sStage[(n  )*132 + m+8] = acc[mi][nj][2];
      sStage[(n+1)*132 + m+8] = acc[mi][nj][3];
    }
  __syncthreads();

  const int tx = tid&31, ty = tid>>5;
  #pragma unroll
  for (int r=0;r<12;r++){
    int o = ty*12 + r;
    float4 v = *(float4*)(sStage + o*132 + tx*4);
    float bv = bias[wrow0+o];
    v.x+=bv; v.y+=bv; v.z+=bv; v.w+=bv;
    size_t off = (size_t)o*HW + px0 + tx*4;
    if (EPI==2){
      float4 q = *(const float4*)(xinb + off);
      v.x+=q.x; v.y+=q.y; v.z+=q.z; v.w+=q.w;
      *(float4*)((float*)outv + off) = v;
    } else if (EPI==3){
      float rs = g_rescale[bIdx][o], rb = g_rebias[bIdx][o];
      float4 xi = *(const float4*)(xinb + off);
      v = make_float4(xi.x + v.x*rs + rb, xi.y + v.y*rs + rb,
                      xi.z + v.z*rs + rb, xi.w + v.w*rs + rb);
      *(float4*)((float*)outv + off) = v;
    } else {
      *(float4*)((float*)outv + off) = v;
    }
  }
}

// ---- multi-group body: act loaded ONCE, loop over weight groups ----
template<int LOAD, int RELU, int GROUPS>
__device__ __forceinline__ void mma_multi(
    const void* actb, const float* const* Wg, const float* const* biasg,
    const int* wrow0g, __nv_bfloat16* const* outg)
{
  extern __shared__ char smem_raw[];
  __nv_bfloat16* sA = (__nv_bfloat16*)smem_raw;
  __nv_bfloat16* sW = (__nv_bfloat16*)(smem_raw + 24576);
  const int tid = threadIdx.x;
  const int px0 = blockIdx.x * 128;
  const int warp = tid >> 5, t = tid & 31;
  const int m0w = (warp>>1)*32, n0w = (warp&1)*48;
  unsigned sAb = (unsigned)__cvta_generic_to_shared(sA);
  unsigned sWb = (unsigned)__cvta_generic_to_shared(sW);
  const int g = t>>3, gi = t&7;
  const int t15 = t&15;

  // ---- load activation tile once ----
  if (LOAD==0){
    const float* a = (const float*)actb;
    #pragma unroll
    for (int j=0;j<12;j++){
      int i = tid + 256*j;
      int c = i>>5, px = (i&31)*4;
      float4 v = *(const float4*)(a + (size_t)c*HW + px0 + px);
      uint2 u; u.x = bf2u(v.x,v.y); u.y = bf2u(v.z,v.w);
      *(uint2*)(sA + c*128 + ((((px>>3)^(c&7))<<3) + (px&7))) = u;
    }
  } else {
    const __nv_bfloat16* a = (const __nv_bfloat16*)actb;
    #pragma unroll
    for (int j=0;j<6;j++){
      int i = tid + 256*j;
      int c = i>>4, s8 = (i&15)*8;
      uint4 v = *(const uint4*)(a + (size_t)c*HW + px0 + s8);
      *(uint4*)(sA + c*128 + ((((s8>>3)^(c&7))<<3))) = v;
    }
  }

  unsigned addrA0[2];
  {
    int kb = ((g>=2)?8:0) + gi;
    int px_a0 = m0w + (g&1)*8;
    int px_a1 = px_a0 + 16;
    addrA0[0] = sAb + kb*256 + ((((px_a0>>3) ^ gi)<<4));
    addrA0[1] = sAb + kb*256 + ((((px_a1>>3) ^ gi)<<4));
  }
  unsigned addrB0;
  {
    int n = n0w + (t15&7);
    int kc = (t15>>3)*8;
    addrB0 = sWb + n*208 + kc*2;
  }

  #pragma unroll
  for (int grp=0; grp<GROUPS; grp++){
    const float* W = Wg[grp];
    int wrow0 = wrow0g[grp];
    #pragma unroll
    for (int j=0;j<9;j++){
      int i = tid + 256*j;
      int r = i/24, c4 = (i%24)*4;
      float4 v = *(const float4*)(W + (size_t)(wrow0+r)*96 + c4);
      uint2 u; u.x = bf2u(v.x,v.y); u.y = bf2u(v.z,v.w);
      *(uint2*)(sW + r*104 + c4) = u;
    }
    __syncthreads();

    float acc[2][6][4];
    #pragma unroll
    for (int mi=0;mi<2;mi++)
      #pragma unroll
      for (int nj=0;nj<6;nj++)
        #pragma unroll
        for (int e=0;e<4;e++) acc[mi][nj][e]=0.f;

    unsigned addrA[2] = {addrA0[0], addrA0[1]};
    unsigned addrB[6];
    #pragma unroll
    for (int nj=0;nj<6;nj++) addrB[nj] = addrB0 + nj*8*208;

    #pragma unroll
    for (int ks=0; ks<6; ks++){
      unsigned a[2][4], bfr[6][2];
      ldsm_x4_t(addrA[0], a[0][0],a[0][1],a[0][2],a[0][3]);
      ldsm_x4_t(addrA[1], a[1][0],a[1][1],a[1][2],a[1][3]);
      #pragma unroll
      for (int nj=0;nj<6;nj++) ldsm_x2(addrB[nj], bfr[nj][0], bfr[nj][1]);
      #pragma unroll
      for (int mi=0;mi<2;mi++)
        #pragma unroll
        for (int nj=0;nj<6;nj++)
          mma16816(acc[mi][nj], a[mi], bfr[nj]);
      addrA[0]+=4096; addrA[1]+=4096;
      #pragma unroll
      for (int nj=0;nj<6;nj++) addrB[nj]+=32;
    }
    __syncthreads();

    const float* bias = biasg[grp];
    __nv_bfloat16* outb = outg[grp];
    #pragma unroll
    for (int nj=0;nj<6;nj++){
      int nl = n0w + nj*8 + (t&3)*2;
      float b0 = __ldg(bias + wrow0g[grp] + nl);
      float b1 = __ldg(bias + wrow0g[grp] + nl + 1);
      #pragma unroll
      for (int mi=0;mi<2;mi++){
        int m = m0w + mi*16 + (t>>2);
        float c0 = acc[mi][nj][0] + b0;
        float c1 = acc[mi][nj][1] + b1;
        float c2 = acc[mi][nj][2] + b0;
        float c3 = acc[mi][nj][3] + b1;
        if (RELU){
          c0=fmaxf(c0,0.f); c1=fmaxf(c1,0.f); c2=fmaxf(c2,0.f); c3=fmaxf(c3,0.f);
        }
        size_t base0 = (size_t)nl*HW + px0 + m;
        size_t base1 = (size_t)(nl+1)*HW + px0 + m;
        outb[base0    ] = __float2bfloat16(c0);
        outb[base1    ] = __float2bfloat16(c1);
        outb[base0 + 8] = __float2bfloat16(c2);
        outb[base1 + 8] = __float2bfloat16(c3);
      }
    }
  }
}

__global__ void __launch_bounds__(256) k_mma_qkv(
    const float* __restrict__ qW, const float* __restrict__ qb,
    const float* __restrict__ kvW, const float* __restrict__ kvb)
{
  int b = blockIdx.z;
  const __nv_bfloat16* actb = g_y + (size_t)b*CB*HW;
  __nv_bfloat16* o0 = g_qkv + ((size_t)b*3*CB + 0 )*HW;
  __nv_bfloat16* o1 = g_qkv + ((size_t)b*3*CB + 96)*HW;
  __nv_bfloat16* o2 = g_qkv + ((size_t)b*3*CB +192)*HW;
  const float* Wg[3]    = {qW, kvW, kvW};
  const float* biasg[3] = {qb, kvb, kvb};
  int wrow0g[3]         = {0, 0, 96};
  __nv_bfloat16* outg[3]= {o0, o1, o2};
  mma_multi<1,0,3>(actb, Wg, biasg, wrow0g, outg);
}

__global__ void __launch_bounds__(256) k_mma_m1(
    const float* __restrict__ W, const float* __restrict__ bias)
{
  int b = blockIdx.z;
  const float* actb = g_x2 + (size_t)b*CB*HW;
  __nv_bfloat16* hb = g_hid + (size_t)b*4*CB*HW;
  const float* Wg[4]    = {W, W, W, W};
  const float* biasg[4] = {bias, bias, bias, bias};
  int wrow0g[4]         = {0, 96, 192, 288};
  __nv_bfloat16* outg[4]= {hb, hb+(size_t)96*HW, hb+(size_t)192*HW, hb+(size_t)288*HW};
  mma_multi<0,1,4>(actb, Wg, biasg, wrow0g, outg);
}

__global__ void __launch_bounds__(256) k_mma_proj(
    const float* __restrict__ W, const float* __restrict__ bias,
    const float* __restrict__ xin)
{
  int b = blockIdx.z;
  const __nv_bfloat16* actb = g_attn + (size_t)b*HW*96;
  mma_body<2,3>(actb, W, bias, 96, 0, g_x2 + (size_t)b*CB*HW,
                xin + (size_t)b*CB*HW, b);
}

__global__ void __launch_bounds__(256) k_mma_m2(
    const float* __restrict__ W, const float* __restrict__ bias,
    float* __restrict__ out)
{
  int b = blockIdx.z;
  mma_body<1,2>(g_hid + (size_t)b*4*CB*HW, W, bias, 384, 0,
                out + (size_t)b*CB*HW, g_x2 + (size_t)b*CB*HW, b);
}

// ---------------- attention: one (window, head) per 64-thread block ----------------
__global__ void __launch_bounds__(64) k_attn(const float* __restrict__ lsp){
  __shared__ __align__(16) float sK[32][64];
  __shared__ __align__(16) float sVt[64][36];
  int widx=blockIdx.x, h=blockIdx.y;
  int b=widx>>10, rem=widx&1023;
  int r0=(rem>>5)*8, c0=(rem&31)*8;
  int t=threadIdx.x;
  float ls = __expf(fminf(lsp[0], LOGIT_MAXV));
  size_t baseK = ((size_t)b*3*CB +   CB + h*32)*HW;
  size_t baseV = ((size_t)b*3*CB + 2*CB + h*32)*HW;
  for (int i=t;i<2048;i+=64){
    int d=i>>6, m=i&63;
    int hw = (r0+(m>>3))*256 + c0 + (m&7);
    sK[d][m]  = __bfloat162float(g_qkv[baseK + (size_t)d*HW + hw])*SCALEV;
    sVt[m][d] = __bfloat162float(g_qkv[baseV + (size_t)d*HW + hw]);
  }
  int hw_t = (r0+(t>>3))*256 + c0 + (t&7);
  size_t baseQ = ((size_t)b*CB + h*32)*HW;
  unsigned long long q2[32];
  #pragma unroll
  for (int d=0;d<32;d++)
    q2[d] = pack2(__bfloat162float(g_co[baseQ + (size_t)d*HW + hw_t]));
  __syncthreads();
  float l[64];
  const float* brow = &g_bias_tab[h][t][0];
  #pragma unroll
  for (int m0=0;m0<64;m0+=4){
    unsigned long long s01=0ull, s23=0ull;
    #pragma unroll
    for (int d=0;d<32;d++){
      ulonglong2 kk = *(const ulonglong2*)&sK[d][m0];
      ffma2(s01, q2[d], kk.x);
      ffma2(s23, q2[d], kk.y);
    }
    float2 pa=u2f(s01), pb=u2f(s23);
    float4 bi = *(const float4*)(brow + m0);
    l[m0  ]=pa.x*ls+bi.x; l[m0+1]=pa.y*ls+bi.y;
    l[m0+2]=pb.x*ls+bi.z; l[m0+3]=pb.y*ls+bi.w;
  }
  float mx=l[0];
  #pragma unroll
  for (int m=1;m<64;m++) mx = fmaxf(mx,l[m]);
  float sum=0.f;
  #pragma unroll
  for (int m=0;m<64;m++){ float e=__expf(l[m]-mx); l[m]=e; sum+=e; }
  float inv = 1.f/sum;
  unsigned long long o2[16];
  #pragma unroll
  for (int i=0;i<16;i++) o2[i]=0ull;
  #pragma unroll
  for (int m=0;m<64;m++){
    unsigned long long p2 = pack2(l[m]);
    const ulonglong2* vp = (const ulonglong2*)&sVt[m][0];
    #pragma unroll
    for (int dd=0;dd<8;dd++){
      ulonglong2 vv = vp[dd];
      ffma2(o2[2*dd  ], p2, vv.x);
      ffma2(o2[2*dd+1], p2, vv.y);
    }
  }
  __nv_bfloat16* dst = g_attn + ((size_t)b*HW + hw_t)*96 + h*32;
  #pragma unroll
  for (int k=0;k<8;k++){
    float2 pa=u2f(o2[2*k]), pb=u2f(o2[2*k+1]);
    uint2 u; u.x = bf2u(pa.x*inv, pa.y*inv); u.y = bf2u(pb.x*inv, pb.y*inv);
    *(uint2*)(dst + 4*k) = u;
  }
}

// ---------------- host launch ----------------
extern "C" void kernel_launch(void* const* d_in, const int* in_sizes, int n_in,
                              void* d_out, int out_size){
  const float* x       = (const float*)d_in[0];
  const float* agn_w   = (const float*)d_in[1];
  const float* agn_b   = (const float*)d_in[2];
  const float* meta1_w = (const float*)d_in[3];
  const float* meta1_b = (const float*)d_in[4];
  const float* meta2_w = (const float*)d_in[5];
  const float* meta2_b = (const float*)d_in[6];
  const float* la1_w   = (const float*)d_in[7];
  const float* la1_b   = (const float*)d_in[8];
  const float* la2_w   = (const float*)d_in[9];
  const float* la2_b   = (const float*)d_in[10];
  const float* ta1_w   = (const float*)d_in[11];
  const float* ta1_b   = (const float*)d_in[12];
  const float* ta2_w   = (const float*)d_in[13];
  const float* ta2_b   = (const float*)d_in[14];
  const float* q_w     = (const float*)d_in[15];
  const float* q_b     = (const float*)d_in[16];
  const float* kv_w    = (const float*)d_in[17];
  const float* kv_b    = (const float*)d_in[18];
  const float* dw_w    = (const float*)d_in[19];
  const float* dw_b    = (const float*)d_in[20];
  const float* proj_w  = (const float*)d_in[21];
  const float* proj_b  = (const float*)d_in[22];
  const float* logit_s = (const float*)d_in[23];
  const float* rp_w1   = (const float*)d_in[24];
  const float* rp_b1   = (const float*)d_in[25];
  const float* rp_w2   = (const float*)d_in[26];
  const float* rp_b2   = (const float*)d_in[27];
  const float* m1_w    = (const float*)d_in[28];
  const float* m1_b    = (const float*)d_in[29];
  const float* m2_w    = (const float*)d_in[30];
  const float* m2_b    = (const float*)d_in[31];
  float* out = (float*)d_out;

  cudaFuncSetAttribute(k_mma_qkv, cudaFuncAttributeMaxDynamicSharedMemorySize, SMEM_MMA);
  cudaFuncSetAttribute(k_mma_proj,cudaFuncAttributeMaxDynamicSharedMemorySize, SMEM_MMA);
  cudaFuncSetAttribute(k_mma_m1,  cudaFuncAttributeMaxDynamicSharedMemorySize, SMEM_MMA);
  cudaFuncSetAttribute(k_mma_m2,  cudaFuncAttributeMaxDynamicSharedMemorySize, SMEM_MMA);

  // 1. stats + bias table
  k_reduce_partial<<<dim3(192,BATCH), 256>>>(x);
  k_finalize<<<BATCH, 256>>>(meta1_w, meta1_b, meta2_w, meta2_b);
  k_bias<<<64, 64>>>(rp_w1, rp_b1, rp_w2, rp_b2);

  // 2. fused AGN (writes bf16 g_y)
  dim3 agrid(IMG/128, IMG/8, BATCH*CB);
  k_agn_fused<<<agrid, 256>>>(x, agn_w, agn_b, la1_w, la1_b, la2_w, la2_b,
                              ta1_w, ta1_b, ta2_w, ta2_b);

  // 3. QKV projections — single merged launch, act loaded once
  k_mma_qkv<<<dim3(512,1,BATCH), 256, SMEM_MMA>>>(q_w, q_b, kv_w, kv_b);

  // 4. reflect 5x5 dwconv on Q, then window attention
  dim3 cgrid(IMG/32, IMG/8, BATCH*CB), cblk(32, 8);
  k_co5<<<cgrid, cblk>>>(dw_w, dw_b);
  k_attn<<<dim3(4096,3), 64>>>(logit_s);

  // 5. proj + residual/rescale/rebias -> g_x2 (fp32)
  k_mma_proj<<<dim3(512,1,BATCH), 256, SMEM_MMA>>>(proj_w, proj_b, x);

  // 6. MLP (merged m1, then m2 with residual -> out)
  k_mma_m1<<<dim3(512,1,BATCH), 256, SMEM_MMA>>>(m1_w, m1_b);
  k_mma_m2<<<dim3(512,1,BATCH), 256, SMEM_MMA>>>(m2_w, m2_b, out);
}

// round 12
// speedup vs baseline: 1.0375x; 1.0375x over previous
#include <cuda_runtime.h>
#include <cuda_bf16.h>
#include <math.h>

#define HW 65536
#define IMG 256
#define CB 96
#define BATCH 4

// ---------------- device scratch ----------------
__device__ float g_mean[BATCH], g_istd[BATCH];
__device__ float g_rescale[BATCH][CB], g_rebias[BATCH][CB];
__device__ float g_partial[BATCH][192][2];
__device__ float g_bias_tab[3][64][64];

__device__ __nv_bfloat16 g_y  [(size_t)BATCH*CB*HW];
__device__ __nv_bfloat16 g_qkv[(size_t)BATCH*3*CB*HW];
__device__ __nv_bfloat16 g_co [(size_t)BATCH*CB*HW];
__device__ __nv_bfloat16 g_attn[(size_t)BATCH*HW*CB];
__device__ float         g_x2 [(size_t)BATCH*CB*HW];
__device__ __nv_bfloat16 g_hid[(size_t)BATCH*4*CB*HW];

#define SCALEV 0.17677669529663687f
#define LOGIT_MAXV 4.605170185988091f

// ---------------- f32x2 helpers ----------------
__device__ __forceinline__ unsigned long long pack2(float w){
  unsigned long long r; asm("mov.b64 %0, {%1, %1};" : "=l"(r) : "f"(w)); return r;
}
__device__ __forceinline__ float2 u2f(unsigned long long v){
  float2 f; asm("mov.b64 {%0, %1}, %2;" : "=f"(f.x), "=f"(f.y) : "l"(v)); return f;
}
__device__ __forceinline__ void ffma2(unsigned long long &d, unsigned long long a, unsigned long long b){
  asm("fma.rn.f32x2 %0, %1, %2, %0;" : "+l"(d) : "l"(a), "l"(b));
}

// ---------------- mma helpers ----------------
__device__ __forceinline__ void ldsm_x4(unsigned addr, unsigned &r0, unsigned &r1, unsigned &r2, unsigned &r3){
  asm volatile("ldmatrix.sync.aligned.m8n8.x4.shared.b16 {%0,%1,%2,%3}, [%4];"
    : "=r"(r0),"=r"(r1),"=r"(r2),"=r"(r3) : "r"(addr));
}
__device__ __forceinline__ void ldsm_x4_t(unsigned addr, unsigned &r0, unsigned &r1, unsigned &r2, unsigned &r3){
  asm volatile("ldmatrix.sync.aligned.m8n8.x4.trans.shared.b16 {%0,%1,%2,%3}, [%4];"
    : "=r"(r0),"=r"(r1),"=r"(r2),"=r"(r3) : "r"(addr));
}
__device__ __forceinline__ void ldsm_x2(unsigned addr, unsigned &r0, unsigned &r1){
  asm volatile("ldmatrix.sync.aligned.m8n8.x2.shared.b16 {%0,%1}, [%2];"
    : "=r"(r0),"=r"(r1) : "r"(addr));
}
__device__ __forceinline__ void mma16816(float* c, const unsigned* a, const unsigned* b){
  asm volatile("mma.sync.aligned.m16n8k16.row.col.f32.bf16.bf16.f32 "
    "{%0,%1,%2,%3},{%4,%5,%6,%7},{%8,%9},{%0,%1,%2,%3};"
    : "+f"(c[0]),"+f"(c[1]),"+f"(c[2]),"+f"(c[3])
    : "r"(a[0]),"r"(a[1]),"r"(a[2]),"r"(a[3]),"r"(b[0]),"r"(b[1]));
}
__device__ __forceinline__ unsigned bf2u(float x, float y){
  __nv_bfloat162 t = __floats2bfloat162_rn(x, y);
  return reinterpret_cast<unsigned&>(t);
}

// ---------------- K1: per-sample partial sums ----------------
__global__ void k_reduce_partial(const float* __restrict__ x){
  int b = blockIdx.y, blk = blockIdx.x, tid = threadIdx.x;
  const float4* xb = (const float4*)(x + (size_t)b*CB*HW);
  size_t base = (size_t)blk*8192;
  float s=0.f, s2=0.f;
  for (int i=tid;i<8192;i+=256){
    float4 v = xb[base+i];
    s  += v.x+v.y+v.z+v.w;
    s2 += v.x*v.x+v.y*v.y+v.z*v.z+v.w*v.w;
  }
  __shared__ float rs[256], rq[256];
  rs[tid]=s; rq[tid]=s2; __syncthreads();
  for (int st=128;st>0;st>>=1){
    if (tid<st){ rs[tid]+=rs[tid+st]; rq[tid]+=rq[tid+st]; }
    __syncthreads();
  }
  if (tid==0){ g_partial[b][blk][0]=rs[0]; g_partial[b][blk][1]=rq[0]; }
}

// ---------------- K2: finalize ----------------
__global__ void k_finalize(const float* __restrict__ m1w, const float* __restrict__ m1b,
                           const float* __restrict__ m2w, const float* __restrict__ m2b){
  int b = blockIdx.x, tid = threadIdx.x;
  __shared__ float rs[256], rq[256];
  rs[tid] = (tid<192)? g_partial[b][tid][0] : 0.f;
  rq[tid] = (tid<192)? g_partial[b][tid][1] : 0.f;
  __syncthreads();
  for (int st=128;st>0;st>>=1){
    if (tid<st){ rs[tid]+=rs[tid+st]; rq[tid]+=rq[tid+st]; }
    __syncthreads();
  }
  __shared__ float sh_mean, sh_std;
  if (tid==0){
    float M = (float)((size_t)CB*HW);
    float mean = rs[0]/M;
    float var  = rq[0]/M - mean*mean;
    float sd   = sqrtf(var + 1e-5f);
    g_mean[b]=mean; g_istd[b]=1.f/sd;
    sh_mean=mean; sh_std=sd;
  }
  __syncthreads();
  if (tid<CB){
    g_rescale[b][tid] = sh_std *m1w[tid] + m1b[tid];
    g_rebias [b][tid] = sh_mean*m2w[tid] + m2b[tid];
  }
}

// ---------------- K3: relative-position bias table ----------------
__global__ void k_bias(const float* __restrict__ w1, const float* __restrict__ b1,
                       const float* __restrict__ w2, const float* __restrict__ b2){
  int n = blockIdx.x, m = threadIdx.x;
  float di = (float)((n>>3) - (m>>3));
  float dj = (float)((n&7) - (m&7));
  float a0l = log1pf(fabsf(di)); float r0 = di<0.f ? -a0l : (di>0.f ? a0l : 0.f);
  float a1l = log1pf(fabsf(dj)); float r1 = dj<0.f ? -a1l : (dj>0.f ? a1l : 0.f);
  float a0=0.f,a1=0.f,a2=0.f;
  for (int k=0;k<256;k++){
    float h = fmaxf(r0*w1[2*k]+r1*w1[2*k+1]+b1[k], 0.f);
    a0 += h*w2[k]; a1 += h*w2[256+k]; a2 += h*w2[512+k];
  }
  g_bias_tab[0][n][m]=a0+b2[0];
  g_bias_tab[1][n][m]=a1+b2[1];
  g_bias_tab[2][n][m]=a2+b2[2];
}

// ---------------- K4: fused AGN (kept from R5/R6) ----------------
__global__ void __launch_bounds__(256) k_agn_fused(const float* __restrict__ x,
    const float* __restrict__ agnw, const float* __restrict__ agnb,
    const float* __restrict__ la1w, const float* __restrict__ la1b,
    const float* __restrict__ la2w, const float* __restrict__ la2b,
    const float* __restrict__ ta1w, const float* __restrict__ ta1b,
    const float* __restrict__ ta2w, const float* __restrict__ ta2b){
  __shared__ float xt[12*136];
  __shared__ __align__(8) float2 tb[10*136];
  int bc = blockIdx.z; int b = bc/CB, c = bc - b*CB;
  const float* xb = x + (size_t)bc*HW;
  float mean = g_mean[b], istd = g_istd[b];
  int x0 = blockIdx.x*128, y0 = blockIdx.y*8;
  int tid = threadIdx.x;

  for (int i=tid; i<12*136; i+=256){
    int ry = i/136, cc = i-ry*136;
    int gy = y0+ry-2, gx = x0+cc-2;
    float v = 0.f;
    if ((unsigned)gy<256u && (unsigned)gx<256u) v = (xb[gy*256+gx]-mean)*istd;
    xt[ry*136 + ((cc&3)*34 + (cc>>2))] = v;
  }
  float w1l[9], w1t[9];
  #pragma unroll
  for (int k=0;k<9;k++){ w1l[k]=la1w[c*9+k]; w1t[k]=ta1w[c*9+k]; }
  float b1l=la1b[c], b1t=ta1b[c];
  __syncthreads();

  for (int run=tid; run<330; run+=256){
    int r = run/33, rn = run - r*33;
    float al[4], at[4];
    #pragma unroll
    for (int o=0;o<4;o++){ al[o]=b1l; at[o]=b1t; }
    #pragma unroll
    for (int dy=0;dy<3;dy++){
      const float* xr = xt + (r+dy)*136;
      float v[6];
      v[0]=xr[rn]; v[1]=xr[34+rn]; v[2]=xr[68+rn]; v[3]=xr[102+rn];
      v[4]=xr[rn+1]; v[5]=xr[34+rn+1];
      #pragma unroll
      for (int o=0;o<4;o++){
        al[o] += v[o]*w1l[dy*3] + v[o+1]*w1l[dy*3+1] + v[o+2]*w1l[dy*3+2];
        at[o] += v[o]*w1t[dy*3] + v[o+1]*w1t[dy*3+1] + v[o+2]*w1t[dy*3+2];
      }
    }
    float2* tr = tb + r*136;
    #pragma unroll
    for (int o=0;o<4;o++)
      tr[o*34+rn] = make_float2(fmaxf(al[o],0.f), fmaxf(at[o],0.f));
  }
  __syncthreads();

  float w2l[9], w2t[9];
  #pragma unroll
  for (int k=0;k<9;k++){ w2l[k]=la2w[c*9+k]; w2t[k]=ta2w[c*9+k]; }
  int tx = tid&31, ty = tid>>5;
  float acc[4];
  float base2 = la2b[c] + ta2b[c];
  #pragma unroll
  for (int o=0;o<4;o++) acc[o]=base2;
  #pragma unroll
  for (int dy=0;dy<3;dy++){
    const float2* tr = tb + (ty+dy)*136;
    float2 t0=tr[tx], t1=tr[34+tx], t2=tr[68+tx], t3=tr[102+tx];
    float2 t4=tr[tx+1], t5=tr[34+tx+1];
    float2 tv[6] = {t0,t1,t2,t3,t4,t5};
    #pragma unroll
    for (int o=0;o<4;o++){
      #pragma unroll
      for (int dx=0;dx<3;dx++){
        float2 v = tv[o+dx];
        acc[o] += v.x*w2l[dy*3+dx] + v.y*w2t[dy*3+dx];
      }
    }
  }
  float sc = agnw[c]*g_rescale[b][c];
  float sb = agnb[c]+g_rebias[b][c];
  const float* xnr = xt + (ty+2)*136;
  float xn0 = xnr[68+tx], xn1 = xnr[102+tx], xn2 = xnr[tx+1], xn3 = xnr[34+tx+1];
  float r0 = xn0*sc + sb + acc[0];
  float r1 = xn1*sc + sb + acc[1];
  float r2 = xn2*sc + sb + acc[2];
  float r3 = xn3*sc + sb + acc[3];
  uint2 u; u.x = bf2u(r0,r1); u.y = bf2u(r2,r3);
  *(uint2*)(g_y + (size_t)bc*HW + (size_t)(y0+ty)*256 + x0 + 4*tx) = u;
}

// ---------------- K6: 5x5 reflect dwconv on Q ----------------
__global__ void k_co5(const float* __restrict__ dww, const float* __restrict__ dwb){
  int bc=blockIdx.z; int b=bc/CB, c=bc-b*CB;
  const __nv_bfloat16* Q = g_qkv + ((size_t)b*3*CB + c)*HW;
  __shared__ float tile[12][36];
  int x0=blockIdx.x*32, y0=blockIdx.y*8;
  int tid=threadIdx.y*32+threadIdx.x;
  for (int i=tid;i<432;i+=256){
    int ry=i/36, rx=i-ry*36;
    int gy=y0+ry-2, gx=x0+rx-2;
    gy = gy<0 ? -gy : (gy>255 ? 510-gy : gy);
    gx = gx<0 ? -gx : (gx>255 ? 510-gx : gx);
    tile[ry][rx] = __bfloat162float(Q[gy*256+gx]);
  }
  __syncthreads();
  float w[25];
  #pragma unroll
  for (int k=0;k<25;k++) w[k]=dww[c*25+k];
  float acc = dwb[c];
  #pragma unroll
  for (int ky=0;ky<5;ky++)
    #pragma unroll
    for (int kx=0;kx<5;kx++)
      acc += tile[threadIdx.y+ky][threadIdx.x+kx]*w[ky*5+kx];
  g_co[(size_t)bc*HW + (size_t)(y0+threadIdx.y)*256 + x0+threadIdx.x] = __float2bfloat16(acc);
}

// =====================================================================
// Tensor-core GEMM bodies
// =====================================================================
#define SMEM_MMA   50688
#define SMEM_MULTI 70656   // sA 24576 + sW 19968 + bf16 stage 26112

// ---- single-group body (staged epilogue) — proj, m2 (unchanged R6) ----
template<int LOAD, int EPI>
__device__ __forceinline__ void mma_body(
    const void* actb, const float* W, const float* bias,
    int CinTot, int wrow0, void* outv,
    const float* xinb, int bIdx)
{
  extern __shared__ char smem_raw[];
  __nv_bfloat16* sA = (__nv_bfloat16*)smem_raw;
  __nv_bfloat16* sW = (__nv_bfloat16*)(smem_raw + (LOAD==2 ? 26624 : 24576));
  float* sStage = (float*)smem_raw;
  const int tid = threadIdx.x;
  const int px0 = blockIdx.x * 128;
  const int warp = tid >> 5, t = tid & 31;
  const int m0w = (warp>>1)*32, n0w = (warp&1)*48;
  unsigned sAb = (unsigned)__cvta_generic_to_shared(sA);
  unsigned sWb = (unsigned)__cvta_generic_to_shared(sW);

  float acc[2][6][4];
  #pragma unroll
  for (int mi=0;mi<2;mi++)
    #pragma unroll
    for (int nj=0;nj<6;nj++)
      #pragma unroll
      for (int e=0;e<4;e++) acc[mi][nj][e]=0.f;

  const int g = t>>3, gi = t&7;
  const int t15 = t&15;

  for (int k0g=0; k0g<CinTot; k0g+=96){
    if (LOAD==0){
      const float* a = (const float*)actb;
      #pragma unroll
      for (int j=0;j<12;j++){
        int i = tid + 256*j;
        int c = i>>5, px = (i&31)*4;
        float4 v = *(const float4*)(a + (size_t)(k0g+c)*HW + px0 + px);
        uint2 u; u.x = bf2u(v.x,v.y); u.y = bf2u(v.z,v.w);
        *(uint2*)(sA + c*128 + ((((px>>3)^(c&7))<<3) + (px&7))) = u;
      }
    } else if (LOAD==1){
      const __nv_bfloat16* a = (const __nv_bfloat16*)actb;
      #pragma unroll
      for (int j=0;j<6;j++){
        int i = tid + 256*j;
        int c = i>>4, s8 = (i&15)*8;
        uint4 v = *(const uint4*)(a + (size_t)(k0g+c)*HW + px0 + s8);
        *(uint4*)(sA + c*128 + ((((s8>>3)^(c&7))<<3))) = v;
      }
    } else {
      const __nv_bfloat16* a = (const __nv_bfloat16*)actb + (size_t)px0*96;
      #pragma unroll
      for (int j=0;j<6;j++){
        int i = tid + 256*j;
        int px = i/12, c0 = (i%12)*8;
        uint4 v = *(const uint4*)(a + (size_t)px*96 + c0);
        *(uint4*)(sA + px*104 + c0) = v;
      }
    }
    #pragma unroll
    for (int j=0;j<9;j++){
      int i = tid + 256*j;
      int r = i/24, c4 = (i%24)*4;
      float4 v = *(const float4*)(W + (size_t)(wrow0+r)*CinTot + k0g + c4);
      uint2 u; u.x = bf2u(v.x,v.y); u.y = bf2u(v.z,v.w);
      *(uint2*)(sW + r*104 + c4) = u;
    }
    __syncthreads();

    unsigned addrA[2], addrB[6];
    if (LOAD==2){
      int row0 = m0w + (g&1)*8 + gi;
      int kc = (g>=2)?16:0;
      addrA[0] = sAb + (row0     )*208 + kc;
      addrA[1] = sAb + (row0 + 16)*208 + kc;
    } else {
      int kb = ((g>=2)?8:0) + gi;
      int px_a0 = m0w + (g&1)*8;
      int px_a1 = px_a0 + 16;
      addrA[0] = sAb + kb*256 + ((((px_a0>>3) ^ gi)<<4));
      addrA[1] = sAb + kb*256 + ((((px_a1>>3) ^ gi)<<4));
    }
    {
      int n = n0w + (t15&7);
      int kc = (t15>>3)*8;
      #pragma unroll
      for (int nj=0;nj<6;nj++) addrB[nj] = sWb + (n + nj*8)*208 + kc*2;
    }

    #pragma unroll
    for (int ks=0; ks<6; ks++){
      unsigned a[2][4], bfr[6][2];
      if (LOAD==2){ ldsm_x4(addrA[0], a[0][0],a[0][1],a[0][2],a[0][3]);
                    ldsm_x4(addrA[1], a[1][0],a[1][1],a[1][2],a[1][3]); }
      else        { ldsm_x4_t(addrA[0], a[0][0],a[0][1],a[0][2],a[0][3]);
                    ldsm_x4_t(addrA[1], a[1][0],a[1][1],a[1][2],a[1][3]); }
      #pragma unroll
      for (int nj=0;nj<6;nj++) ldsm_x2(addrB[nj], bfr[nj][0], bfr[nj][1]);
      #pragma unroll
      for (int mi=0;mi<2;mi++)
        #pragma unroll
        for (int nj=0;nj<6;nj++)
          mma16816(acc[mi][nj], a[mi], bfr[nj]);
      if (LOAD==2){ addrA[0]+=32; addrA[1]+=32; }
      else        { addrA[0]+=4096; addrA[1]+=4096; }
      #pragma unroll
      for (int nj=0;nj<6;nj++) addrB[nj]+=32;
    }
    __syncthreads();
  }

  #pragma unroll
  for (int mi=0;mi<2;mi++)
    #pragma unroll
    for (int nj=0;nj<6;nj++){
      int m = m0w + mi*16 + (t>>2);
      int n = n0w + nj*8 + (t&3)*2;
      sStage[(n  )*132 + m  ] = acc[mi][nj][0];
      sStage[(n+1)*132 + m  ] = acc[mi][nj][1];
      sStage[(n  )*132 + m+8] = acc[mi][nj][2];
      sStage[(n+1)*132 + m+8] = acc[mi][nj][3];
    }
  __syncthreads();

  const int tx = tid&31, ty = tid>>5;
  #pragma unroll
  for (int r=0;r<12;r++){
    int o = ty*12 + r;
    float4 v = *(float4*)(sStage + o*132 + tx*4);
    float bv = bias[wrow0+o];
    v.x+=bv; v.y+=bv; v.z+=bv; v.w+=bv;
    size_t off = (size_t)o*HW + px0 + tx*4;
    if (EPI==2){
      float4 q = *(const float4*)(xinb + off);
      v.x+=q.x; v.y+=q.y; v.z+=q.z; v.w+=q.w;
      *(float4*)((float*)outv + off) = v;
    } else if (EPI==3){
      float rs = g_rescale[bIdx][o], rb = g_rebias[bIdx][o];
      float4 xi = *(const float4*)(xinb + off);
      v = make_float4(xi.x + v.x*rs + rb, xi.y + v.y*rs + rb,
                      xi.z + v.z*rs + rb, xi.w + v.w*rs + rb);
      *(float4*)((float*)outv + off) = v;
    } else {
      *(float4*)((float*)outv + off) = v;
    }
  }
}

// ---- multi-group body: act loaded ONCE; bf16 smem-staged vector epilogue ----
template<int LOAD, int RELU, int GROUPS>
__device__ __forceinline__ void mma_multi(
    const void* actb, const float* const* Wg, const float* const* biasg,
    const int* wrow0g, __nv_bfloat16* const* outg)
{
  extern __shared__ char smem_raw[];
  __nv_bfloat16* sA = (__nv_bfloat16*)smem_raw;
  __nv_bfloat16* sW = (__nv_bfloat16*)(smem_raw + 24576);
  __nv_bfloat16* sStage = (__nv_bfloat16*)(smem_raw + 44544);  // [96][136] bf16
  const int tid = threadIdx.x;
  const int px0 = blockIdx.x * 128;
  const int warp = tid >> 5, t = tid & 31;
  const int m0w = (warp>>1)*32, n0w = (warp&1)*48;
  unsigned sAb = (unsigned)__cvta_generic_to_shared(sA);
  unsigned sWb = (unsigned)__cvta_generic_to_shared(sW);
  const int g = t>>3, gi = t&7;
  const int t15 = t&15;

  // ---- load activation tile once ----
  if (LOAD==0){
    const float* a = (const float*)actb;
    #pragma unroll
    for (int j=0;j<12;j++){
      int i = tid + 256*j;
      int c = i>>5, px = (i&31)*4;
      float4 v = *(const float4*)(a + (size_t)c*HW + px0 + px);
      uint2 u; u.x = bf2u(v.x,v.y); u.y = bf2u(v.z,v.w);
      *(uint2*)(sA + c*128 + ((((px>>3)^(c&7))<<3) + (px&7))) = u;
    }
  } else {
    const __nv_bfloat16* a = (const __nv_bfloat16*)actb;
    #pragma unroll
    for (int j=0;j<6;j++){
      int i = tid + 256*j;
      int c = i>>4, s8 = (i&15)*8;
      uint4 v = *(const uint4*)(a + (size_t)c*HW + px0 + s8);
      *(uint4*)(sA + c*128 + ((((s8>>3)^(c&7))<<3))) = v;
    }
  }

  unsigned addrA0[2];
  {
    int kb = ((g>=2)?8:0) + gi;
    int px_a0 = m0w + (g&1)*8;
    int px_a1 = px_a0 + 16;
    addrA0[0] = sAb + kb*256 + ((((px_a0>>3) ^ gi)<<4));
    addrA0[1] = sAb + kb*256 + ((((px_a1>>3) ^ gi)<<4));
  }
  unsigned addrB0;
  {
    int n = n0w + (t15&7);
    int kc = (t15>>3)*8;
    addrB0 = sWb + n*208 + kc*2;
  }

  #pragma unroll
  for (int grp=0; grp<GROUPS; grp++){
    const float* W = Wg[grp];
    int wrow0 = wrow0g[grp];
    #pragma unroll
    for (int j=0;j<9;j++){
      int i = tid + 256*j;
      int r = i/24, c4 = (i%24)*4;
      float4 v = *(const float4*)(W + (size_t)(wrow0+r)*96 + c4);
      uint2 u; u.x = bf2u(v.x,v.y); u.y = bf2u(v.z,v.w);
      *(uint2*)(sW + r*104 + c4) = u;
    }
    __syncthreads();

    float acc[2][6][4];
    #pragma unroll
    for (int mi=0;mi<2;mi++)
      #pragma unroll
      for (int nj=0;nj<6;nj++)
        #pragma unroll
        for (int e=0;e<4;e++) acc[mi][nj][e]=0.f;

    unsigned addrA[2] = {addrA0[0], addrA0[1]};
    unsigned addrB[6];
    #pragma unroll
    for (int nj=0;nj<6;nj++) addrB[nj] = addrB0 + nj*8*208;

    #pragma unroll
    for (int ks=0; ks<6; ks++){
      unsigned a[2][4], bfr[6][2];
      ldsm_x4_t(addrA[0], a[0][0],a[0][1],a[0][2],a[0][3]);
      ldsm_x4_t(addrA[1], a[1][0],a[1][1],a[1][2],a[1][3]);
      #pragma unroll
      for (int nj=0;nj<6;nj++) ldsm_x2(addrB[nj], bfr[nj][0], bfr[nj][1]);
      #pragma unroll
      for (int mi=0;mi<2;mi++)
        #pragma unroll
        for (int nj=0;nj<6;nj++)
          mma16816(acc[mi][nj], a[mi], bfr[nj]);
      addrA[0]+=4096; addrA[1]+=4096;
      #pragma unroll
      for (int nj=0;nj<6;nj++) addrB[nj]+=32;
    }
    __syncthreads();

    // ---- stage accumulators (bias+relu applied) into bf16 smem ----
    const float* bias = biasg[grp];
    #pragma unroll
    for (int nj=0;nj<6;nj++){
      int nl = n0w + nj*8 + (t&3)*2;
      float b0 = __ldg(bias + wrow0g[grp] + nl);
      float b1 = __ldg(bias + wrow0g[grp] + nl + 1);
      #pragma unroll
      for (int mi=0;mi<2;mi++){
        int m = m0w + mi*16 + (t>>2);
        float c0 = acc[mi][nj][0] + b0;
        float c1 = acc[mi][nj][1] + b1;
        float c2 = acc[mi][nj][2] + b0;
        float c3 = acc[mi][nj][3] + b1;
        if (RELU){
          c0=fmaxf(c0,0.f); c1=fmaxf(c1,0.f); c2=fmaxf(c2,0.f); c3=fmaxf(c3,0.f);
        }
        sStage[nl*136 + m        ] = __float2bfloat16(c0);
        sStage[(nl+1)*136 + m    ] = __float2bfloat16(c1);
        sStage[nl*136 + m + 8    ] = __float2bfloat16(c2);
        sStage[(nl+1)*136 + m + 8] = __float2bfloat16(c3);
      }
    }
    __syncthreads();

    // ---- vectorized writeout: 96ch x 128px bf16 = 1536 uint4 ----
    __nv_bfloat16* outb = outg[grp];
    #pragma unroll
    for (int j=0;j<6;j++){
      int i4 = tid + 256*j;
      int ch = i4>>4, seg = i4&15;
      uint4 v = *(const uint4*)(sStage + ch*136 + seg*8);
      *(uint4*)(outb + (size_t)ch*HW + px0 + seg*8) = v;
    }
    // next group's post-Wload sync separates these stage reads from
    // the next stage writes.
  }
}

__global__ void __launch_bounds__(256) k_mma_qkv(
    const float* __restrict__ qW, const float* __restrict__ qb,
    const float* __restrict__ kvW, const float* __restrict__ kvb)
{
  int b = blockIdx.z;
  const __nv_bfloat16* actb = g_y + (size_t)b*CB*HW;
  __nv_bfloat16* o0 = g_qkv + ((size_t)b*3*CB + 0 )*HW;
  __nv_bfloat16* o1 = g_qkv + ((size_t)b*3*CB + 96)*HW;
  __nv_bfloat16* o2 = g_qkv + ((size_t)b*3*CB +192)*HW;
  const float* Wg[3]    = {qW, kvW, kvW};
  const float* biasg[3] = {qb, kvb, kvb};
  int wrow0g[3]         = {0, 0, 96};
  __nv_bfloat16* outg[3]= {o0, o1, o2};
  mma_multi<1,0,3>(actb, Wg, biasg, wrow0g, outg);
}

__global__ void __launch_bounds__(256) k_mma_m1(
    const float* __restrict__ W, const float* __restrict__ bias)
{
  int b = blockIdx.z;
  const float* actb = g_x2 + (size_t)b*CB*HW;
  __nv_bfloat16* hb = g_hid + (size_t)b*4*CB*HW;
  const float* Wg[4]    = {W, W, W, W};
  const float* biasg[4] = {bias, bias, bias, bias};
  int wrow0g[4]         = {0, 96, 192, 288};
  __nv_bfloat16* outg[4]= {hb, hb+(size_t)96*HW, hb+(size_t)192*HW, hb+(size_t)288*HW};
  mma_multi<0,1,4>(actb, Wg, biasg, wrow0g, outg);
}

__global__ void __launch_bounds__(256) k_mma_proj(
    const float* __restrict__ W, const float* __restrict__ bias,
    const float* __restrict__ xin)
{
  int b = blockIdx.z;
  const __nv_bfloat16* actb = g_attn + (size_t)b*HW*96;
  mma_body<2,3>(actb, W, bias, 96, 0, g_x2 + (size_t)b*CB*HW,
                xin + (size_t)b*CB*HW, b);
}

__global__ void __launch_bounds__(256) k_mma_m2(
    const float* __restrict__ W, const float* __restrict__ bias,
    float* __restrict__ out)
{
  int b = blockIdx.z;
  mma_body<1,2>(g_hid + (size_t)b*4*CB*HW, W, bias, 384, 0,
                out + (size_t)b*CB*HW, g_x2 + (size_t)b*CB*HW, b);
}

// ---------------- attention: one (window, head) per 64-thread block ----------------
__global__ void __launch_bounds__(64) k_attn(const float* __restrict__ lsp){
  __shared__ __align__(16) float sK[32][64];
  __shared__ __align__(16) float sVt[64][36];
  int widx=blockIdx.x, h=blockIdx.y;
  int b=widx>>10, rem=widx&1023;
  int r0=(rem>>5)*8, c0=(rem&31)*8;
  int t=threadIdx.x;
  float ls = __expf(fminf(lsp[0], LOGIT_MAXV));
  size_t baseK = ((size_t)b*3*CB +   CB + h*32)*HW;
  size_t baseV = ((size_t)b*3*CB + 2*CB + h*32)*HW;
  for (int i=t;i<2048;i+=64){
    int d=i>>6, m=i&63;
    int hw = (r0+(m>>3))*256 + c0 + (m&7);
    sK[d][m]  = __bfloat162float(g_qkv[baseK + (size_t)d*HW + hw])*SCALEV;
    sVt[m][d] = __bfloat162float(g_qkv[baseV + (size_t)d*HW + hw]);
  }
  int hw_t = (r0+(t>>3))*256 + c0 + (t&7);
  size_t baseQ = ((size_t)b*CB + h*32)*HW;
  unsigned long long q2[32];
  #pragma unroll
  for (int d=0;d<32;d++)
    q2[d] = pack2(__bfloat162float(g_co[baseQ + (size_t)d*HW + hw_t]));
  __syncthreads();
  float l[64];
  const float* brow = &g_bias_tab[h][t][0];
  #pragma unroll
  for (int m0=0;m0<64;m0+=4){
    unsigned long long s01=0ull, s23=0ull;
    #pragma unroll
    for (int d=0;d<32;d++){
      ulonglong2 kk = *(const ulonglong2*)&sK[d][m0];
      ffma2(s01, q2[d], kk.x);
      ffma2(s23, q2[d], kk.y);
    }
    float2 pa=u2f(s01), pb=u2f(s23);
    float4 bi = *(const float4*)(brow + m0);
    l[m0  ]=pa.x*ls+bi.x; l[m0+1]=pa.y*ls+bi.y;
    l[m0+2]=pb.x*ls+bi.z; l[m0+3]=pb.y*ls+bi.w;
  }
  float mx=l[0];
  #pragma unroll
  for (int m=1;m<64;m++) mx = fmaxf(mx,l[m]);
  float sum=0.f;
  #pragma unroll
  for (int m=0;m<64;m++){ float e=__expf(l[m]-mx); l[m]=e; sum+=e; }
  float inv = 1.f/sum;
  unsigned long long o2[16];
  #pragma unroll
  for (int i=0;i<16;i++) o2[i]=0ull;
  #pragma unroll
  for (int m=0;m<64;m++){
    unsigned long long p2 = pack2(l[m]);
    const ulonglong2* vp = (const ulonglong2*)&sVt[m][0];
    #pragma unroll
    for (int dd=0;dd<8;dd++){
      ulonglong2 vv = vp[dd];
      ffma2(o2[2*dd  ], p2, vv.x);
      ffma2(o2[2*dd+1], p2, vv.y);
    }
  }
  __nv_bfloat16* dst = g_attn + ((size_t)b*HW + hw_t)*96 + h*32;
  #pragma unroll
  for (int k=0;k<8;k++){
    float2 pa=u2f(o2[2*k]), pb=u2f(o2[2*k+1]);
    uint2 u; u.x = bf2u(pa.x*inv, pa.y*inv); u.y = bf2u(pb.x*inv, pb.y*inv);
    *(uint2*)(dst + 4*k) = u;
  }
}

// ---------------- host launch ----------------
extern "C" void kernel_launch(void* const* d_in, const int* in_sizes, int n_in,
                              void* d_out, int out_size){
  const float* x       = (const float*)d_in[0];
  const float* agn_w   = (const float*)d_in[1];
  const float* agn_b   = (const float*)d_in[2];
  const float* meta1_w = (const float*)d_in[3];
  const float* meta1_b = (const float*)d_in[4];
  const float* meta2_w = (const float*)d_in[5];
  const float* meta2_b = (const float*)d_in[6];
  const float* la1_w   = (const float*)d_in[7];
  const float* la1_b   = (const float*)d_in[8];
  const float* la2_w   = (const float*)d_in[9];
  const float* la2_b   = (const float*)d_in[10];
  const float* ta1_w   = (const float*)d_in[11];
  const float* ta1_b   = (const float*)d_in[12];
  const float* ta2_w   = (const float*)d_in[13];
  const float* ta2_b   = (const float*)d_in[14];
  const float* q_w     = (const float*)d_in[15];
  const float* q_b     = (const float*)d_in[16];
  const float* kv_w    = (const float*)d_in[17];
  const float* kv_b    = (const float*)d_in[18];
  const float* dw_w    = (const float*)d_in[19];
  const float* dw_b    = (const float*)d_in[20];
  const float* proj_w  = (const float*)d_in[21];
  const float* proj_b  = (const float*)d_in[22];
  const float* logit_s = (const float*)d_in[23];
  const float* rp_w1   = (const float*)d_in[24];
  const float* rp_b1   = (const float*)d_in[25];
  const float* rp_w2   = (const float*)d_in[26];
  const float* rp_b2   = (const float*)d_in[27];
  const float* m1_w    = (const float*)d_in[28];
  const float* m1_b    = (const float*)d_in[29];
  const float* m2_w    = (const float*)d_in[30];
  const float* m2_b    = (const float*)d_in[31];
  float* out = (float*)d_out;

  cudaFuncSetAttribute(k_mma_qkv, cudaFuncAttributeMaxDynamicSharedMemorySize, SMEM_MULTI);
  cudaFuncSetAttribute(k_mma_m1,  cudaFuncAttributeMaxDynamicSharedMemorySize, SMEM_MULTI);
  cudaFuncSetAttribute(k_mma_proj,cudaFuncAttributeMaxDynamicSharedMemorySize, SMEM_MMA);
  cudaFuncSetAttribute(k_mma_m2,  cudaFuncAttributeMaxDynamicSharedMemorySize, SMEM_MMA);

  // 1. stats + bias table
  k_reduce_partial<<<dim3(192,BATCH), 256>>>(x);
  k_finalize<<<BATCH, 256>>>(meta1_w, meta1_b, meta2_w, meta2_b);
  k_bias<<<64, 64>>>(rp_w1, rp_b1, rp_w2, rp_b2);

  // 2. fused AGN (writes bf16 g_y)
  dim3 agrid(IMG/128, IMG/8, BATCH*CB);
  k_agn_fused<<<agrid, 256>>>(x, agn_w, agn_b, la1_w, la1_b, la2_w, la2_b,
                              ta1_w, ta1_b, ta2_w, ta2_b);

  // 3. QKV projections — merged, act loaded once, vector epilogue
  k_mma_qkv<<<dim3(512,1,BATCH), 256, SMEM_MULTI>>>(q_w, q_b, kv_w, kv_b);

  // 4. reflect 5x5 dwconv on Q, then window attention
  dim3 cgrid(IMG/32, IMG/8, BATCH*CB), cblk(32, 8);
  k_co5<<<cgrid, cblk>>>(dw_w, dw_b);
  k_attn<<<dim3(4096,3), 64>>>(logit_s);

  // 5. proj + residual/rescale/rebias -> g_x2 (fp32)
  k_mma_proj<<<dim3(512,1,BATCH), 256, SMEM_MMA>>>(proj_w, proj_b, x);

  // 6. MLP (merged m1 with vector epilogue, then m2 with residual -> out)
  k_mma_m1<<<dim3(512,1,BATCH), 256, SMEM_MULTI>>>(m1_w, m1_b);
  k_mma_m2<<<dim3(512,1,BATCH), 256, SMEM_MMA>>>(m2_w, m2_b, out);
}

// round 13
// speedup vs baseline: 1.0431x; 1.0054x over previous
#include <cuda_runtime.h>
#include <cuda_bf16.h>
#include <math.h>

#define HW 65536
#define IMG 256
#define CB 96
#define BATCH 4

// ---------------- device scratch ----------------
__device__ float g_mean[BATCH], g_istd[BATCH];
__device__ float g_rescale[BATCH][CB], g_rebias[BATCH][CB];
__device__ float g_partial[BATCH][192][2];
__device__ float g_bias_tab[3][64][64];

__device__ __nv_bfloat16 g_y  [(size_t)BATCH*CB*HW];
__device__ __nv_bfloat16 g_qkv[(size_t)BATCH*3*CB*HW];
__device__ __nv_bfloat16 g_co [(size_t)BATCH*CB*HW];
__device__ __nv_bfloat16 g_attn[(size_t)BATCH*HW*CB];
__device__ float         g_x2 [(size_t)BATCH*CB*HW];
__device__ __nv_bfloat16 g_hid[(size_t)BATCH*4*CB*HW];

#define SCALEV 0.17677669529663687f
#define LOGIT_MAXV 4.605170185988091f

// ---------------- f32x2 helpers ----------------
__device__ __forceinline__ unsigned long long pack2(float w){
  unsigned long long r; asm("mov.b64 %0, {%1, %1};" : "=l"(r) : "f"(w)); return r;
}
__device__ __forceinline__ float2 u2f(unsigned long long v){
  float2 f; asm("mov.b64 {%0, %1}, %2;" : "=f"(f.x), "=f"(f.y) : "l"(v)); return f;
}
__device__ __forceinline__ void ffma2(unsigned long long &d, unsigned long long a, unsigned long long b){
  asm("fma.rn.f32x2 %0, %1, %2, %0;" : "+l"(d) : "l"(a), "l"(b));
}

// ---------------- mma helpers ----------------
__device__ __forceinline__ void ldsm_x4(unsigned addr, unsigned &r0, unsigned &r1, unsigned &r2, unsigned &r3){
  asm volatile("ldmatrix.sync.aligned.m8n8.x4.shared.b16 {%0,%1,%2,%3}, [%4];"
    : "=r"(r0),"=r"(r1),"=r"(r2),"=r"(r3) : "r"(addr));
}
__device__ __forceinline__ void ldsm_x4_t(unsigned addr, unsigned &r0, unsigned &r1, unsigned &r2, unsigned &r3){
  asm volatile("ldmatrix.sync.aligned.m8n8.x4.trans.shared.b16 {%0,%1,%2,%3}, [%4];"
    : "=r"(r0),"=r"(r1),"=r"(r2),"=r"(r3) : "r"(addr));
}
__device__ __forceinline__ void mma16816(float* c, const unsigned* a, const unsigned* b){
  asm volatile("mma.sync.aligned.m16n8k16.row.col.f32.bf16.bf16.f32 "
    "{%0,%1,%2,%3},{%4,%5,%6,%7},{%8,%9},{%0,%1,%2,%3};"
    : "+f"(c[0]),"+f"(c[1]),"+f"(c[2]),"+f"(c[3])
    : "r"(a[0]),"r"(a[1]),"r"(a[2]),"r"(a[3]),"r"(b[0]),"r"(b[1]));
}
__device__ __forceinline__ unsigned bf2u(float x, float y){
  __nv_bfloat162 t = __floats2bfloat162_rn(x, y);
  return reinterpret_cast<unsigned&>(t);
}

// ---------------- K1: per-sample partial sums ----------------
__global__ void k_reduce_partial(const float* __restrict__ x){
  int b = blockIdx.y, blk = blockIdx.x, tid = threadIdx.x;
  const float4* xb = (const float4*)(x + (size_t)b*CB*HW);
  size_t base = (size_t)blk*8192;
  float s=0.f, s2=0.f;
  for (int i=tid;i<8192;i+=256){
    float4 v = xb[base+i];
    s  += v.x+v.y+v.z+v.w;
    s2 += v.x*v.x+v.y*v.y+v.z*v.z+v.w*v.w;
  }
  __shared__ float rs[256], rq[256];
  rs[tid]=s; rq[tid]=s2; __syncthreads();
  for (int st=128;st>0;st>>=1){
    if (tid<st){ rs[tid]+=rs[tid+st]; rq[tid]+=rq[tid+st]; }
    __syncthreads();
  }
  if (tid==0){ g_partial[b][blk][0]=rs[0]; g_partial[b][blk][1]=rq[0]; }
}

// ---------------- K2: finalize ----------------
__global__ void k_finalize(const float* __restrict__ m1w, const float* __restrict__ m1b,
                           const float* __restrict__ m2w, const float* __restrict__ m2b){
  int b = blockIdx.x, tid = threadIdx.x;
  __shared__ float rs[256], rq[256];
  rs[tid] = (tid<192)? g_partial[b][tid][0] : 0.f;
  rq[tid] = (tid<192)? g_partial[b][tid][1] : 0.f;
  __syncthreads();
  for (int st=128;st>0;st>>=1){
    if (tid<st){ rs[tid]+=rs[tid+st]; rq[tid]+=rq[tid+st]; }
    __syncthreads();
  }
  __shared__ float sh_mean, sh_std;
  if (tid==0){
    float M = (float)((size_t)CB*HW);
    float mean = rs[0]/M;
    float var  = rq[0]/M - mean*mean;
    float sd   = sqrtf(var + 1e-5f);
    g_mean[b]=mean; g_istd[b]=1.f/sd;
    sh_mean=mean; sh_std=sd;
  }
  __syncthreads();
  if (tid<CB){
    g_rescale[b][tid] = sh_std *m1w[tid] + m1b[tid];
    g_rebias [b][tid] = sh_mean*m2w[tid] + m2b[tid];
  }
}

// ---------------- K3: relative-position bias table ----------------
__global__ void k_bias(const float* __restrict__ w1, const float* __restrict__ b1,
                       const float* __restrict__ w2, const float* __restrict__ b2){
  int n = blockIdx.x, m = threadIdx.x;
  float di = (float)((n>>3) - (m>>3));
  float dj = (float)((n&7) - (m&7));
  float a0l = log1pf(fabsf(di)); float r0 = di<0.f ? -a0l : (di>0.f ? a0l : 0.f);
  float a1l = log1pf(fabsf(dj)); float r1 = dj<0.f ? -a1l : (dj>0.f ? a1l : 0.f);
  float a0=0.f,a1=0.f,a2=0.f;
  for (int k=0;k<256;k++){
    float h = fmaxf(r0*w1[2*k]+r1*w1[2*k+1]+b1[k], 0.f);
    a0 += h*w2[k]; a1 += h*w2[256+k]; a2 += h*w2[512+k];
  }
  g_bias_tab[0][n][m]=a0+b2[0];
  g_bias_tab[1][n][m]=a1+b2[1];
  g_bias_tab[2][n][m]=a2+b2[2];
}

// ---------------- K4: fused AGN (kept from R5/R6) ----------------
__global__ void __launch_bounds__(256) k_agn_fused(const float* __restrict__ x,
    const float* __restrict__ agnw, const float* __restrict__ agnb,
    const float* __restrict__ la1w, const float* __restrict__ la1b,
    const float* __restrict__ la2w, const float* __restrict__ la2b,
    const float* __restrict__ ta1w, const float* __restrict__ ta1b,
    const float* __restrict__ ta2w, const float* __restrict__ ta2b){
  __shared__ float xt[12*136];
  __shared__ __align__(8) float2 tb[10*136];
  int bc = blockIdx.z; int b = bc/CB, c = bc - b*CB;
  const float* xb = x + (size_t)bc*HW;
  float mean = g_mean[b], istd = g_istd[b];
  int x0 = blockIdx.x*128, y0 = blockIdx.y*8;
  int tid = threadIdx.x;

  for (int i=tid; i<12*136; i+=256){
    int ry = i/136, cc = i-ry*136;
    int gy = y0+ry-2, gx = x0+cc-2;
    float v = 0.f;
    if ((unsigned)gy<256u && (unsigned)gx<256u) v = (xb[gy*256+gx]-mean)*istd;
    xt[ry*136 + ((cc&3)*34 + (cc>>2))] = v;
  }
  float w1l[9], w1t[9];
  #pragma unroll
  for (int k=0;k<9;k++){ w1l[k]=la1w[c*9+k]; w1t[k]=ta1w[c*9+k]; }
  float b1l=la1b[c], b1t=ta1b[c];
  __syncthreads();

  for (int run=tid; run<330; run+=256){
    int r = run/33, rn = run - r*33;
    float al[4], at[4];
    #pragma unroll
    for (int o=0;o<4;o++){ al[o]=b1l; at[o]=b1t; }
    #pragma unroll
    for (int dy=0;dy<3;dy++){
      const float* xr = xt + (r+dy)*136;
      float v[6];
      v[0]=xr[rn]; v[1]=xr[34+rn]; v[2]=xr[68+rn]; v[3]=xr[102+rn];
      v[4]=xr[rn+1]; v[5]=xr[34+rn+1];
      #pragma unroll
      for (int o=0;o<4;o++){
        al[o] += v[o]*w1l[dy*3] + v[o+1]*w1l[dy*3+1] + v[o+2]*w1l[dy*3+2];
        at[o] += v[o]*w1t[dy*3] + v[o+1]*w1t[dy*3+1] + v[o+2]*w1t[dy*3+2];
      }
    }
    float2* tr = tb + r*136;
    #pragma unroll
    for (int o=0;o<4;o++)
      tr[o*34+rn] = make_float2(fmaxf(al[o],0.f), fmaxf(at[o],0.f));
  }
  __syncthreads();

  float w2l[9], w2t[9];
  #pragma unroll
  for (int k=0;k<9;k++){ w2l[k]=la2w[c*9+k]; w2t[k]=ta2w[c*9+k]; }
  int tx = tid&31, ty = tid>>5;
  float acc[4];
  float base2 = la2b[c] + ta2b[c];
  #pragma unroll
  for (int o=0;o<4;o++) acc[o]=base2;
  #pragma unroll
  for (int dy=0;dy<3;dy++){
    const float2* tr = tb + (ty+dy)*136;
    float2 t0=tr[tx], t1=tr[34+tx], t2=tr[68+tx], t3=tr[102+tx];
    float2 t4=tr[tx+1], t5=tr[34+tx+1];
    float2 tv[6] = {t0,t1,t2,t3,t4,t5};
    #pragma unroll
    for (int o=0;o<4;o++){
      #pragma unroll
      for (int dx=0;dx<3;dx++){
        float2 v = tv[o+dx];
        acc[o] += v.x*w2l[dy*3+dx] + v.y*w2t[dy*3+dx];
      }
    }
  }
  float sc = agnw[c]*g_rescale[b][c];
  float sb = agnb[c]+g_rebias[b][c];
  const float* xnr = xt + (ty+2)*136;
  float xn0 = xnr[68+tx], xn1 = xnr[102+tx], xn2 = xnr[tx+1], xn3 = xnr[34+tx+1];
  float r0 = xn0*sc + sb + acc[0];
  float r1 = xn1*sc + sb + acc[1];
  float r2 = xn2*sc + sb + acc[2];
  float r3 = xn3*sc + sb + acc[3];
  uint2 u; u.x = bf2u(r0,r1); u.y = bf2u(r2,r3);
  *(uint2*)(g_y + (size_t)bc*HW + (size_t)(y0+ty)*256 + x0 + 4*tx) = u;
}

// ---------------- K6: 5x5 reflect dwconv on Q ----------------
__global__ void k_co5(const float* __restrict__ dww, const float* __restrict__ dwb){
  int bc=blockIdx.z; int b=bc/CB, c=bc-b*CB;
  const __nv_bfloat16* Q = g_qkv + ((size_t)b*3*CB + c)*HW;
  __shared__ float tile[12][36];
  int x0=blockIdx.x*32, y0=blockIdx.y*8;
  int tid=threadIdx.y*32+threadIdx.x;
  for (int i=tid;i<432;i+=256){
    int ry=i/36, rx=i-ry*36;
    int gy=y0+ry-2, gx=x0+rx-2;
    gy = gy<0 ? -gy : (gy>255 ? 510-gy : gy);
    gx = gx<0 ? -gx : (gx>255 ? 510-gx : gx);
    tile[ry][rx] = __bfloat162float(Q[gy*256+gx]);
  }
  __syncthreads();
  float w[25];
  #pragma unroll
  for (int k=0;k<25;k++) w[k]=dww[c*25+k];
  float acc = dwb[c];
  #pragma unroll
  for (int ky=0;ky<5;ky++)
    #pragma unroll
    for (int kx=0;kx<5;kx++)
      acc += tile[threadIdx.y+ky][threadIdx.x+kx]*w[ky*5+kx];
  g_co[(size_t)bc*HW + (size_t)(y0+threadIdx.y)*256 + x0+threadIdx.x] = __float2bfloat16(acc);
}

// =====================================================================
// Tensor-core GEMM bodies. B fragments loaded via ldsm_x4 (3 per k-step).
// =====================================================================
#define SMEM_MMA 50688

// ---- single-group body (staged epilogue) — proj, m2 ----
template<int LOAD, int EPI>
__device__ __forceinline__ void mma_body(
    const void* actb, const float* W, const float* bias,
    int CinTot, int wrow0, void* outv,
    const float* xinb, int bIdx)
{
  extern __shared__ char smem_raw[];
  __nv_bfloat16* sA = (__nv_bfloat16*)smem_raw;
  __nv_bfloat16* sW = (__nv_bfloat16*)(smem_raw + (LOAD==2 ? 26624 : 24576));
  float* sStage = (float*)smem_raw;
  const int tid = threadIdx.x;
  const int px0 = blockIdx.x * 128;
  const int warp = tid >> 5, t = tid & 31;
  const int m0w = (warp>>1)*32, n0w = (warp&1)*48;
  unsigned sAb = (unsigned)__cvta_generic_to_shared(sA);
  unsigned sWb = (unsigned)__cvta_generic_to_shared(sW);

  float acc[2][6][4];
  #pragma unroll
  for (int mi=0;mi<2;mi++)
    #pragma unroll
    for (int nj=0;nj<6;nj++)
      #pragma unroll
      for (int e=0;e<4;e++) acc[mi][nj][e]=0.f;

  const int g = t>>3, gi = t&7;

  for (int k0g=0; k0g<CinTot; k0g+=96){
    if (LOAD==0){
      const float* a = (const float*)actb;
      #pragma unroll
      for (int j=0;j<12;j++){
        int i = tid + 256*j;
        int c = i>>5, px = (i&31)*4;
        float4 v = *(const float4*)(a + (size_t)(k0g+c)*HW + px0 + px);
        uint2 u; u.x = bf2u(v.x,v.y); u.y = bf2u(v.z,v.w);
        *(uint2*)(sA + c*128 + ((((px>>3)^(c&7))<<3) + (px&7))) = u;
      }
    } else if (LOAD==1){
      const __nv_bfloat16* a = (const __nv_bfloat16*)actb;
      #pragma unroll
      for (int j=0;j<6;j++){
        int i = tid + 256*j;
        int c = i>>4, s8 = (i&15)*8;
        uint4 v = *(const uint4*)(a + (size_t)(k0g+c)*HW + px0 + s8);
        *(uint4*)(sA + c*128 + ((((s8>>3)^(c&7))<<3))) = v;
      }
    } else {
      const __nv_bfloat16* a = (const __nv_bfloat16*)actb + (size_t)px0*96;
      #pragma unroll
      for (int j=0;j<6;j++){
        int i = tid + 256*j;
        int px = i/12, c0 = (i%12)*8;
        uint4 v = *(const uint4*)(a + (size_t)px*96 + c0);
        *(uint4*)(sA + px*104 + c0) = v;
      }
    }
    #pragma unroll
    for (int j=0;j<9;j++){
      int i = tid + 256*j;
      int r = i/24, c4 = (i%24)*4;
      float4 v = *(const float4*)(W + (size_t)(wrow0+r)*CinTot + k0g + c4);
      uint2 u; u.x = bf2u(v.x,v.y); u.y = bf2u(v.z,v.w);
      *(uint2*)(sW + r*104 + c4) = u;
    }
    __syncthreads();

    unsigned addrA[2], addrB[3];
    if (LOAD==2){
      int row0 = m0w + (g&1)*8 + gi;
      int kc = (g>=2)?16:0;
      addrA[0] = sAb + (row0     )*208 + kc;
      addrA[1] = sAb + (row0 + 16)*208 + kc;
    } else {
      int kb = ((g>=2)?8:0) + gi;
      int px_a0 = m0w + (g&1)*8;
      int px_a1 = px_a0 + 16;
      addrA[0] = sAb + kb*256 + ((((px_a0>>3) ^ gi)<<4));
      addrA[1] = sAb + kb*256 + ((((px_a1>>3) ^ gi)<<4));
    }
    {
      // x4 B addressing: groups 0-7:(rows n, k0-7) 8-15:(n, k8-15)
      //                  16-23:(n+8, k0-7)        24-31:(n+8, k8-15)
      int nb = n0w + (t&7) + ((t>>4)<<3);
      int kcb = ((t>>3)&1)*8;
      #pragma unroll
      for (int p=0;p<3;p++) addrB[p] = sWb + (nb + p*16)*208 + kcb*2;
    }

    #pragma unroll
    for (int ks=0; ks<6; ks++){
      unsigned a[2][4], br[3][4];
      if (LOAD==2){ ldsm_x4(addrA[0], a[0][0],a[0][1],a[0][2],a[0][3]);
                    ldsm_x4(addrA[1], a[1][0],a[1][1],a[1][2],a[1][3]); }
      else        { ldsm_x4_t(addrA[0], a[0][0],a[0][1],a[0][2],a[0][3]);
                    ldsm_x4_t(addrA[1], a[1][0],a[1][1],a[1][2],a[1][3]); }
      #pragma unroll
      for (int p=0;p<3;p++) ldsm_x4(addrB[p], br[p][0],br[p][1],br[p][2],br[p][3]);
      #pragma unroll
      for (int mi=0;mi<2;mi++)
        #pragma unroll
        for (int nj=0;nj<6;nj++)
          mma16816(acc[mi][nj], a[mi], &br[nj>>1][(nj&1)*2]);
      if (LOAD==2){ addrA[0]+=32; addrA[1]+=32; }
      else        { addrA[0]+=4096; addrA[1]+=4096; }
      #pragma unroll
      for (int p=0;p<3;p++) addrB[p]+=32;
    }
    __syncthreads();
  }

  #pragma unroll
  for (int mi=0;mi<2;mi++)
    #pragma unroll
    for (int nj=0;nj<6;nj++){
      int m = m0w + mi*16 + (t>>2);
      int n = n0w + nj*8 + (t&3)*2;
      sStage[(n  )*132 + m  ] = acc[mi][nj][0];
      sStage[(n+1)*132 + m  ] = acc[mi][nj][1];
      sStage[(n  )*132 + m+8] = acc[mi][nj][2];
      sStage[(n+1)*132 + m+8] = acc[mi][nj][3];
    }
  __syncthreads();

  const int tx = tid&31, ty = tid>>5;
  #pragma unroll
  for (int r=0;r<12;r++){
    int o = ty*12 + r;
    float4 v = *(float4*)(sStage + o*132 + tx*4);
    float bv = bias[wrow0+o];
    v.x+=bv; v.y+=bv; v.z+=bv; v.w+=bv;
    size_t off = (size_t)o*HW + px0 + tx*4;
    if (EPI==2){
      float4 q = *(const float4*)(xinb + off);
      v.x+=q.x; v.y+=q.y; v.z+=q.z; v.w+=q.w;
      *(float4*)((float*)outv + off) = v;
    } else if (EPI==3){
      float rs = g_rescale[bIdx][o], rb = g_rebias[bIdx][o];
      float4 xi = *(const float4*)(xinb + off);
      v = make_float4(xi.x + v.x*rs + rb, xi.y + v.y*rs + rb,
                      xi.z + v.z*rs + rb, xi.w + v.w*rs + rb);
      *(float4*)((float*)outv + off) = v;
    } else {
      *(float4*)((float*)outv + off) = v;
    }
  }
}

// ---- multi-group body: act loaded ONCE; stage overlaps sW (occ stays 4) ----
template<int LOAD, int RELU, int GROUPS>
__device__ __forceinline__ void mma_multi(
    const void* actb, const float* const* Wg, const float* const* biasg,
    const int* wrow0g, __nv_bfloat16* const* outg)
{
  extern __shared__ char smem_raw[];
  __nv_bfloat16* sA = (__nv_bfloat16*)smem_raw;
  __nv_bfloat16* sW = (__nv_bfloat16*)(smem_raw + 24576);      // 19968 B
  __nv_bfloat16* sStage = (__nv_bfloat16*)(smem_raw + 24576);  // [96][136] bf16, OVERLAPS sW
  const int tid = threadIdx.x;
  const int px0 = blockIdx.x * 128;
  const int warp = tid >> 5, t = tid & 31;
  const int m0w = (warp>>1)*32, n0w = (warp&1)*48;
  unsigned sAb = (unsigned)__cvta_generic_to_shared(sA);
  unsigned sWb = (unsigned)__cvta_generic_to_shared(sW);
  const int g = t>>3, gi = t&7;

  // ---- load activation tile once ----
  if (LOAD==0){
    const float* a = (const float*)actb;
    #pragma unroll
    for (int j=0;j<12;j++){
      int i = tid + 256*j;
      int c = i>>5, px = (i&31)*4;
      float4 v = *(const float4*)(a + (size_t)c*HW + px0 + px);
      uint2 u; u.x = bf2u(v.x,v.y); u.y = bf2u(v.z,v.w);
      *(uint2*)(sA + c*128 + ((((px>>3)^(c&7))<<3) + (px&7))) = u;
    }
  } else {
    const __nv_bfloat16* a = (const __nv_bfloat16*)actb;
    #pragma unroll
    for (int j=0;j<6;j++){
      int i = tid + 256*j;
      int c = i>>4, s8 = (i&15)*8;
      uint4 v = *(const uint4*)(a + (size_t)c*HW + px0 + s8);
      *(uint4*)(sA + c*128 + ((((s8>>3)^(c&7))<<3))) = v;
    }
  }

  unsigned addrA0[2];
  {
    int kb = ((g>=2)?8:0) + gi;
    int px_a0 = m0w + (g&1)*8;
    int px_a1 = px_a0 + 16;
    addrA0[0] = sAb + kb*256 + ((((px_a0>>3) ^ gi)<<4));
    addrA0[1] = sAb + kb*256 + ((((px_a1>>3) ^ gi)<<4));
  }
  unsigned addrB0;
  {
    int nb = n0w + (t&7) + ((t>>4)<<3);
    int kcb = ((t>>3)&1)*8;
    addrB0 = sWb + nb*208 + kcb*2;
  }

  #pragma unroll
  for (int grp=0; grp<GROUPS; grp++){
    const float* W = Wg[grp];
    int wrow0 = wrow0g[grp];
    // ---- load W for this group (stage region from prev group is free:
    //      the loop-end sync separates prior stage reads from this write) ----
    #pragma unroll
    for (int j=0;j<9;j++){
      int i = tid + 256*j;
      int r = i/24, c4 = (i%24)*4;
      float4 v = *(const float4*)(W + (size_t)(wrow0+r)*96 + c4);
      uint2 u; u.x = bf2u(v.x,v.y); u.y = bf2u(v.z,v.w);
      *(uint2*)(sW + r*104 + c4) = u;
    }
    __syncthreads();

    float acc[2][6][4];
    #pragma unroll
    for (int mi=0;mi<2;mi++)
      #pragma unroll
      for (int nj=0;nj<6;nj++)
        #pragma unroll
        for (int e=0;e<4;e++) acc[mi][nj][e]=0.f;

    unsigned addrA[2] = {addrA0[0], addrA0[1]};
    unsigned addrB[3];
    #pragma unroll
    for (int p=0;p<3;p++) addrB[p] = addrB0 + p*16*208;

    #pragma unroll
    for (int ks=0; ks<6; ks++){
      unsigned a[2][4], br[3][4];
      ldsm_x4_t(addrA[0], a[0][0],a[0][1],a[0][2],a[0][3]);
      ldsm_x4_t(addrA[1], a[1][0],a[1][1],a[1][2],a[1][3]);
      #pragma unroll
      for (int p=0;p<3;p++) ldsm_x4(addrB[p], br[p][0],br[p][1],br[p][2],br[p][3]);
      #pragma unroll
      for (int mi=0;mi<2;mi++)
        #pragma unroll
        for (int nj=0;nj<6;nj++)
          mma16816(acc[mi][nj], a[mi], &br[nj>>1][(nj&1)*2]);
      addrA[0]+=4096; addrA[1]+=4096;
      #pragma unroll
      for (int p=0;p<3;p++) addrB[p]+=32;
    }
    __syncthreads();   // all warps done reading sW -> safe to overwrite as stage

    // ---- stage accumulators (bias+relu applied) into bf16 smem ----
    const float* bias = biasg[grp];
    #pragma unroll
    for (int nj=0;nj<6;nj++){
      int nl = n0w + nj*8 + (t&3)*2;
      float b0 = __ldg(bias + wrow0g[grp] + nl);
      float b1 = __ldg(bias + wrow0g[grp] + nl + 1);
      #pragma unroll
      for (int mi=0;mi<2;mi++){
        int m = m0w + mi*16 + (t>>2);
        float c0 = acc[mi][nj][0] + b0;
        float c1 = acc[mi][nj][1] + b1;
        float c2 = acc[mi][nj][2] + b0;
        float c3 = acc[mi][nj][3] + b1;
        if (RELU){
          c0=fmaxf(c0,0.f); c1=fmaxf(c1,0.f); c2=fmaxf(c2,0.f); c3=fmaxf(c3,0.f);
        }
        sStage[nl*136 + m        ] = __float2bfloat16(c0);
        sStage[(nl+1)*136 + m    ] = __float2bfloat16(c1);
        sStage[nl*136 + m + 8    ] = __float2bfloat16(c2);
        sStage[(nl+1)*136 + m + 8] = __float2bfloat16(c3);
      }
    }
    __syncthreads();

    // ---- vectorized writeout: 96ch x 128px bf16 = 1536 uint4 ----
    __nv_bfloat16* outb = outg[grp];
    #pragma unroll
    for (int j=0;j<6;j++){
      int i4 = tid + 256*j;
      int ch = i4>>4, seg = i4&15;
      uint4 v = *(const uint4*)(sStage + ch*136 + seg*8);
      *(uint4*)(outb + (size_t)ch*HW + px0 + seg*8) = v;
    }
    __syncthreads();   // stage reads done before next group's W overwrites it
  }
}

__global__ void __launch_bounds__(256) k_mma_qkv(
    const float* __restrict__ qW, const float* __restrict__ qb,
    const float* __restrict__ kvW, const float* __restrict__ kvb)
{
  int b = blockIdx.z;
  const __nv_bfloat16* actb = g_y + (size_t)b*CB*HW;
  __nv_bfloat16* o0 = g_qkv + ((size_t)b*3*CB + 0 )*HW;
  __nv_bfloat16* o1 = g_qkv + ((size_t)b*3*CB + 96)*HW;
  __nv_bfloat16* o2 = g_qkv + ((size_t)b*3*CB +192)*HW;
  const float* Wg[3]    = {qW, kvW, kvW};
  const float* biasg[3] = {qb, kvb, kvb};
  int wrow0g[3]         = {0, 0, 96};
  __nv_bfloat16* outg[3]= {o0, o1, o2};
  mma_multi<1,0,3>(actb, Wg, biasg, wrow0g, outg);
}

__global__ void __launch_bounds__(256) k_mma_m1(
    const float* __restrict__ W, const float* __restrict__ bias)
{
  int b = blockIdx.z;
  const float* actb = g_x2 + (size_t)b*CB*HW;
  __nv_bfloat16* hb = g_hid + (size_t)b*4*CB*HW;
  const float* Wg[4]    = {W, W, W, W};
  const float* biasg[4] = {bias, bias, bias, bias};
  int wrow0g[4]         = {0, 96, 192, 288};
  __nv_bfloat16* outg[4]= {hb, hb+(size_t)96*HW, hb+(size_t)192*HW, hb+(size_t)288*HW};
  mma_multi<0,1,4>(actb, Wg, biasg, wrow0g, outg);
}

__global__ void __launch_bounds__(256) k_mma_proj(
    const float* __restrict__ W, const float* __restrict__ bias,
    const float* __restrict__ xin)
{
  int b = blockIdx.z;
  const __nv_bfloat16* actb = g_attn + (size_t)b*HW*96;
  mma_body<2,3>(actb, W, bias, 96, 0, g_x2 + (size_t)b*CB*HW,
                xin + (size_t)b*CB*HW, b);
}

__global__ void __launch_bounds__(256) k_mma_m2(
    const float* __restrict__ W, const float* __restrict__ bias,
    float* __restrict__ out)
{
  int b = blockIdx.z;
  mma_body<1,2>(g_hid + (size_t)b*4*CB*HW, W, bias, 384, 0,
                out + (size_t)b*CB*HW, g_x2 + (size_t)b*CB*HW, b);
}

// ---------------- attention: one (window, head) per 64-thread block ----------------
__global__ void __launch_bounds__(64) k_attn(const float* __restrict__ lsp){
  __shared__ __align__(16) float sK[32][64];
  __shared__ __align__(16) float sVt[64][36];
  int widx=blockIdx.x, h=blockIdx.y;
  int b=widx>>10, rem=widx&1023;
  int r0=(rem>>5)*8, c0=(rem&31)*8;
  int t=threadIdx.x;
  float ls = __expf(fminf(lsp[0], LOGIT_MAXV));
  size_t baseK = ((size_t)b*3*CB +   CB + h*32)*HW;
  size_t baseV = ((size_t)b*3*CB + 2*CB + h*32)*HW;
  for (int i=t;i<2048;i+=64){
    int d=i>>6, m=i&63;
    int hw = (r0+(m>>3))*256 + c0 + (m&7);
    sK[d][m]  = __bfloat162float(g_qkv[baseK + (size_t)d*HW + hw])*SCALEV;
    sVt[m][d] = __bfloat162float(g_qkv[baseV + (size_t)d*HW + hw]);
  }
  int hw_t = (r0+(t>>3))*256 + c0 + (t&7);
  size_t baseQ = ((size_t)b*CB + h*32)*HW;
  unsigned long long q2[32];
  #pragma unroll
  for (int d=0;d<32;d++)
    q2[d] = pack2(__bfloat162float(g_co[baseQ + (size_t)d*HW + hw_t]));
  __syncthreads();
  float l[64];
  const float* brow = &g_bias_tab[h][t][0];
  #pragma unroll
  for (int m0=0;m0<64;m0+=4){
    unsigned long long s01=0ull, s23=0ull;
    #pragma unroll
    for (int d=0;d<32;d++){
      ulonglong2 kk = *(const ulonglong2*)&sK[d][m0];
      ffma2(s01, q2[d], kk.x);
      ffma2(s23, q2[d], kk.y);
    }
    float2 pa=u2f(s01), pb=u2f(s23);
    float4 bi = *(const float4*)(brow + m0);
    l[m0  ]=pa.x*ls+bi.x; l[m0+1]=pa.y*ls+bi.y;
    l[m0+2]=pb.x*ls+bi.z; l[m0+3]=pb.y*ls+bi.w;
  }
  float mx=l[0];
  #pragma unroll
  for (int m=1;m<64;m++) mx = fmaxf(mx,l[m]);
  float sum=0.f;
  #pragma unroll
  for (int m=0;m<64;m++){ float e=__expf(l[m]-mx); l[m]=e; sum+=e; }
  float inv = 1.f/sum;
  unsigned long long o2[16];
  #pragma unroll
  for (int i=0;i<16;i++) o2[i]=0ull;
  #pragma unroll
  for (int m=0;m<64;m++){
    unsigned long long p2 = pack2(l[m]);
    const ulonglong2* vp = (const ulonglong2*)&sVt[m][0];
    #pragma unroll
    for (int dd=0;dd<8;dd++){
      ulonglong2 vv = vp[dd];
      ffma2(o2[2*dd  ], p2, vv.x);
      ffma2(o2[2*dd+1], p2, vv.y);
    }
  }
  __nv_bfloat16* dst = g_attn + ((size_t)b*HW + hw_t)*96 + h*32;
  #pragma unroll
  for (int k=0;k<8;k++){
    float2 pa=u2f(o2[2*k]), pb=u2f(o2[2*k+1]);
    uint2 u; u.x = bf2u(pa.x*inv, pa.y*inv); u.y = bf2u(pb.x*inv, pb.y*inv);
    *(uint2*)(dst + 4*k) = u;
  }
}

// ---------------- host launch ----------------
extern "C" void kernel_launch(void* const* d_in, const int* in_sizes, int n_in,
                              void* d_out, int out_size){
  const float* x       = (const float*)d_in[0];
  const float* agn_w   = (const float*)d_in[1];
  const float* agn_b   = (const float*)d_in[2];
  const float* meta1_w = (const float*)d_in[3];
  const float* meta1_b = (const float*)d_in[4];
  const float* meta2_w = (const float*)d_in[5];
  const float* meta2_b = (const float*)d_in[6];
  const float* la1_w   = (const float*)d_in[7];
  const float* la1_b   = (const float*)d_in[8];
  const float* la2_w   = (const float*)d_in[9];
  const float* la2_b   = (const float*)d_in[10];
  const float* ta1_w   = (const float*)d_in[11];
  const float* ta1_b   = (const float*)d_in[12];
  const float* ta2_w   = (const float*)d_in[13];
  const float* ta2_b   = (const float*)d_in[14];
  const float* q_w     = (const float*)d_in[15];
  const float* q_b     = (const float*)d_in[16];
  const float* kv_w    = (const float*)d_in[17];
  const float* kv_b    = (const float*)d_in[18];
  const float* dw_w    = (const float*)d_in[19];
  const float* dw_b    = (const float*)d_in[20];
  const float* proj_w  = (const float*)d_in[21];
  const float* proj_b  = (const float*)d_in[22];
  const float* logit_s = (const float*)d_in[23];
  const float* rp_w1   = (const float*)d_in[24];
  const float* rp_b1   = (const float*)d_in[25];
  const float* rp_w2   = (const float*)d_in[26];
  const float* rp_b2   = (const float*)d_in[27];
  const float* m1_w    = (const float*)d_in[28];
  const float* m1_b    = (const float*)d_in[29];
  const float* m2_w    = (const float*)d_in[30];
  const float* m2_b    = (const float*)d_in[31];
  float* out = (float*)d_out;

  cudaFuncSetAttribute(k_mma_qkv, cudaFuncAttributeMaxDynamicSharedMemorySize, SMEM_MMA);
  cudaFuncSetAttribute(k_mma_m1,  cudaFuncAttributeMaxDynamicSharedMemorySize, SMEM_MMA);
  cudaFuncSetAttribute(k_mma_proj,cudaFuncAttributeMaxDynamicSharedMemorySize, SMEM_MMA);
  cudaFuncSetAttribute(k_mma_m2,  cudaFuncAttributeMaxDynamicSharedMemorySize, SMEM_MMA);

  // 1. stats + bias table
  k_reduce_partial<<<dim3(192,BATCH), 256>>>(x);
  k_finalize<<<BATCH, 256>>>(meta1_w, meta1_b, meta2_w, meta2_b);
  k_bias<<<64, 64>>>(rp_w1, rp_b1, rp_w2, rp_b2);

  // 2. fused AGN (writes bf16 g_y)
  dim3 agrid(IMG/128, IMG/8, BATCH*CB);
  k_agn_fused<<<agrid, 256>>>(x, agn_w, agn_b, la1_w, la1_b, la2_w, la2_b,
                              ta1_w, ta1_b, ta2_w, ta2_b);

  // 3. QKV projections — merged, act loaded once, occ-4 smem footprint
  k_mma_qkv<<<dim3(512,1,BATCH), 256, SMEM_MMA>>>(q_w, q_b, kv_w, kv_b);

  // 4. reflect 5x5 dwconv on Q, then window attention
  dim3 cgrid(IMG/32, IMG/8, BATCH*CB), cblk(32, 8);
  k_co5<<<cgrid, cblk>>>(dw_w, dw_b);
  k_attn<<<dim3(4096,3), 64>>>(logit_s);

  // 5. proj + residual/rescale/rebias -> g_x2 (fp32)
  k_mma_proj<<<dim3(512,1,BATCH), 256, SMEM_MMA>>>(proj_w, proj_b, x);

  // 6. MLP (merged m1, then m2 with residual -> out)
  k_mma_m1<<<dim3(512,1,BATCH), 256, SMEM_MMA>>>(m1_w, m1_b);
  k_mma_m2<<<dim3(512,1,BATCH), 256, SMEM_MMA>>>(m2_w, m2_b, out);
}

// round 14
// speedup vs baseline: 1.0677x; 1.0236x over previous
#include <cuda_runtime.h>
#include <cuda_bf16.h>
#include <math.h>

#define HW 65536
#define IMG 256
#define CB 96
#define BATCH 4

// ---------------- device scratch ----------------
__device__ float g_mean[BATCH], g_istd[BATCH];
__device__ float g_rescale[BATCH][CB], g_rebias[BATCH][CB];
__device__ float g_partial[BATCH][192][2];
__device__ float g_bias_tab[3][64][64];

__device__ __nv_bfloat16 g_y  [(size_t)BATCH*CB*HW];
__device__ __nv_bfloat16 g_qkv[(size_t)BATCH*3*CB*HW];
__device__ __nv_bfloat16 g_co [(size_t)BATCH*CB*HW];
__device__ __nv_bfloat16 g_attn[(size_t)BATCH*HW*CB];
__device__ float         g_x2 [(size_t)BATCH*CB*HW];
__device__ __nv_bfloat16 g_hid[(size_t)BATCH*4*CB*HW];

#define SCALEV 0.17677669529663687f
#define LOGIT_MAXV 4.605170185988091f

// ---------------- f32x2 helpers ----------------
__device__ __forceinline__ unsigned long long pack2(float w){
  unsigned long long r; asm("mov.b64 %0, {%1, %1};" : "=l"(r) : "f"(w)); return r;
}
__device__ __forceinline__ float2 u2f(unsigned long long v){
  float2 f; asm("mov.b64 {%0, %1}, %2;" : "=f"(f.x), "=f"(f.y) : "l"(v)); return f;
}
__device__ __forceinline__ void ffma2(unsigned long long &d, unsigned long long a, unsigned long long b){
  asm("fma.rn.f32x2 %0, %1, %2, %0;" : "+l"(d) : "l"(a), "l"(b));
}

// ---------------- mma helpers ----------------
__device__ __forceinline__ void ldsm_x4(unsigned addr, unsigned &r0, unsigned &r1, unsigned &r2, unsigned &r3){
  asm volatile("ldmatrix.sync.aligned.m8n8.x4.shared.b16 {%0,%1,%2,%3}, [%4];"
    : "=r"(r0),"=r"(r1),"=r"(r2),"=r"(r3) : "r"(addr));
}
__device__ __forceinline__ void ldsm_x4_t(unsigned addr, unsigned &r0, unsigned &r1, unsigned &r2, unsigned &r3){
  asm volatile("ldmatrix.sync.aligned.m8n8.x4.trans.shared.b16 {%0,%1,%2,%3}, [%4];"
    : "=r"(r0),"=r"(r1),"=r"(r2),"=r"(r3) : "r"(addr));
}
__device__ __forceinline__ void mma16816(float* c, const unsigned* a, const unsigned* b){
  asm volatile("mma.sync.aligned.m16n8k16.row.col.f32.bf16.bf16.f32 "
    "{%0,%1,%2,%3},{%4,%5,%6,%7},{%8,%9},{%0,%1,%2,%3};"
    : "+f"(c[0]),"+f"(c[1]),"+f"(c[2]),"+f"(c[3])
    : "r"(a[0]),"r"(a[1]),"r"(a[2]),"r"(a[3]),"r"(b[0]),"r"(b[1]));
}
__device__ __forceinline__ unsigned bf2u(float x, float y){
  __nv_bfloat162 t = __floats2bfloat162_rn(x, y);
  return reinterpret_cast<unsigned&>(t);
}

// ---------------- K1: per-sample partial sums ----------------
__global__ void k_reduce_partial(const float* __restrict__ x){
  int b = blockIdx.y, blk = blockIdx.x, tid = threadIdx.x;
  const float4* xb = (const float4*)(x + (size_t)b*CB*HW);
  size_t base = (size_t)blk*8192;
  float s=0.f, s2=0.f;
  for (int i=tid;i<8192;i+=256){
    float4 v = xb[base+i];
    s  += v.x+v.y+v.z+v.w;
    s2 += v.x*v.x+v.y*v.y+v.z*v.z+v.w*v.w;
  }
  __shared__ float rs[256], rq[256];
  rs[tid]=s; rq[tid]=s2; __syncthreads();
  for (int st=128;st>0;st>>=1){
    if (tid<st){ rs[tid]+=rs[tid+st]; rq[tid]+=rq[tid+st]; }
    __syncthreads();
  }
  if (tid==0){ g_partial[b][blk][0]=rs[0]; g_partial[b][blk][1]=rq[0]; }
}

// ---------------- K2: finalize ----------------
__global__ void k_finalize(const float* __restrict__ m1w, const float* __restrict__ m1b,
                           const float* __restrict__ m2w, const float* __restrict__ m2b){
  int b = blockIdx.x, tid = threadIdx.x;
  __shared__ float rs[256], rq[256];
  rs[tid] = (tid<192)? g_partial[b][tid][0] : 0.f;
  rq[tid] = (tid<192)? g_partial[b][tid][1] : 0.f;
  __syncthreads();
  for (int st=128;st>0;st>>=1){
    if (tid<st){ rs[tid]+=rs[tid+st]; rq[tid]+=rq[tid+st]; }
    __syncthreads();
  }
  __shared__ float sh_mean, sh_std;
  if (tid==0){
    float M = (float)((size_t)CB*HW);
    float mean = rs[0]/M;
    float var  = rq[0]/M - mean*mean;
    float sd   = sqrtf(var + 1e-5f);
    g_mean[b]=mean; g_istd[b]=1.f/sd;
    sh_mean=mean; sh_std=sd;
  }
  __syncthreads();
  if (tid<CB){
    g_rescale[b][tid] = sh_std *m1w[tid] + m1b[tid];
    g_rebias [b][tid] = sh_mean*m2w[tid] + m2b[tid];
  }
}

// ---------------- K3: relative-position bias table ----------------
__global__ void k_bias(const float* __restrict__ w1, const float* __restrict__ b1,
                       const float* __restrict__ w2, const float* __restrict__ b2){
  int n = blockIdx.x, m = threadIdx.x;
  float di = (float)((n>>3) - (m>>3));
  float dj = (float)((n&7) - (m&7));
  float a0l = log1pf(fabsf(di)); float r0 = di<0.f ? -a0l : (di>0.f ? a0l : 0.f);
  float a1l = log1pf(fabsf(dj)); float r1 = dj<0.f ? -a1l : (dj>0.f ? a1l : 0.f);
  float a0=0.f,a1=0.f,a2=0.f;
  for (int k=0;k<256;k++){
    float h = fmaxf(r0*w1[2*k]+r1*w1[2*k+1]+b1[k], 0.f);
    a0 += h*w2[k]; a1 += h*w2[256+k]; a2 += h*w2[512+k];
  }
  g_bias_tab[0][n][m]=a0+b2[0];
  g_bias_tab[1][n][m]=a1+b2[1];
  g_bias_tab[2][n][m]=a2+b2[2];
}

// ---------------- K4: fused AGN (kept from R5/R6) ----------------
__global__ void __launch_bounds__(256) k_agn_fused(const float* __restrict__ x,
    const float* __restrict__ agnw, const float* __restrict__ agnb,
    const float* __restrict__ la1w, const float* __restrict__ la1b,
    const float* __restrict__ la2w, const float* __restrict__ la2b,
    const float* __restrict__ ta1w, const float* __restrict__ ta1b,
    const float* __restrict__ ta2w, const float* __restrict__ ta2b){
  __shared__ float xt[12*136];
  __shared__ __align__(8) float2 tb[10*136];
  int bc = blockIdx.z; int b = bc/CB, c = bc - b*CB;
  const float* xb = x + (size_t)bc*HW;
  float mean = g_mean[b], istd = g_istd[b];
  int x0 = blockIdx.x*128, y0 = blockIdx.y*8;
  int tid = threadIdx.x;

  for (int i=tid; i<12*136; i+=256){
    int ry = i/136, cc = i-ry*136;
    int gy = y0+ry-2, gx = x0+cc-2;
    float v = 0.f;
    if ((unsigned)gy<256u && (unsigned)gx<256u) v = (xb[gy*256+gx]-mean)*istd;
    xt[ry*136 + ((cc&3)*34 + (cc>>2))] = v;
  }
  float w1l[9], w1t[9];
  #pragma unroll
  for (int k=0;k<9;k++){ w1l[k]=la1w[c*9+k]; w1t[k]=ta1w[c*9+k]; }
  float b1l=la1b[c], b1t=ta1b[c];
  __syncthreads();

  for (int run=tid; run<330; run+=256){
    int r = run/33, rn = run - r*33;
    float al[4], at[4];
    #pragma unroll
    for (int o=0;o<4;o++){ al[o]=b1l; at[o]=b1t; }
    #pragma unroll
    for (int dy=0;dy<3;dy++){
      const float* xr = xt + (r+dy)*136;
      float v[6];
      v[0]=xr[rn]; v[1]=xr[34+rn]; v[2]=xr[68+rn]; v[3]=xr[102+rn];
      v[4]=xr[rn+1]; v[5]=xr[34+rn+1];
      #pragma unroll
      for (int o=0;o<4;o++){
        al[o] += v[o]*w1l[dy*3] + v[o+1]*w1l[dy*3+1] + v[o+2]*w1l[dy*3+2];
        at[o] += v[o]*w1t[dy*3] + v[o+1]*w1t[dy*3+1] + v[o+2]*w1t[dy*3+2];
      }
    }
    float2* tr = tb + r*136;
    #pragma unroll
    for (int o=0;o<4;o++)
      tr[o*34+rn] = make_float2(fmaxf(al[o],0.f), fmaxf(at[o],0.f));
  }
  __syncthreads();

  float w2l[9], w2t[9];
  #pragma unroll
  for (int k=0;k<9;k++){ w2l[k]=la2w[c*9+k]; w2t[k]=ta2w[c*9+k]; }
  int tx = tid&31, ty = tid>>5;
  float acc[4];
  float base2 = la2b[c] + ta2b[c];
  #pragma unroll
  for (int o=0;o<4;o++) acc[o]=base2;
  #pragma unroll
  for (int dy=0;dy<3;dy++){
    const float2* tr = tb + (ty+dy)*136;
    float2 t0=tr[tx], t1=tr[34+tx], t2=tr[68+tx], t3=tr[102+tx];
    float2 t4=tr[tx+1], t5=tr[34+tx+1];
    float2 tv[6] = {t0,t1,t2,t3,t4,t5};
    #pragma unroll
    for (int o=0;o<4;o++){
      #pragma unroll
      for (int dx=0;dx<3;dx++){
        float2 v = tv[o+dx];
        acc[o] += v.x*w2l[dy*3+dx] + v.y*w2t[dy*3+dx];
      }
    }
  }
  float sc = agnw[c]*g_rescale[b][c];
  float sb = agnb[c]+g_rebias[b][c];
  const float* xnr = xt + (ty+2)*136;
  float xn0 = xnr[68+tx], xn1 = xnr[102+tx], xn2 = xnr[tx+1], xn3 = xnr[34+tx+1];
  float r0 = xn0*sc + sb + acc[0];
  float r1 = xn1*sc + sb + acc[1];
  float r2 = xn2*sc + sb + acc[2];
  float r3 = xn3*sc + sb + acc[3];
  uint2 u; u.x = bf2u(r0,r1); u.y = bf2u(r2,r3);
  *(uint2*)(g_y + (size_t)bc*HW + (size_t)(y0+ty)*256 + x0 + 4*tx) = u;
}

// ---------------- K6: 5x5 reflect dwconv on Q ----------------
__global__ void k_co5(const float* __restrict__ dww, const float* __restrict__ dwb){
  int bc=blockIdx.z; int b=bc/CB, c=bc-b*CB;
  const __nv_bfloat16* Q = g_qkv + ((size_t)b*3*CB + c)*HW;
  __shared__ float tile[12][36];
  int x0=blockIdx.x*32, y0=blockIdx.y*8;
  int tid=threadIdx.y*32+threadIdx.x;
  for (int i=tid;i<432;i+=256){
    int ry=i/36, rx=i-ry*36;
    int gy=y0+ry-2, gx=x0+rx-2;
    gy = gy<0 ? -gy : (gy>255 ? 510-gy : gy);
    gx = gx<0 ? -gx : (gx>255 ? 510-gx : gx);
    tile[ry][rx] = __bfloat162float(Q[gy*256+gx]);
  }
  __syncthreads();
  float w[25];
  #pragma unroll
  for (int k=0;k<25;k++) w[k]=dww[c*25+k];
  float acc = dwb[c];
  #pragma unroll
  for (int ky=0;ky<5;ky++)
    #pragma unroll
    for (int kx=0;kx<5;kx++)
      acc += tile[threadIdx.y+ky][threadIdx.x+kx]*w[ky*5+kx];
  g_co[(size_t)bc*HW + (size_t)(y0+threadIdx.y)*256 + x0+threadIdx.x] = __float2bfloat16(acc);
}

// =====================================================================
// Tensor-core GEMM (R6 structure; B operand via ldsm_x4, 3 per k-step)
// LOAD: 0 fp32 CM, 1 bf16 CM, 2 bf16 PM
// EPI: 0 bias->fp32, 1 bias+relu->bf16, 2 bias+resid->fp32,
//      3 xin+(v+bias)*rescale+rebias->fp32, 4 bias->bf16
// =====================================================================
#define SMEM_MMA 50688

template<int LOAD, int EPI>
__device__ __forceinline__ void mma_body(
    const void* actb, const float* W, const float* bias,
    int CinTot, int wrow0, void* outv,
    const float* xinb, int bIdx)
{
  extern __shared__ char smem_raw[];
  __nv_bfloat16* sA = (__nv_bfloat16*)smem_raw;
  __nv_bfloat16* sW = (__nv_bfloat16*)(smem_raw + (LOAD==2 ? 26624 : 24576));
  float* sStage = (float*)smem_raw;
  const int tid = threadIdx.x;
  const int px0 = blockIdx.x * 128;
  const int warp = tid >> 5, t = tid & 31;
  const int m0w = (warp>>1)*32, n0w = (warp&1)*48;
  unsigned sAb = (unsigned)__cvta_generic_to_shared(sA);
  unsigned sWb = (unsigned)__cvta_generic_to_shared(sW);

  float acc[2][6][4];
  #pragma unroll
  for (int mi=0;mi<2;mi++)
    #pragma unroll
    for (int nj=0;nj<6;nj++)
      #pragma unroll
      for (int e=0;e<4;e++) acc[mi][nj][e]=0.f;

  const int g = t>>3, gi = t&7;

  for (int k0g=0; k0g<CinTot; k0g+=96){
    if (LOAD==0){
      const float* a = (const float*)actb;
      #pragma unroll
      for (int j=0;j<12;j++){
        int i = tid + 256*j;
        int c = i>>5, px = (i&31)*4;
        float4 v = *(const float4*)(a + (size_t)(k0g+c)*HW + px0 + px);
        uint2 u; u.x = bf2u(v.x,v.y); u.y = bf2u(v.z,v.w);
        *(uint2*)(sA + c*128 + ((((px>>3)^(c&7))<<3) + (px&7))) = u;
      }
    } else if (LOAD==1){
      const __nv_bfloat16* a = (const __nv_bfloat16*)actb;
      #pragma unroll
      for (int j=0;j<6;j++){
        int i = tid + 256*j;
        int c = i>>4, s8 = (i&15)*8;
        uint4 v = *(const uint4*)(a + (size_t)(k0g+c)*HW + px0 + s8);
        *(uint4*)(sA + c*128 + ((((s8>>3)^(c&7))<<3))) = v;
      }
    } else {
      const __nv_bfloat16* a = (const __nv_bfloat16*)actb + (size_t)px0*96;
      #pragma unroll
      for (int j=0;j<6;j++){
        int i = tid + 256*j;
        int px = i/12, c0 = (i%12)*8;
        uint4 v = *(const uint4*)(a + (size_t)px*96 + c0);
        *(uint4*)(sA + px*104 + c0) = v;
      }
    }
    #pragma unroll
    for (int j=0;j<9;j++){
      int i = tid + 256*j;
      int r = i/24, c4 = (i%24)*4;
      float4 v = *(const float4*)(W + (size_t)(wrow0+r)*CinTot + k0g + c4);
      uint2 u; u.x = bf2u(v.x,v.y); u.y = bf2u(v.z,v.w);
      *(uint2*)(sW + r*104 + c4) = u;
    }
    __syncthreads();

    unsigned addrA[2], addrB[3];
    if (LOAD==2){
      int row0 = m0w + (g&1)*8 + gi;
      int kc = (g>=2)?16:0;
      addrA[0] = sAb + (row0     )*208 + kc;
      addrA[1] = sAb + (row0 + 16)*208 + kc;
    } else {
      int kb = ((g>=2)?8:0) + gi;
      int px_a0 = m0w + (g&1)*8;
      int px_a1 = px_a0 + 16;
      addrA[0] = sAb + kb*256 + ((((px_a0>>3) ^ gi)<<4));
      addrA[1] = sAb + kb*256 + ((((px_a1>>3) ^ gi)<<4));
    }
    {
      // x4 B addressing: thread groups 0-7:(row n, k0-7) 8-15:(n, k8-15)
      //                  16-23:(n+8, k0-7)  24-31:(n+8, k8-15)
      int nb = n0w + (t&7) + ((t>>4)<<3);
      int kcb = ((t>>3)&1)*8;
      #pragma unroll
      for (int p=0;p<3;p++) addrB[p] = sWb + (nb + p*16)*208 + kcb*2;
    }

    #pragma unroll
    for (int ks=0; ks<6; ks++){
      unsigned a[2][4], br[3][4];
      if (LOAD==2){ ldsm_x4(addrA[0], a[0][0],a[0][1],a[0][2],a[0][3]);
                    ldsm_x4(addrA[1], a[1][0],a[1][1],a[1][2],a[1][3]); }
      else        { ldsm_x4_t(addrA[0], a[0][0],a[0][1],a[0][2],a[0][3]);
                    ldsm_x4_t(addrA[1], a[1][0],a[1][1],a[1][2],a[1][3]); }
      #pragma unroll
      for (int p=0;p<3;p++) ldsm_x4(addrB[p], br[p][0],br[p][1],br[p][2],br[p][3]);
      #pragma unroll
      for (int mi=0;mi<2;mi++)
        #pragma unroll
        for (int nj=0;nj<6;nj++)
          mma16816(acc[mi][nj], a[mi], &br[nj>>1][(nj&1)*2]);
      if (LOAD==2){ addrA[0]+=32; addrA[1]+=32; }
      else        { addrA[0]+=4096; addrA[1]+=4096; }
      #pragma unroll
      for (int p=0;p<3;p++) addrB[p]+=32;
    }
    __syncthreads();
  }

  #pragma unroll
  for (int mi=0;mi<2;mi++)
    #pragma unroll
    for (int nj=0;nj<6;nj++){
      int m = m0w + mi*16 + (t>>2);
      int n = n0w + nj*8 + (t&3)*2;
      sStage[(n  )*132 + m  ] = acc[mi][nj][0];
      sStage[(n+1)*132 + m  ] = acc[mi][nj][1];
      sStage[(n  )*132 + m+8] = acc[mi][nj][2];
      sStage[(n+1)*132 + m+8] = acc[mi][nj][3];
    }
  __syncthreads();

  const int tx = tid&31, ty = tid>>5;
  #pragma unroll
  for (int r=0;r<12;r++){
    int o = ty*12 + r;
    float4 v = *(float4*)(sStage + o*132 + tx*4);
    float bv = bias[wrow0+o];
    v.x+=bv; v.y+=bv; v.z+=bv; v.w+=bv;
    size_t off = (size_t)o*HW + px0 + tx*4;
    if (EPI==0){
      *(float4*)((float*)outv + off) = v;
    } else if (EPI==1){
      v.x=fmaxf(v.x,0.f); v.y=fmaxf(v.y,0.f); v.z=fmaxf(v.z,0.f); v.w=fmaxf(v.w,0.f);
      uint2 u; u.x = bf2u(v.x,v.y); u.y = bf2u(v.z,v.w);
      *(uint2*)((__nv_bfloat16*)outv + off) = u;
    } else if (EPI==2){
      float4 q = *(const float4*)(xinb + off);
      v.x+=q.x; v.y+=q.y; v.z+=q.z; v.w+=q.w;
      *(float4*)((float*)outv + off) = v;
    } else if (EPI==3){
      float rs = g_rescale[bIdx][o], rb = g_rebias[bIdx][o];
      float4 xi = *(const float4*)(xinb + off);
      v = make_float4(xi.x + v.x*rs + rb, xi.y + v.y*rs + rb,
                      xi.z + v.z*rs + rb, xi.w + v.w*rs + rb);
      *(float4*)((float*)outv + off) = v;
    } else {
      uint2 u; u.x = bf2u(v.x,v.y); u.y = bf2u(v.z,v.w);
      *(uint2*)((__nv_bfloat16*)outv + off) = u;
    }
  }
}

__global__ void __launch_bounds__(256) k_mma_qkv(
    const float* __restrict__ qW, const float* __restrict__ qb,
    const float* __restrict__ kvW, const float* __restrict__ kvb)
{
  int b = blockIdx.z, gy = blockIdx.y;
  const __nv_bfloat16* actb = g_y + (size_t)b*CB*HW;
  __nv_bfloat16* outb = g_qkv + ((size_t)b*3*CB + gy*96)*HW;
  if (gy==0) mma_body<1,4>(actb, qW, qb, 96, 0, outb, nullptr, b);
  else       mma_body<1,4>(actb, kvW, kvb, 96, (gy-1)*96, outb, nullptr, b);
}

__global__ void __launch_bounds__(256) k_mma_proj(
    const float* __restrict__ W, const float* __restrict__ bias,
    const float* __restrict__ xin)
{
  int b = blockIdx.z;
  const __nv_bfloat16* actb = g_attn + (size_t)b*HW*96;
  mma_body<2,3>(actb, W, bias, 96, 0, g_x2 + (size_t)b*CB*HW,
                xin + (size_t)b*CB*HW, b);
}

__global__ void __launch_bounds__(256) k_mma_m1(
    const float* __restrict__ W, const float* __restrict__ bias)
{
  int b = blockIdx.z, gy = blockIdx.y;
  mma_body<0,1>(g_x2 + (size_t)b*CB*HW, W, bias, 96, gy*96,
                g_hid + ((size_t)b*4*CB + gy*96)*HW, nullptr, b);
}

__global__ void __launch_bounds__(256) k_mma_m2(
    const float* __restrict__ W, const float* __restrict__ bias,
    float* __restrict__ out)
{
  int b = blockIdx.z;
  mma_body<1,2>(g_hid + (size_t)b*4*CB*HW, W, bias, 384, 0,
                out + (size_t)b*CB*HW, g_x2 + (size_t)b*CB*HW, b);
}

// ---------------- attention: one (window, head) per 64-thread block ----------------
// K/V staged via vectorized uint4 loads (window rows are 8 contiguous pixels).
__global__ void __launch_bounds__(64) k_attn(const float* __restrict__ lsp){
  __shared__ __align__(16) float sK[32][68];   // pitch 68: rows 16B-aligned, 2-way store conflicts
  __shared__ __align__(16) float sVt[64][36];
  int widx=blockIdx.x, h=blockIdx.y;
  int b=widx>>10, rem=widx&1023;
  int r0=(rem>>5)*8, c0=(rem&31)*8;
  int t=threadIdx.x;
  float ls = __expf(fminf(lsp[0], LOGIT_MAXV));
  size_t baseK = ((size_t)b*3*CB +   CB + h*32)*HW;
  size_t baseV = ((size_t)b*3*CB + 2*CB + h*32)*HW;
  // 256 uint4 segments per matrix: j -> (d = j>>3, seg = j&7), seg = window row
  #pragma unroll
  for (int j=t; j<256; j+=64){
    int d=j>>3, seg=j&7;
    size_t rowoff = (size_t)d*HW + (size_t)(r0+seg)*256 + c0;
    uint4 kv = *(const uint4*)(g_qkv + baseK + rowoff);
    const __nv_bfloat16* kp = (const __nv_bfloat16*)&kv;
    float kf[8];
    #pragma unroll
    for (int e=0;e<8;e++) kf[e] = __bfloat162float(kp[e])*SCALEV;
    *(float4*)&sK[d][seg*8  ] = make_float4(kf[0],kf[1],kf[2],kf[3]);
    *(float4*)&sK[d][seg*8+4] = make_float4(kf[4],kf[5],kf[6],kf[7]);
    uint4 vv = *(const uint4*)(g_qkv + baseV + rowoff);
    const __nv_bfloat16* vp = (const __nv_bfloat16*)&vv;
    #pragma unroll
    for (int e=0;e<8;e++){
      int r = (e+seg)&7;   // rotation -> conflict-free scalar stores
      sVt[seg*8 + r][d] = __bfloat162float(vp[r]);
    }
  }
  int hw_t = (r0+(t>>3))*256 + c0 + (t&7);
  size_t baseQ = ((size_t)b*CB + h*32)*HW;
  unsigned long long q2[32];
  #pragma unroll
  for (int d=0;d<32;d++)
    q2[d] = pack2(__bfloat162float(g_co[baseQ + (size_t)d*HW + hw_t]));
  __syncthreads();
  float l[64];
  const float* brow = &g_bias_tab[h][t][0];
  #pragma unroll
  for (int m0=0;m0<64;m0+=4){
    unsigned long long s01=0ull, s23=0ull;
    #pragma unroll
    for (int d=0;d<32;d++){
      ulonglong2 kk = *(const ulonglong2*)&sK[d][m0];
      ffma2(s01, q2[d], kk.x);
      ffma2(s23, q2[d], kk.y);
    }
    float2 pa=u2f(s01), pb=u2f(s23);
    float4 bi = *(const float4*)(brow + m0);
    l[m0  ]=pa.x*ls+bi.x; l[m0+1]=pa.y*ls+bi.y;
    l[m0+2]=pb.x*ls+bi.z; l[m0+3]=pb.y*ls+bi.w;
  }
  float mx=l[0];
  #pragma unroll
  for (int m=1;m<64;m++) mx = fmaxf(mx,l[m]);
  float sum=0.f;
  #pragma unroll
  for (int m=0;m<64;m++){ float e=__expf(l[m]-mx); l[m]=e; sum+=e; }
  float inv = 1.f/sum;
  unsigned long long o2[16];
  #pragma unroll
  for (int i=0;i<16;i++) o2[i]=0ull;
  #pragma unroll
  for (int m=0;m<64;m++){
    unsigned long long p2 = pack2(l[m]);
    const ulonglong2* vp = (const ulonglong2*)&sVt[m][0];
    #pragma unroll
    for (int dd=0;dd<8;dd++){
      ulonglong2 vv = vp[dd];
      ffma2(o2[2*dd  ], p2, vv.x);
      ffma2(o2[2*dd+1], p2, vv.y);
    }
  }
  __nv_bfloat16* dst = g_attn + ((size_t)b*HW + hw_t)*96 + h*32;
  #pragma unroll
  for (int k=0;k<8;k++){
    float2 pa=u2f(o2[2*k]), pb=u2f(o2[2*k+1]);
    uint2 u; u.x = bf2u(pa.x*inv, pa.y*inv); u.y = bf2u(pb.x*inv, pb.y*inv);
    *(uint2*)(dst + 4*k) = u;
  }
}

// ---------------- host launch ----------------
extern "C" void kernel_launch(void* const* d_in, const int* in_sizes, int n_in,
                              void* d_out, int out_size){
  const float* x       = (const float*)d_in[0];
  const float* agn_w   = (const float*)d_in[1];
  const float* agn_b   = (const float*)d_in[2];
  const float* meta1_w = (const float*)d_in[3];
  const float* meta1_b = (const float*)d_in[4];
  const float* meta2_w = (const float*)d_in[5];
  const float* meta2_b = (const float*)d_in[6];
  const float* la1_w   = (const float*)d_in[7];
  const float* la1_b   = (const float*)d_in[8];
  const float* la2_w   = (const float*)d_in[9];
  const float* la2_b   = (const float*)d_in[10];
  const float* ta1_w   = (const float*)d_in[11];
  const float* ta1_b   = (const float*)d_in[12];
  const float* ta2_w   = (const float*)d_in[13];
  const float* ta2_b   = (const float*)d_in[14];
  const float* q_w     = (const float*)d_in[15];
  const float* q_b     = (const float*)d_in[16];
  const float* kv_w    = (const float*)d_in[17];
  const float* kv_b    = (const float*)d_in[18];
  const float* dw_w    = (const float*)d_in[19];
  const float* dw_b    = (const float*)d_in[20];
  const float* proj_w  = (const float*)d_in[21];
  const float* proj_b  = (const float*)d_in[22];
  const float* logit_s = (const float*)d_in[23];
  const float* rp_w1   = (const float*)d_in[24];
  const float* rp_b1   = (const float*)d_in[25];
  const float* rp_w2   = (const float*)d_in[26];
  const float* rp_b2   = (const float*)d_in[27];
  const float* m1_w    = (const float*)d_in[28];
  const float* m1_b    = (const float*)d_in[29];
  const float* m2_w    = (const float*)d_in[30];
  const float* m2_b    = (const float*)d_in[31];
  float* out = (float*)d_out;

  cudaFuncSetAttribute(k_mma_qkv, cudaFuncAttributeMaxDynamicSharedMemorySize, SMEM_MMA);
  cudaFuncSetAttribute(k_mma_proj,cudaFuncAttributeMaxDynamicSharedMemorySize, SMEM_MMA);
  cudaFuncSetAttribute(k_mma_m1,  cudaFuncAttributeMaxDynamicSharedMemorySize, SMEM_MMA);
  cudaFuncSetAttribute(k_mma_m2,  cudaFuncAttributeMaxDynamicSharedMemorySize, SMEM_MMA);

  // 1. stats + bias table
  k_reduce_partial<<<dim3(192,BATCH), 256>>>(x);
  k_finalize<<<BATCH, 256>>>(meta1_w, meta1_b, meta2_w, meta2_b);
  k_bias<<<64, 64>>>(rp_w1, rp_b1, rp_w2, rp_b2);

  // 2. fused AGN (writes bf16 g_y)
  dim3 agrid(IMG/128, IMG/8, BATCH*CB);
  k_agn_fused<<<agrid, 256>>>(x, agn_w, agn_b, la1_w, la1_b, la2_w, la2_b,
                              ta1_w, ta1_b, ta2_w, ta2_b);

  // 3. QKV projections (R6 form: independent y-blocks, one launch)
  k_mma_qkv<<<dim3(512,3,BATCH), 256, SMEM_MMA>>>(q_w, q_b, kv_w, kv_b);

  // 4. reflect 5x5 dwconv on Q, then window attention
  dim3 cgrid(IMG/32, IMG/8, BATCH*CB), cblk(32, 8);
  k_co5<<<cgrid, cblk>>>(dw_w, dw_b);
  k_attn<<<dim3(4096,3), 64>>>(logit_s);

  // 5. proj + residual/rescale/rebias -> g_x2 (fp32)
  k_mma_proj<<<dim3(512,1,BATCH), 256, SMEM_MMA>>>(proj_w, proj_b, x);

  // 6. MLP (R6 form)
  k_mma_m1<<<dim3(512,4,BATCH), 256, SMEM_MMA>>>(m1_w, m1_b);
  k_mma_m2<<<dim3(512,1,BATCH), 256, SMEM_MMA>>>(m2_w, m2_b, out);
}

// round 15
// speedup vs baseline: 1.1018x; 1.0320x over previous
#include <cuda_runtime.h>
#include <cuda_bf16.h>
#include <math.h>

#define HW 65536
#define IMG 256
#define CB 96
#define BATCH 4

// ---------------- device scratch ----------------
__device__ float g_mean[BATCH], g_istd[BATCH];
__device__ float g_rescale[BATCH][CB], g_rebias[BATCH][CB];
__device__ float g_partial[BATCH][192][2];
__device__ float g_bias_tab[3][64][64];

__device__ __nv_bfloat16 g_y  [(size_t)BATCH*CB*HW];
__device__ __nv_bfloat16 g_qkv[(size_t)BATCH*3*CB*HW];
__device__ __nv_bfloat16 g_co [(size_t)BATCH*CB*HW];
__device__ __nv_bfloat16 g_attn[(size_t)BATCH*HW*CB];
__device__ float         g_x2 [(size_t)BATCH*CB*HW];
__device__ __nv_bfloat16 g_hid[(size_t)BATCH*4*CB*HW];

#define SCALEV 0.17677669529663687f
#define LOGIT_MAXV 4.605170185988091f

// ---------------- f32x2 helpers ----------------
__device__ __forceinline__ unsigned long long pack2(float w){
  unsigned long long r; asm("mov.b64 %0, {%1, %1};" : "=l"(r) : "f"(w)); return r;
}
__device__ __forceinline__ float2 u2f(unsigned long long v){
  float2 f; asm("mov.b64 {%0, %1}, %2;" : "=f"(f.x), "=f"(f.y) : "l"(v)); return f;
}
__device__ __forceinline__ void ffma2(unsigned long long &d, unsigned long long a, unsigned long long b){
  asm("fma.rn.f32x2 %0, %1, %2, %0;" : "+l"(d) : "l"(a), "l"(b));
}

// ---------------- mma helpers ----------------
__device__ __forceinline__ void ldsm_x4(unsigned addr, unsigned &r0, unsigned &r1, unsigned &r2, unsigned &r3){
  asm volatile("ldmatrix.sync.aligned.m8n8.x4.shared.b16 {%0,%1,%2,%3}, [%4];"
    : "=r"(r0),"=r"(r1),"=r"(r2),"=r"(r3) : "r"(addr));
}
__device__ __forceinline__ void ldsm_x4_t(unsigned addr, unsigned &r0, unsigned &r1, unsigned &r2, unsigned &r3){
  asm volatile("ldmatrix.sync.aligned.m8n8.x4.trans.shared.b16 {%0,%1,%2,%3}, [%4];"
    : "=r"(r0),"=r"(r1),"=r"(r2),"=r"(r3) : "r"(addr));
}
__device__ __forceinline__ void mma16816(float* c, const unsigned* a, const unsigned* b){
  asm volatile("mma.sync.aligned.m16n8k16.row.col.f32.bf16.bf16.f32 "
    "{%0,%1,%2,%3},{%4,%5,%6,%7},{%8,%9},{%0,%1,%2,%3};"
    : "+f"(c[0]),"+f"(c[1]),"+f"(c[2]),"+f"(c[3])
    : "r"(a[0]),"r"(a[1]),"r"(a[2]),"r"(a[3]),"r"(b[0]),"r"(b[1]));
}
__device__ __forceinline__ unsigned bf2u(float x, float y){
  __nv_bfloat162 t = __floats2bfloat162_rn(x, y);
  return reinterpret_cast<unsigned&>(t);
}

// ---------------- K1: per-sample partial sums ----------------
__global__ void k_reduce_partial(const float* __restrict__ x){
  int b = blockIdx.y, blk = blockIdx.x, tid = threadIdx.x;
  const float4* xb = (const float4*)(x + (size_t)b*CB*HW);
  size_t base = (size_t)blk*8192;
  float s=0.f, s2=0.f;
  for (int i=tid;i<8192;i+=256){
    float4 v = xb[base+i];
    s  += v.x+v.y+v.z+v.w;
    s2 += v.x*v.x+v.y*v.y+v.z*v.z+v.w*v.w;
  }
  __shared__ float rs[256], rq[256];
  rs[tid]=s; rq[tid]=s2; __syncthreads();
  for (int st=128;st>0;st>>=1){
    if (tid<st){ rs[tid]+=rs[tid+st]; rq[tid]+=rq[tid+st]; }
    __syncthreads();
  }
  if (tid==0){ g_partial[b][blk][0]=rs[0]; g_partial[b][blk][1]=rq[0]; }
}

// ---------------- K2: finalize ----------------
__global__ void k_finalize(const float* __restrict__ m1w, const float* __restrict__ m1b,
                           const float* __restrict__ m2w, const float* __restrict__ m2b){
  int b = blockIdx.x, tid = threadIdx.x;
  __shared__ float rs[256], rq[256];
  rs[tid] = (tid<192)? g_partial[b][tid][0] : 0.f;
  rq[tid] = (tid<192)? g_partial[b][tid][1] : 0.f;
  __syncthreads();
  for (int st=128;st>0;st>>=1){
    if (tid<st){ rs[tid]+=rs[tid+st]; rq[tid]+=rq[tid+st]; }
    __syncthreads();
  }
  __shared__ float sh_mean, sh_std;
  if (tid==0){
    float M = (float)((size_t)CB*HW);
    float mean = rs[0]/M;
    float var  = rq[0]/M - mean*mean;
    float sd   = sqrtf(var + 1e-5f);
    g_mean[b]=mean; g_istd[b]=1.f/sd;
    sh_mean=mean; sh_std=sd;
  }
  __syncthreads();
  if (tid<CB){
    g_rescale[b][tid] = sh_std *m1w[tid] + m1b[tid];
    g_rebias [b][tid] = sh_mean*m2w[tid] + m2b[tid];
  }
}

// ---------------- K3: relative-position bias table ----------------
__global__ void k_bias(const float* __restrict__ w1, const float* __restrict__ b1,
                       const float* __restrict__ w2, const float* __restrict__ b2){
  int n = blockIdx.x, m = threadIdx.x;
  float di = (float)((n>>3) - (m>>3));
  float dj = (float)((n&7) - (m&7));
  float a0l = log1pf(fabsf(di)); float r0 = di<0.f ? -a0l : (di>0.f ? a0l : 0.f);
  float a1l = log1pf(fabsf(dj)); float r1 = dj<0.f ? -a1l : (dj>0.f ? a1l : 0.f);
  float a0=0.f,a1=0.f,a2=0.f;
  for (int k=0;k<256;k++){
    float h = fmaxf(r0*w1[2*k]+r1*w1[2*k+1]+b1[k], 0.f);
    a0 += h*w2[k]; a1 += h*w2[256+k]; a2 += h*w2[512+k];
  }
  g_bias_tab[0][n][m]=a0+b2[0];
  g_bias_tab[1][n][m]=a1+b2[1];
  g_bias_tab[2][n][m]=a2+b2[2];
}

// ---------------- K4: fused AGN (vectorized loader) ----------------
__global__ void __launch_bounds__(256) k_agn_fused(const float* __restrict__ x,
    const float* __restrict__ agnw, const float* __restrict__ agnb,
    const float* __restrict__ la1w, const float* __restrict__ la1b,
    const float* __restrict__ la2w, const float* __restrict__ la2b,
    const float* __restrict__ ta1w, const float* __restrict__ ta1b,
    const float* __restrict__ ta2w, const float* __restrict__ ta2b){
  __shared__ float xt[12*136];
  __shared__ __align__(8) float2 tb[10*136];
  int bc = blockIdx.z; int b = bc/CB, c = bc - b*CB;
  const float* xb = x + (size_t)bc*HW;
  float mean = g_mean[b], istd = g_istd[b];
  int x0 = blockIdx.x*128, y0 = blockIdx.y*8;
  int tid = threadIdx.x;

  // ---- main load: 12 rows x 32 float4 (cc in [2,130), gx always in-image) ----
  #pragma unroll
  for (int it=0; it<2; it++){
    int i = tid + 256*it;
    if (i < 384){
      int ry = i>>5, m = i&31;
      int gy = y0+ry-2;
      float4 v = make_float4(0.f,0.f,0.f,0.f);
      if ((unsigned)gy<256u) v = *(const float4*)(xb + gy*256 + x0 + 4*m);
      float* row = xt + ry*136;
      row[ 68 + m    ] = (v.x-mean)*istd;   // cc=4m+2 -> plane2, idx m
      row[102 + m    ] = (v.y-mean)*istd;   // cc=4m+3 -> plane3, idx m
      row[      m + 1] = (v.z-mean)*istd;   // cc=4m+4 -> plane0, idx m+1
      row[ 34 + m + 1] = (v.w-mean)*istd;   // cc=4m+5 -> plane1, idx m+1
    }
  }
  // ---- edge load: 12 rows x 8 scalars (cc in {0,1,130..135}) ----
  if (tid < 96){
    int ry = tid>>3, e = tid&7;
    int cc = (e<2) ? e : (128+e);
    int gy = y0+ry-2, gx = x0+cc-2;
    float v = 0.f;
    if ((unsigned)gy<256u && (unsigned)gx<256u) v = (xb[gy*256+gx]-mean)*istd;
    xt[ry*136 + ((cc&3)*34 + (cc>>2))] = v;
  }
  float w1l[9], w1t[9];
  #pragma unroll
  for (int k=0;k<9;k++){ w1l[k]=la1w[c*9+k]; w1t[k]=ta1w[c*9+k]; }
  float b1l=la1b[c], b1t=ta1b[c];
  __syncthreads();

  for (int run=tid; run<330; run+=256){
    int r = run/33, rn = run - r*33;
    float al[4], at[4];
    #pragma unroll
    for (int o=0;o<4;o++){ al[o]=b1l; at[o]=b1t; }
    #pragma unroll
    for (int dy=0;dy<3;dy++){
      const float* xr = xt + (r+dy)*136;
      float v[6];
      v[0]=xr[rn]; v[1]=xr[34+rn]; v[2]=xr[68+rn]; v[3]=xr[102+rn];
      v[4]=xr[rn+1]; v[5]=xr[34+rn+1];
      #pragma unroll
      for (int o=0;o<4;o++){
        al[o] += v[o]*w1l[dy*3] + v[o+1]*w1l[dy*3+1] + v[o+2]*w1l[dy*3+2];
        at[o] += v[o]*w1t[dy*3] + v[o+1]*w1t[dy*3+1] + v[o+2]*w1t[dy*3+2];
      }
    }
    float2* tr = tb + r*136;
    #pragma unroll
    for (int o=0;o<4;o++)
      tr[o*34+rn] = make_float2(fmaxf(al[o],0.f), fmaxf(at[o],0.f));
  }
  __syncthreads();

  float w2l[9], w2t[9];
  #pragma unroll
  for (int k=0;k<9;k++){ w2l[k]=la2w[c*9+k]; w2t[k]=ta2w[c*9+k]; }
  int tx = tid&31, ty = tid>>5;
  float acc[4];
  float base2 = la2b[c] + ta2b[c];
  #pragma unroll
  for (int o=0;o<4;o++) acc[o]=base2;
  #pragma unroll
  for (int dy=0;dy<3;dy++){
    const float2* tr = tb + (ty+dy)*136;
    float2 t0=tr[tx], t1=tr[34+tx], t2=tr[68+tx], t3=tr[102+tx];
    float2 t4=tr[tx+1], t5=tr[34+tx+1];
    float2 tv[6] = {t0,t1,t2,t3,t4,t5};
    #pragma unroll
    for (int o=0;o<4;o++){
      #pragma unroll
      for (int dx=0;dx<3;dx++){
        float2 v = tv[o+dx];
        acc[o] += v.x*w2l[dy*3+dx] + v.y*w2t[dy*3+dx];
      }
    }
  }
  float sc = agnw[c]*g_rescale[b][c];
  float sb = agnb[c]+g_rebias[b][c];
  const float* xnr = xt + (ty+2)*136;
  float xn0 = xnr[68+tx], xn1 = xnr[102+tx], xn2 = xnr[tx+1], xn3 = xnr[34+tx+1];
  float r0 = xn0*sc + sb + acc[0];
  float r1 = xn1*sc + sb + acc[1];
  float r2 = xn2*sc + sb + acc[2];
  float r3 = xn3*sc + sb + acc[3];
  uint2 u; u.x = bf2u(r0,r1); u.y = bf2u(r2,r3);
  *(uint2*)(g_y + (size_t)bc*HW + (size_t)(y0+ty)*256 + x0 + 4*tx) = u;
}

// ---------------- K6: 5x5 reflect dwconv on Q (vectorized interior) ----------------
__global__ void k_co5(const float* __restrict__ dww, const float* __restrict__ dwb){
  int bc=blockIdx.z; int b=bc/CB, c=bc-b*CB;
  const __nv_bfloat16* Q = g_qkv + ((size_t)b*3*CB + c)*HW;
  __shared__ float tile[12][36];
  int x0=blockIdx.x*32, y0=blockIdx.y*8;
  int tid=threadIdx.y*32+threadIdx.x;
  if (x0>=32 && x0<=192){
    // interior in x: gx in [x0-4, x0+36) always valid; only gy reflects.
    if (tid < 120){
      int ry = tid/10, m = tid - ry*10;
      int gy = y0+ry-2;
      gy = gy<0 ? -gy : (gy>255 ? 510-gy : gy);
      uint2 q = *(const uint2*)(Q + gy*256 + (x0-4) + 4*m);
      const __nv_bfloat16* qp = (const __nv_bfloat16*)&q;
      int cc = 4*m - 2;
      #pragma unroll
      for (int e=0;e<4;e++){
        int ce = cc+e;
        if ((unsigned)ce < 36u) tile[ry][ce] = __bfloat162float(qp[e]);
      }
    }
  } else {
    for (int i=tid;i<432;i+=256){
      int ry=i/36, rx=i-ry*36;
      int gy=y0+ry-2, gx=x0+rx-2;
      gy = gy<0 ? -gy : (gy>255 ? 510-gy : gy);
      gx = gx<0 ? -gx : (gx>255 ? 510-gx : gx);
      tile[ry][rx] = __bfloat162float(Q[gy*256+gx]);
    }
  }
  __syncthreads();
  float w[25];
  #pragma unroll
  for (int k=0;k<25;k++) w[k]=dww[c*25+k];
  float acc = dwb[c];
  #pragma unroll
  for (int ky=0;ky<5;ky++)
    #pragma unroll
    for (int kx=0;kx<5;kx++)
      acc += tile[threadIdx.y+ky][threadIdx.x+kx]*w[ky*5+kx];
  g_co[(size_t)bc*HW + (size_t)(y0+threadIdx.y)*256 + x0+threadIdx.x] = __float2bfloat16(acc);
}

// =====================================================================
// Tensor-core GEMM (R14: B operand via ldsm_x4, 3 per k-step)
// =====================================================================
#define SMEM_MMA 50688

template<int LOAD, int EPI>
__device__ __forceinline__ void mma_body(
    const void* actb, const float* W, const float* bias,
    int CinTot, int wrow0, void* outv,
    const float* xinb, int bIdx)
{
  extern __shared__ char smem_raw[];
  __nv_bfloat16* sA = (__nv_bfloat16*)smem_raw;
  __nv_bfloat16* sW = (__nv_bfloat16*)(smem_raw + (LOAD==2 ? 26624 : 24576));
  float* sStage = (float*)smem_raw;
  const int tid = threadIdx.x;
  const int px0 = blockIdx.x * 128;
  const int warp = tid >> 5, t = tid & 31;
  const int m0w = (warp>>1)*32, n0w = (warp&1)*48;
  unsigned sAb = (unsigned)__cvta_generic_to_shared(sA);
  unsigned sWb = (unsigned)__cvta_generic_to_shared(sW);

  float acc[2][6][4];
  #pragma unroll
  for (int mi=0;mi<2;mi++)
    #pragma unroll
    for (int nj=0;nj<6;nj++)
      #pragma unroll
      for (int e=0;e<4;e++) acc[mi][nj][e]=0.f;

  const int g = t>>3, gi = t&7;

  for (int k0g=0; k0g<CinTot; k0g+=96){
    if (LOAD==0){
      const float* a = (const float*)actb;
      #pragma unroll
      for (int j=0;j<12;j++){
        int i = tid + 256*j;
        int c = i>>5, px = (i&31)*4;
        float4 v = *(const float4*)(a + (size_t)(k0g+c)*HW + px0 + px);
        uint2 u; u.x = bf2u(v.x,v.y); u.y = bf2u(v.z,v.w);
        *(uint2*)(sA + c*128 + ((((px>>3)^(c&7))<<3) + (px&7))) = u;
      }
    } else if (LOAD==1){
      const __nv_bfloat16* a = (const __nv_bfloat16*)actb;
      #pragma unroll
      for (int j=0;j<6;j++){
        int i = tid + 256*j;
        int c = i>>4, s8 = (i&15)*8;
        uint4 v = *(const uint4*)(a + (size_t)(k0g+c)*HW + px0 + s8);
        *(uint4*)(sA + c*128 + ((((s8>>3)^(c&7))<<3))) = v;
      }
    } else {
      const __nv_bfloat16* a = (const __nv_bfloat16*)actb + (size_t)px0*96;
      #pragma unroll
      for (int j=0;j<6;j++){
        int i = tid + 256*j;
        int px = i/12, c0 = (i%12)*8;
        uint4 v = *(const uint4*)(a + (size_t)px*96 + c0);
        *(uint4*)(sA + px*104 + c0) = v;
      }
    }
    #pragma unroll
    for (int j=0;j<9;j++){
      int i = tid + 256*j;
      int r = i/24, c4 = (i%24)*4;
      float4 v = *(const float4*)(W + (size_t)(wrow0+r)*CinTot + k0g + c4);
      uint2 u; u.x = bf2u(v.x,v.y); u.y = bf2u(v.z,v.w);
      *(uint2*)(sW + r*104 + c4) = u;
    }
    __syncthreads();

    unsigned addrA[2], addrB[3];
    if (LOAD==2){
      int row0 = m0w + (g&1)*8 + gi;
      int kc = (g>=2)?16:0;
      addrA[0] = sAb + (row0     )*208 + kc;
      addrA[1] = sAb + (row0 + 16)*208 + kc;
    } else {
      int kb = ((g>=2)?8:0) + gi;
      int px_a0 = m0w + (g&1)*8;
      int px_a1 = px_a0 + 16;
      addrA[0] = sAb + kb*256 + ((((px_a0>>3) ^ gi)<<4));
      addrA[1] = sAb + kb*256 + ((((px_a1>>3) ^ gi)<<4));
    }
    {
      int nb = n0w + (t&7) + ((t>>4)<<3);
      int kcb = ((t>>3)&1)*8;
      #pragma unroll
      for (int p=0;p<3;p++) addrB[p] = sWb + (nb + p*16)*208 + kcb*2;
    }

    #pragma unroll
    for (int ks=0; ks<6; ks++){
      unsigned a[2][4], br[3][4];
      if (LOAD==2){ ldsm_x4(addrA[0], a[0][0],a[0][1],a[0][2],a[0][3]);
                    ldsm_x4(addrA[1], a[1][0],a[1][1],a[1][2],a[1][3]); }
      else        { ldsm_x4_t(addrA[0], a[0][0],a[0][1],a[0][2],a[0][3]);
                    ldsm_x4_t(addrA[1], a[1][0],a[1][1],a[1][2],a[1][3]); }
      #pragma unroll
      for (int p=0;p<3;p++) ldsm_x4(addrB[p], br[p][0],br[p][1],br[p][2],br[p][3]);
      #pragma unroll
      for (int mi=0;mi<2;mi++)
        #pragma unroll
        for (int nj=0;nj<6;nj++)
          mma16816(acc[mi][nj], a[mi], &br[nj>>1][(nj&1)*2]);
      if (LOAD==2){ addrA[0]+=32; addrA[1]+=32; }
      else        { addrA[0]+=4096; addrA[1]+=4096; }
      #pragma unroll
      for (int p=0;p<3;p++) addrB[p]+=32;
    }
    __syncthreads();
  }

  #pragma unroll
  for (int mi=0;mi<2;mi++)
    #pragma unroll
    for (int nj=0;nj<6;nj++){
      int m = m0w + mi*16 + (t>>2);
      int n = n0w + nj*8 + (t&3)*2;
      sStage[(n  )*132 + m  ] = acc[mi][nj][0];
      sStage[(n+1)*132 + m  ] = acc[mi][nj][1];
      sStage[(n  )*132 + m+8] = acc[mi][nj][2];
      sStage[(n+1)*132 + m+8] = acc[mi][nj][3];
    }
  __syncthreads();

  const int tx = tid&31, ty = tid>>5;
  #pragma unroll
  for (int r=0;r<12;r++){
    int o = ty*12 + r;
    float4 v = *(float4*)(sStage + o*132 + tx*4);
    float bv = bias[wrow0+o];
    v.x+=bv; v.y+=bv; v.z+=bv; v.w+=bv;
    size_t off = (size_t)o*HW + px0 + tx*4;
    if (EPI==0){
      *(float4*)((float*)outv + off) = v;
    } else if (EPI==1){
      v.x=fmaxf(v.x,0.f); v.y=fmaxf(v.y,0.f); v.z=fmaxf(v.z,0.f); v.w=fmaxf(v.w,0.f);
      uint2 u; u.x = bf2u(v.x,v.y); u.y = bf2u(v.z,v.w);
      *(uint2*)((__nv_bfloat16*)outv + off) = u;
    } else if (EPI==2){
      float4 q = *(const float4*)(xinb + off);
      v.x+=q.x; v.y+=q.y; v.z+=q.z; v.w+=q.w;
      *(float4*)((float*)outv + off) = v;
    } else if (EPI==3){
      float rs = g_rescale[bIdx][o], rb = g_rebias[bIdx][o];
      float4 xi = *(const float4*)(xinb + off);
      v = make_float4(xi.x + v.x*rs + rb, xi.y + v.y*rs + rb,
                      xi.z + v.z*rs + rb, xi.w + v.w*rs + rb);
      *(float4*)((float*)outv + off) = v;
    } else {
      uint2 u; u.x = bf2u(v.x,v.y); u.y = bf2u(v.z,v.w);
      *(uint2*)((__nv_bfloat16*)outv + off) = u;
    }
  }
}

__global__ void __launch_bounds__(256) k_mma_qkv(
    const float* __restrict__ qW, const float* __restrict__ qb,
    const float* __restrict__ kvW, const float* __restrict__ kvb)
{
  int b = blockIdx.z, gy = blockIdx.y;
  const __nv_bfloat16* actb = g_y + (size_t)b*CB*HW;
  __nv_bfloat16* outb = g_qkv + ((size_t)b*3*CB + gy*96)*HW;
  if (gy==0) mma_body<1,4>(actb, qW, qb, 96, 0, outb, nullptr, b);
  else       mma_body<1,4>(actb, kvW, kvb, 96, (gy-1)*96, outb, nullptr, b);
}

__global__ void __launch_bounds__(256) k_mma_proj(
    const float* __restrict__ W, const float* __restrict__ bias,
    const float* __restrict__ xin)
{
  int b = blockIdx.z;
  const __nv_bfloat16* actb = g_attn + (size_t)b*HW*96;
  mma_body<2,3>(actb, W, bias, 96, 0, g_x2 + (size_t)b*CB*HW,
                xin + (size_t)b*CB*HW, b);
}

__global__ void __launch_bounds__(256) k_mma_m1(
    const float* __restrict__ W, const float* __restrict__ bias)
{
  int b = blockIdx.z, gy = blockIdx.y;
  mma_body<0,1>(g_x2 + (size_t)b*CB*HW, W, bias, 96, gy*96,
                g_hid + ((size_t)b*4*CB + gy*96)*HW, nullptr, b);
}

__global__ void __launch_bounds__(256) k_mma_m2(
    const float* __restrict__ W, const float* __restrict__ bias,
    float* __restrict__ out)
{
  int b = blockIdx.z;
  mma_body<1,2>(g_hid + (size_t)b*4*CB*HW, W, bias, 384, 0,
                out + (size_t)b*CB*HW, g_x2 + (size_t)b*CB*HW, b);
}

// ---------------- attention: one (window, head) per 64-thread block ----------------
__global__ void __launch_bounds__(64) k_attn(const float* __restrict__ lsp){
  __shared__ __align__(16) float sK[32][68];
  __shared__ __align__(16) float sVt[64][36];
  int widx=blockIdx.x, h=blockIdx.y;
  int b=widx>>10, rem=widx&1023;
  int r0=(rem>>5)*8, c0=(rem&31)*8;
  int t=threadIdx.x;
  float ls = __expf(fminf(lsp[0], LOGIT_MAXV));
  size_t baseK = ((size_t)b*3*CB +   CB + h*32)*HW;
  size_t baseV = ((size_t)b*3*CB + 2*CB + h*32)*HW;
  #pragma unroll
  for (int j=t; j<256; j+=64){
    int d=j>>3, seg=j&7;
    size_t rowoff = (size_t)d*HW + (size_t)(r0+seg)*256 + c0;
    uint4 kv = *(const uint4*)(g_qkv + baseK + rowoff);
    const __nv_bfloat16* kp = (const __nv_bfloat16*)&kv;
    float kf[8];
    #pragma unroll
    for (int e=0;e<8;e++) kf[e] = __bfloat162float(kp[e])*SCALEV;
    *(float4*)&sK[d][seg*8  ] = make_float4(kf[0],kf[1],kf[2],kf[3]);
    *(float4*)&sK[d][seg*8+4] = make_float4(kf[4],kf[5],kf[6],kf[7]);
    uint4 vv = *(const uint4*)(g_qkv + baseV + rowoff);
    const __nv_bfloat16* vp = (const __nv_bfloat16*)&vv;
    #pragma unroll
    for (int e=0;e<8;e++){
      int r = (e+seg)&7;
      sVt[seg*8 + r][d] = __bfloat162float(vp[r]);
    }
  }
  int hw_t = (r0+(t>>3))*256 + c0 + (t&7);
  size_t baseQ = ((size_t)b*CB + h*32)*HW;
  unsigned long long q2[32];
  #pragma unroll
  for (int d=0;d<32;d++)
    q2[d] = pack2(__bfloat162float(g_co[baseQ + (size_t)d*HW + hw_t]));
  __syncthreads();
  float l[64];
  const float* brow = &g_bias_tab[h][t][0];
  #pragma unroll
  for (int m0=0;m0<64;m0+=4){
    unsigned long long s01=0ull, s23=0ull;
    #pragma unroll
    for (int d=0;d<32;d++){
      ulonglong2 kk = *(const ulonglong2*)&sK[d][m0];
      ffma2(s01, q2[d], kk.x);
      ffma2(s23, q2[d], kk.y);
    }
    float2 pa=u2f(s01), pb=u2f(s23);
    float4 bi = *(const float4*)(brow + m0);
    l[m0  ]=pa.x*ls+bi.x; l[m0+1]=pa.y*ls+bi.y;
    l[m0+2]=pb.x*ls+bi.z; l[m0+3]=pb.y*ls+bi.w;
  }
  float mx=l[0];
  #pragma unroll
  for (int m=1;m<64;m++) mx = fmaxf(mx,l[m]);
  float sum=0.f;
  #pragma unroll
  for (int m=0;m<64;m++){ float e=__expf(l[m]-mx); l[m]=e; sum+=e; }
  float inv = 1.f/sum;
  unsigned long long o2[16];
  #pragma unroll
  for (int i=0;i<16;i++) o2[i]=0ull;
  #pragma unroll
  for (int m=0;m<64;m++){
    unsigned long long p2 = pack2(l[m]);
    const ulonglong2* vp = (const ulonglong2*)&sVt[m][0];
    #pragma unroll
    for (int dd=0;dd<8;dd++){
      ulonglong2 vv = vp[dd];
      ffma2(o2[2*dd  ], p2, vv.x);
      ffma2(o2[2*dd+1], p2, vv.y);
    }
  }
  __nv_bfloat16* dst = g_attn + ((size_t)b*HW + hw_t)*96 + h*32;
  #pragma unroll
  for (int k=0;k<8;k++){
    float2 pa=u2f(o2[2*k]), pb=u2f(o2[2*k+1]);
    uint2 u; u.x = bf2u(pa.x*inv, pa.y*inv); u.y = bf2u(pb.x*inv, pb.y*inv);
    *(uint2*)(dst + 4*k) = u;
  }
}

// ---------------- host launch ----------------
extern "C" void kernel_launch(void* const* d_in, const int* in_sizes, int n_in,
                              void* d_out, int out_size){
  const float* x       = (const float*)d_in[0];
  const float* agn_w   = (const float*)d_in[1];
  const float* agn_b   = (const float*)d_in[2];
  const float* meta1_w = (const float*)d_in[3];
  const float* meta1_b = (const float*)d_in[4];
  const float* meta2_w = (const float*)d_in[5];
  const float* meta2_b = (const float*)d_in[6];
  const float* la1_w   = (const float*)d_in[7];
  const float* la1_b   = (const float*)d_in[8];
  const float* la2_w   = (const float*)d_in[9];
  const float* la2_b   = (const float*)d_in[10];
  const float* ta1_w   = (const float*)d_in[11];
  const float* ta1_b   = (const float*)d_in[12];
  const float* ta2_w   = (const float*)d_in[13];
  const float* ta2_b   = (const float*)d_in[14];
  const float* q_w     = (const float*)d_in[15];
  const float* q_b     = (const float*)d_in[16];
  const float* kv_w    = (const float*)d_in[17];
  const float* kv_b    = (const float*)d_in[18];
  const float* dw_w    = (const float*)d_in[19];
  const float* dw_b    = (const float*)d_in[20];
  const float* proj_w  = (const float*)d_in[21];
  const float* proj_b  = (const float*)d_in[22];
  const float* logit_s = (const float*)d_in[23];
  const float* rp_w1   = (const float*)d_in[24];
  const float* rp_b1   = (const float*)d_in[25];
  const float* rp_w2   = (const float*)d_in[26];
  const float* rp_b2   = (const float*)d_in[27];
  const float* m1_w    = (const float*)d_in[28];
  const float* m1_b    = (const float*)d_in[29];
  const float* m2_w    = (const float*)d_in[30];
  const float* m2_b    = (const float*)d_in[31];
  float* out = (float*)d_out;

  cudaFuncSetAttribute(k_mma_qkv, cudaFuncAttributeMaxDynamicSharedMemorySize, SMEM_MMA);
  cudaFuncSetAttribute(k_mma_proj,cudaFuncAttributeMaxDynamicSharedMemorySize, SMEM_MMA);
  cudaFuncSetAttribute(k_mma_m1,  cudaFuncAttributeMaxDynamicSharedMemorySize, SMEM_MMA);
  cudaFuncSetAttribute(k_mma_m2,  cudaFuncAttributeMaxDynamicSharedMemorySize, SMEM_MMA);

  // 1. stats + bias table
  k_reduce_partial<<<dim3(192,BATCH), 256>>>(x);
  k_finalize<<<BATCH, 256>>>(meta1_w, meta1_b, meta2_w, meta2_b);
  k_bias<<<64, 64>>>(rp_w1, rp_b1, rp_w2, rp_b2);

  // 2. fused AGN (writes bf16 g_y)
  dim3 agrid(IMG/128, IMG/8, BATCH*CB);
  k_agn_fused<<<agrid, 256>>>(x, agn_w, agn_b, la1_w, la1_b, la2_w, la2_b,
                              ta1_w, ta1_b, ta2_w, ta2_b);

  // 3. QKV projections
  k_mma_qkv<<<dim3(512,3,BATCH), 256, SMEM_MMA>>>(q_w, q_b, kv_w, kv_b);

  // 4. reflect 5x5 dwconv on Q, then window attention
  dim3 cgrid(IMG/32, IMG/8, BATCH*CB), cblk(32, 8);
  k_co5<<<cgrid, cblk>>>(dw_w, dw_b);
  k_attn<<<dim3(4096,3), 64>>>(logit_s);

  // 5. proj + residual/rescale/rebias -> g_x2 (fp32)
  k_mma_proj<<<dim3(512,1,BATCH), 256, SMEM_MMA>>>(proj_w, proj_b, x);

  // 6. MLP
  k_mma_m1<<<dim3(512,4,BATCH), 256, SMEM_MMA>>>(m1_w, m1_b);
  k_mma_m2<<<dim3(512,1,BATCH), 256, SMEM_MMA>>>(m2_w, m2_b, out);
}

// round 16
// speedup vs baseline: 1.2648x; 1.1479x over previous
#include <cuda_runtime.h>
#include <cuda_bf16.h>
#include <math.h>

#define HW 65536
#define IMG 256
#define CB 96
#define BATCH 4

// ---------------- device scratch ----------------
__device__ float g_mean[BATCH], g_istd[BATCH];
__device__ float g_rescale[BATCH][CB], g_rebias[BATCH][CB];
__device__ float g_partial[BATCH][192][2];
__device__ float g_bias_tab[3][64][64];

__device__ __nv_bfloat16 g_y  [(size_t)BATCH*CB*HW];
__device__ __nv_bfloat16 g_qkv[(size_t)BATCH*3*CB*HW];
__device__ __nv_bfloat16 g_co [(size_t)BATCH*CB*HW];
__device__ __nv_bfloat16 g_attn[(size_t)BATCH*HW*CB];
__device__ float         g_x2 [(size_t)BATCH*CB*HW];
__device__ __nv_bfloat16 g_hid[(size_t)BATCH*4*CB*HW];

#define SCALEV 0.17677669529663687f
#define LOGIT_MAXV 4.605170185988091f

// ---------------- f32x2 helpers ----------------
__device__ __forceinline__ unsigned long long pack2(float w){
  unsigned long long r; asm("mov.b64 %0, {%1, %1};" : "=l"(r) : "f"(w)); return r;
}
__device__ __forceinline__ float2 u2f(unsigned long long v){
  float2 f; asm("mov.b64 {%0, %1}, %2;" : "=f"(f.x), "=f"(f.y) : "l"(v)); return f;
}
__device__ __forceinline__ void ffma2(unsigned long long &d, unsigned long long a, unsigned long long b){
  asm("fma.rn.f32x2 %0, %1, %2, %0;" : "+l"(d) : "l"(a), "l"(b));
}

// ---------------- mma helpers ----------------
__device__ __forceinline__ void ldsm_x4(unsigned addr, unsigned &r0, unsigned &r1, unsigned &r2, unsigned &r3){
  asm volatile("ldmatrix.sync.aligned.m8n8.x4.shared.b16 {%0,%1,%2,%3}, [%4];"
    : "=r"(r0),"=r"(r1),"=r"(r2),"=r"(r3) : "r"(addr));
}
__device__ __forceinline__ void ldsm_x4_t(unsigned addr, unsigned &r0, unsigned &r1, unsigned &r2, unsigned &r3){
  asm volatile("ldmatrix.sync.aligned.m8n8.x4.trans.shared.b16 {%0,%1,%2,%3}, [%4];"
    : "=r"(r0),"=r"(r1),"=r"(r2),"=r"(r3) : "r"(addr));
}
__device__ __forceinline__ void mma16816(float* c, const unsigned* a, const unsigned* b){
  asm volatile("mma.sync.aligned.m16n8k16.row.col.f32.bf16.bf16.f32 "
    "{%0,%1,%2,%3},{%4,%5,%6,%7},{%8,%9},{%0,%1,%2,%3};"
    : "+f"(c[0]),"+f"(c[1]),"+f"(c[2]),"+f"(c[3])
    : "r"(a[0]),"r"(a[1]),"r"(a[2]),"r"(a[3]),"r"(b[0]),"r"(b[1]));
}
__device__ __forceinline__ unsigned bf2u(float x, float y){
  __nv_bfloat162 t = __floats2bfloat162_rn(x, y);
  return reinterpret_cast<unsigned&>(t);
}

// ---------------- K1: per-sample partial sums ----------------
__global__ void k_reduce_partial(const float* __restrict__ x){
  int b = blockIdx.y, blk = blockIdx.x, tid = threadIdx.x;
  const float4* xb = (const float4*)(x + (size_t)b*CB*HW);
  size_t base = (size_t)blk*8192;
  float s=0.f, s2=0.f;
  for (int i=tid;i<8192;i+=256){
    float4 v = xb[base+i];
    s  += v.x+v.y+v.z+v.w;
    s2 += v.x*v.x+v.y*v.y+v.z*v.z+v.w*v.w;
  }
  __shared__ float rs[256], rq[256];
  rs[tid]=s; rq[tid]=s2; __syncthreads();
  for (int st=128;st>0;st>>=1){
    if (tid<st){ rs[tid]+=rs[tid+st]; rq[tid]+=rq[tid+st]; }
    __syncthreads();
  }
  if (tid==0){ g_partial[b][blk][0]=rs[0]; g_partial[b][blk][1]=rq[0]; }
}

// ---------------- K2: finalize ----------------
__global__ void k_finalize(const float* __restrict__ m1w, const float* __restrict__ m1b,
                           const float* __restrict__ m2w, const float* __restrict__ m2b){
  int b = blockIdx.x, tid = threadIdx.x;
  __shared__ float rs[256], rq[256];
  rs[tid] = (tid<192)? g_partial[b][tid][0] : 0.f;
  rq[tid] = (tid<192)? g_partial[b][tid][1] : 0.f;
  __syncthreads();
  for (int st=128;st>0;st>>=1){
    if (tid<st){ rs[tid]+=rs[tid+st]; rq[tid]+=rq[tid+st]; }
    __syncthreads();
  }
  __shared__ float sh_mean, sh_std;
  if (tid==0){
    float M = (float)((size_t)CB*HW);
    float mean = rs[0]/M;
    float var  = rq[0]/M - mean*mean;
    float sd   = sqrtf(var + 1e-5f);
    g_mean[b]=mean; g_istd[b]=1.f/sd;
    sh_mean=mean; sh_std=sd;
  }
  __syncthreads();
  if (tid<CB){
    g_rescale[b][tid] = sh_std *m1w[tid] + m1b[tid];
    g_rebias [b][tid] = sh_mean*m2w[tid] + m2b[tid];
  }
}

// ---------------- K3: relative-position bias table ----------------
__global__ void k_bias(const float* __restrict__ w1, const float* __restrict__ b1,
                       const float* __restrict__ w2, const float* __restrict__ b2){
  int n = blockIdx.x, m = threadIdx.x;
  float di = (float)((n>>3) - (m>>3));
  float dj = (float)((n&7) - (m&7));
  float a0l = log1pf(fabsf(di)); float r0 = di<0.f ? -a0l : (di>0.f ? a0l : 0.f);
  float a1l = log1pf(fabsf(dj)); float r1 = dj<0.f ? -a1l : (dj>0.f ? a1l : 0.f);
  float a0=0.f,a1=0.f,a2=0.f;
  for (int k=0;k<256;k++){
    float h = fmaxf(r0*w1[2*k]+r1*w1[2*k+1]+b1[k], 0.f);
    a0 += h*w2[k]; a1 += h*w2[256+k]; a2 += h*w2[512+k];
  }
  g_bias_tab[0][n][m]=a0+b2[0];
  g_bias_tab[1][n][m]=a1+b2[1];
  g_bias_tab[2][n][m]=a2+b2[2];
}

// ---------------- K4: fused AGN (vectorized loader, R15) ----------------
__global__ void __launch_bounds__(256) k_agn_fused(const float* __restrict__ x,
    const float* __restrict__ agnw, const float* __restrict__ agnb,
    const float* __restrict__ la1w, const float* __restrict__ la1b,
    const float* __restrict__ la2w, const float* __restrict__ la2b,
    const float* __restrict__ ta1w, const float* __restrict__ ta1b,
    const float* __restrict__ ta2w, const float* __restrict__ ta2b){
  __shared__ float xt[12*136];
  __shared__ __align__(8) float2 tb[10*136];
  int bc = blockIdx.z; int b = bc/CB, c = bc - b*CB;
  const float* xb = x + (size_t)bc*HW;
  float mean = g_mean[b], istd = g_istd[b];
  int x0 = blockIdx.x*128, y0 = blockIdx.y*8;
  int tid = threadIdx.x;

  #pragma unroll
  for (int it=0; it<2; it++){
    int i = tid + 256*it;
    if (i < 384){
      int ry = i>>5, m = i&31;
      int gy = y0+ry-2;
      float4 v = make_float4(0.f,0.f,0.f,0.f);
      if ((unsigned)gy<256u) v = *(const float4*)(xb + gy*256 + x0 + 4*m);
      float* row = xt + ry*136;
      row[ 68 + m    ] = (v.x-mean)*istd;
      row[102 + m    ] = (v.y-mean)*istd;
      row[      m + 1] = (v.z-mean)*istd;
      row[ 34 + m + 1] = (v.w-mean)*istd;
    }
  }
  if (tid < 96){
    int ry = tid>>3, e = tid&7;
    int cc = (e<2) ? e : (128+e);
    int gy = y0+ry-2, gx = x0+cc-2;
    float v = 0.f;
    if ((unsigned)gy<256u && (unsigned)gx<256u) v = (xb[gy*256+gx]-mean)*istd;
    xt[ry*136 + ((cc&3)*34 + (cc>>2))] = v;
  }
  float w1l[9], w1t[9];
  #pragma unroll
  for (int k=0;k<9;k++){ w1l[k]=la1w[c*9+k]; w1t[k]=ta1w[c*9+k]; }
  float b1l=la1b[c], b1t=ta1b[c];
  __syncthreads();

  for (int run=tid; run<330; run+=256){
    int r = run/33, rn = run - r*33;
    float al[4], at[4];
    #pragma unroll
    for (int o=0;o<4;o++){ al[o]=b1l; at[o]=b1t; }
    #pragma unroll
    for (int dy=0;dy<3;dy++){
      const float* xr = xt + (r+dy)*136;
      float v[6];
      v[0]=xr[rn]; v[1]=xr[34+rn]; v[2]=xr[68+rn]; v[3]=xr[102+rn];
      v[4]=xr[rn+1]; v[5]=xr[34+rn+1];
      #pragma unroll
      for (int o=0;o<4;o++){
        al[o] += v[o]*w1l[dy*3] + v[o+1]*w1l[dy*3+1] + v[o+2]*w1l[dy*3+2];
        at[o] += v[o]*w1t[dy*3] + v[o+1]*w1t[dy*3+1] + v[o+2]*w1t[dy*3+2];
      }
    }
    float2* tr = tb + r*136;
    #pragma unroll
    for (int o=0;o<4;o++)
      tr[o*34+rn] = make_float2(fmaxf(al[o],0.f), fmaxf(at[o],0.f));
  }
  __syncthreads();

  float w2l[9], w2t[9];
  #pragma unroll
  for (int k=0;k<9;k++){ w2l[k]=la2w[c*9+k]; w2t[k]=ta2w[c*9+k]; }
  int tx = tid&31, ty = tid>>5;
  float acc[4];
  float base2 = la2b[c] + ta2b[c];
  #pragma unroll
  for (int o=0;o<4;o++) acc[o]=base2;
  #pragma unroll
  for (int dy=0;dy<3;dy++){
    const float2* tr = tb + (ty+dy)*136;
    float2 t0=tr[tx], t1=tr[34+tx], t2=tr[68+tx], t3=tr[102+tx];
    float2 t4=tr[tx+1], t5=tr[34+tx+1];
    float2 tv[6] = {t0,t1,t2,t3,t4,t5};
    #pragma unroll
    for (int o=0;o<4;o++){
      #pragma unroll
      for (int dx=0;dx<3;dx++){
        float2 v = tv[o+dx];
        acc[o] += v.x*w2l[dy*3+dx] + v.y*w2t[dy*3+dx];
      }
    }
  }
  float sc = agnw[c]*g_rescale[b][c];
  float sb = agnb[c]+g_rebias[b][c];
  const float* xnr = xt + (ty+2)*136;
  float xn0 = xnr[68+tx], xn1 = xnr[102+tx], xn2 = xnr[tx+1], xn3 = xnr[34+tx+1];
  float r0 = xn0*sc + sb + acc[0];
  float r1 = xn1*sc + sb + acc[1];
  float r2 = xn2*sc + sb + acc[2];
  float r3 = xn3*sc + sb + acc[3];
  uint2 u; u.x = bf2u(r0,r1); u.y = bf2u(r2,r3);
  *(uint2*)(g_y + (size_t)bc*HW + (size_t)(y0+ty)*256 + x0 + 4*tx) = u;
}

// ---------------- K6: 5x5 reflect dwconv on Q (R15) ----------------
__global__ void k_co5(const float* __restrict__ dww, const float* __restrict__ dwb){
  int bc=blockIdx.z; int b=bc/CB, c=bc-b*CB;
  const __nv_bfloat16* Q = g_qkv + ((size_t)b*3*CB + c)*HW;
  __shared__ float tile[12][36];
  int x0=blockIdx.x*32, y0=blockIdx.y*8;
  int tid=threadIdx.y*32+threadIdx.x;
  if (x0>=32 && x0<=192){
    if (tid < 120){
      int ry = tid/10, m = tid - ry*10;
      int gy = y0+ry-2;
      gy = gy<0 ? -gy : (gy>255 ? 510-gy : gy);
      uint2 q = *(const uint2*)(Q + gy*256 + (x0-4) + 4*m);
      const __nv_bfloat16* qp = (const __nv_bfloat16*)&q;
      int cc = 4*m - 2;
      #pragma unroll
      for (int e=0;e<4;e++){
        int ce = cc+e;
        if ((unsigned)ce < 36u) tile[ry][ce] = __bfloat162float(qp[e]);
      }
    }
  } else {
    for (int i=tid;i<432;i+=256){
      int ry=i/36, rx=i-ry*36;
      int gy=y0+ry-2, gx=x0+rx-2;
      gy = gy<0 ? -gy : (gy>255 ? 510-gy : gy);
      gx = gx<0 ? -gx : (gx>255 ? 510-gx : gx);
      tile[ry][rx] = __bfloat162float(Q[gy*256+gx]);
    }
  }
  __syncthreads();
  float w[25];
  #pragma unroll
  for (int k=0;k<25;k++) w[k]=dww[c*25+k];
  float acc = dwb[c];
  #pragma unroll
  for (int ky=0;ky<5;ky++)
    #pragma unroll
    for (int kx=0;kx<5;kx++)
      acc += tile[threadIdx.y+ky][threadIdx.x+kx]*w[ky*5+kx];
  g_co[(size_t)bc*HW + (size_t)(y0+threadIdx.y)*256 + x0+threadIdx.x] = __float2bfloat16(acc);
}

// =====================================================================
// Tensor-core GEMM (R14/R15 structure)
// =====================================================================
#define SMEM_MMA 50688

template<int LOAD, int EPI>
__device__ __forceinline__ void mma_body(
    const void* actb, const float* W, const float* bias,
    int CinTot, int wrow0, void* outv,
    const float* xinb, int bIdx)
{
  extern __shared__ char smem_raw[];
  __nv_bfloat16* sA = (__nv_bfloat16*)smem_raw;
  __nv_bfloat16* sW = (__nv_bfloat16*)(smem_raw + (LOAD==2 ? 26624 : 24576));
  float* sStage = (float*)smem_raw;
  const int tid = threadIdx.x;
  const int px0 = blockIdx.x * 128;
  const int warp = tid >> 5, t = tid & 31;
  const int m0w = (warp>>1)*32, n0w = (warp&1)*48;
  unsigned sAb = (unsigned)__cvta_generic_to_shared(sA);
  unsigned sWb = (unsigned)__cvta_generic_to_shared(sW);

  float acc[2][6][4];
  #pragma unroll
  for (int mi=0;mi<2;mi++)
    #pragma unroll
    for (int nj=0;nj<6;nj++)
      #pragma unroll
      for (int e=0;e<4;e++) acc[mi][nj][e]=0.f;

  const int g = t>>3, gi = t&7;

  for (int k0g=0; k0g<CinTot; k0g+=96){
    if (LOAD==0){
      const float* a = (const float*)actb;
      #pragma unroll
      for (int j=0;j<12;j++){
        int i = tid + 256*j;
        int c = i>>5, px = (i&31)*4;
        float4 v = *(const float4*)(a + (size_t)(k0g+c)*HW + px0 + px);
        uint2 u; u.x = bf2u(v.x,v.y); u.y = bf2u(v.z,v.w);
        *(uint2*)(sA + c*128 + ((((px>>3)^(c&7))<<3) + (px&7))) = u;
      }
    } else if (LOAD==1){
      const __nv_bfloat16* a = (const __nv_bfloat16*)actb;
      #pragma unroll
      for (int j=0;j<6;j++){
        int i = tid + 256*j;
        int c = i>>4, s8 = (i&15)*8;
        uint4 v = *(const uint4*)(a + (size_t)(k0g+c)*HW + px0 + s8);
        *(uint4*)(sA + c*128 + ((((s8>>3)^(c&7))<<3))) = v;
      }
    } else {
      const __nv_bfloat16* a = (const __nv_bfloat16*)actb + (size_t)px0*96;
      #pragma unroll
      for (int j=0;j<6;j++){
        int i = tid + 256*j;
        int px = i/12, c0 = (i%12)*8;
        uint4 v = *(const uint4*)(a + (size_t)px*96 + c0);
        *(uint4*)(sA + px*104 + c0) = v;
      }
    }
    #pragma unroll
    for (int j=0;j<9;j++){
      int i = tid + 256*j;
      int r = i/24, c4 = (i%24)*4;
      float4 v = *(const float4*)(W + (size_t)(wrow0+r)*CinTot + k0g + c4);
      uint2 u; u.x = bf2u(v.x,v.y); u.y = bf2u(v.z,v.w);
      *(uint2*)(sW + r*104 + c4) = u;
    }
    __syncthreads();

    unsigned addrA[2], addrB[3];
    if (LOAD==2){
      int row0 = m0w + (g&1)*8 + gi;
      int kc = (g>=2)?16:0;
      addrA[0] = sAb + (row0     )*208 + kc;
      addrA[1] = sAb + (row0 + 16)*208 + kc;
    } else {
      int kb = ((g>=2)?8:0) + gi;
      int px_a0 = m0w + (g&1)*8;
      int px_a1 = px_a0 + 16;
      addrA[0] = sAb + kb*256 + ((((px_a0>>3) ^ gi)<<4));
      addrA[1] = sAb + kb*256 + ((((px_a1>>3) ^ gi)<<4));
    }
    {
      int nb = n0w + (t&7) + ((t>>4)<<3);
      int kcb = ((t>>3)&1)*8;
      #pragma unroll
      for (int p=0;p<3;p++) addrB[p] = sWb + (nb + p*16)*208 + kcb*2;
    }

    #pragma unroll
    for (int ks=0; ks<6; ks++){
      unsigned a[2][4], br[3][4];
      if (LOAD==2){ ldsm_x4(addrA[0], a[0][0],a[0][1],a[0][2],a[0][3]);
                    ldsm_x4(addrA[1], a[1][0],a[1][1],a[1][2],a[1][3]); }
      else        { ldsm_x4_t(addrA[0], a[0][0],a[0][1],a[0][2],a[0][3]);
                    ldsm_x4_t(addrA[1], a[1][0],a[1][1],a[1][2],a[1][3]); }
      #pragma unroll
      for (int p=0;p<3;p++) ldsm_x4(addrB[p], br[p][0],br[p][1],br[p][2],br[p][3]);
      #pragma unroll
      for (int mi=0;mi<2;mi++)
        #pragma unroll
        for (int nj=0;nj<6;nj++)
          mma16816(acc[mi][nj], a[mi], &br[nj>>1][(nj&1)*2]);
      if (LOAD==2){ addrA[0]+=32; addrA[1]+=32; }
      else        { addrA[0]+=4096; addrA[1]+=4096; }
      #pragma unroll
      for (int p=0;p<3;p++) addrB[p]+=32;
    }
    __syncthreads();
  }

  #pragma unroll
  for (int mi=0;mi<2;mi++)
    #pragma unroll
    for (int nj=0;nj<6;nj++){
      int m = m0w + mi*16 + (t>>2);
      int n = n0w + nj*8 + (t&3)*2;
      sStage[(n  )*132 + m  ] = acc[mi][nj][0];
      sStage[(n+1)*132 + m  ] = acc[mi][nj][1];
      sStage[(n  )*132 + m+8] = acc[mi][nj][2];
      sStage[(n+1)*132 + m+8] = acc[mi][nj][3];
    }
  __syncthreads();

  const int tx = tid&31, ty = tid>>5;
  #pragma unroll
  for (int r=0;r<12;r++){
    int o = ty*12 + r;
    float4 v = *(float4*)(sStage + o*132 + tx*4);
    float bv = bias[wrow0+o];
    v.x+=bv; v.y+=bv; v.z+=bv; v.w+=bv;
    size_t off = (size_t)o*HW + px0 + tx*4;
    if (EPI==0){
      *(float4*)((float*)outv + off) = v;
    } else if (EPI==1){
      v.x=fmaxf(v.x,0.f); v.y=fmaxf(v.y,0.f); v.z=fmaxf(v.z,0.f); v.w=fmaxf(v.w,0.f);
      uint2 u; u.x = bf2u(v.x,v.y); u.y = bf2u(v.z,v.w);
      *(uint2*)((__nv_bfloat16*)outv + off) = u;
    } else if (EPI==2){
      float4 q = *(const float4*)(xinb + off);
      v.x+=q.x; v.y+=q.y; v.z+=q.z; v.w+=q.w;
      *(float4*)((float*)outv + off) = v;
    } else if (EPI==3){
      float rs = g_rescale[bIdx][o], rb = g_rebias[bIdx][o];
      float4 xi = *(const float4*)(xinb + off);
      v = make_float4(xi.x + v.x*rs + rb, xi.y + v.y*rs + rb,
                      xi.z + v.z*rs + rb, xi.w + v.w*rs + rb);
      *(float4*)((float*)outv + off) = v;
    } else {
      uint2 u; u.x = bf2u(v.x,v.y); u.y = bf2u(v.z,v.w);
      *(uint2*)((__nv_bfloat16*)outv + off) = u;
    }
  }
}

__global__ void __launch_bounds__(256) k_mma_qkv(
    const float* __restrict__ qW, const float* __restrict__ qb,
    const float* __restrict__ kvW, const float* __restrict__ kvb)
{
  int b = blockIdx.z, gy = blockIdx.y;
  const __nv_bfloat16* actb = g_y + (size_t)b*CB*HW;
  __nv_bfloat16* outb = g_qkv + ((size_t)b*3*CB + gy*96)*HW;
  if (gy==0) mma_body<1,4>(actb, qW, qb, 96, 0, outb, nullptr, b);
  else       mma_body<1,4>(actb, kvW, kvb, 96, (gy-1)*96, outb, nullptr, b);
}

__global__ void __launch_bounds__(256) k_mma_proj(
    const float* __restrict__ W, const float* __restrict__ bias,
    const float* __restrict__ xin)
{
  int b = blockIdx.z;
  const __nv_bfloat16* actb = g_attn + (size_t)b*HW*96;
  mma_body<2,3>(actb, W, bias, 96, 0, g_x2 + (size_t)b*CB*HW,
                xin + (size_t)b*CB*HW, b);
}

__global__ void __launch_bounds__(256) k_mma_m1(
    const float* __restrict__ W, const float* __restrict__ bias)
{
  int b = blockIdx.z, gy = blockIdx.y;
  mma_body<0,1>(g_x2 + (size_t)b*CB*HW, W, bias, 96, gy*96,
                g_hid + ((size_t)b*4*CB + gy*96)*HW, nullptr, b);
}

__global__ void __launch_bounds__(256) k_mma_m2(
    const float* __restrict__ W, const float* __restrict__ bias,
    float* __restrict__ out)
{
  int b = blockIdx.z;
  mma_body<1,2>(g_hid + (size_t)b*4*CB*HW, W, bias, 384, 0,
                out + (size_t)b*CB*HW, g_x2 + (size_t)b*CB*HW, b);
}

// =====================================================================
// Tensor-core window attention: 1 block (128 thr, 4 warps) per window,
// head loop x3. QK^T and PV via mma.m16n8k16; softmax in fp32 fragments.
// =====================================================================
__global__ void __launch_bounds__(128) k_attn(const float* __restrict__ lsp){
  __shared__ __nv_bfloat16 sQ[64*40];   // [tok][d] pitch 40
  __shared__ __nv_bfloat16 sK[64*40];   // [tok][d] pitch 40
  __shared__ __nv_bfloat16 sV[32*72];   // [d][tok] pitch 72
  int widx = blockIdx.x;
  int b = widx>>10, rem = widx&1023;
  int r0 = (rem>>5)*8, c0 = (rem&31)*8;
  int tid = threadIdx.x;
  int warp = tid>>5, t = tid&31;
  int m0w = warp*16;
  float scl = __expf(fminf(lsp[0], LOGIT_MAXV)) * SCALEV;
  unsigned sQb = (unsigned)__cvta_generic_to_shared(sQ);
  unsigned sKb = (unsigned)__cvta_generic_to_shared(sK);
  unsigned sVb = (unsigned)__cvta_generic_to_shared(sV);

  // lane addressing (constant across heads)
  unsigned addrQ0 = sQb + (m0w + (t&15))*80 + ((t>>4)&1)*16;   // k-half 0; +32 for kh1
  const int nbv = (t&7) + ((t>>4)<<3);
  const int kcb = ((t>>3)&1)*8;
  unsigned addrK0 = sKb + nbv*80  + kcb*2;   // + p*16*80  + kh*32
  unsigned addrV0 = sVb + nbv*144 + kcb*2;   // + p*16*144 + kt*32

  const int rA = (t>>2), cb2 = (t&3)*2;

  for (int h=0; h<3; h++){
    size_t baseQ = ((size_t)b*CB      + h*32)*HW;
    size_t baseK = ((size_t)b*3*CB +   CB + h*32)*HW;
    size_t baseV = ((size_t)b*3*CB + 2*CB + h*32)*HW;
    // ---- stage Q/K/V ----
    #pragma unroll
    for (int j=tid; j<256; j+=128){
      int d=j>>3, seg=j&7;
      size_t rowoff = (size_t)d*HW + (size_t)(r0+seg)*256 + c0;
      uint4 qv = *(const uint4*)(g_co + baseQ + rowoff);
      const __nv_bfloat16* qp = (const __nv_bfloat16*)&qv;
      #pragma unroll
      for (int e=0;e<8;e++) sQ[(seg*8+e)*40 + d] = qp[e];
      uint4 kv = *(const uint4*)(g_qkv + baseK + rowoff);
      const __nv_bfloat16* kp = (const __nv_bfloat16*)&kv;
      #pragma unroll
      for (int e=0;e<8;e++) sK[(seg*8+e)*40 + d] = kp[e];
      *(uint4*)(sV + d*72 + seg*8) = *(const uint4*)(g_qkv + baseV + rowoff);
    }
    __syncthreads();

    // ---- QK^T: S[m16][n64] over k=32 ----
    float s[8][4];
    #pragma unroll
    for (int nj=0;nj<8;nj++){ s[nj][0]=0.f; s[nj][1]=0.f; s[nj][2]=0.f; s[nj][3]=0.f; }
    unsigned a[2][4];
    ldsm_x4(addrQ0,      a[0][0],a[0][1],a[0][2],a[0][3]);
    ldsm_x4(addrQ0 + 32, a[1][0],a[1][1],a[1][2],a[1][3]);
    #pragma unroll
    for (int kh=0; kh<2; kh++){
      unsigned brk[4][4];
      #pragma unroll
      for (int p=0;p<4;p++)
        ldsm_x4(addrK0 + p*16*80 + kh*32, brk[p][0],brk[p][1],brk[p][2],brk[p][3]);
      #pragma unroll
      for (int nj=0;nj<8;nj++)
        mma16816(s[nj], a[kh], &brk[nj>>1][(nj&1)*2]);
    }

    // ---- bias + scale + softmax (rows mA = m0w+rA, mB = mA+8) ----
    int mA = m0w + rA, mB = mA + 8;
    const float* bA = &g_bias_tab[h][mA][0];
    const float* bB = &g_bias_tab[h][mB][0];
    float mxA = -1e30f, mxB = -1e30f;
    #pragma unroll
    for (int nj=0;nj<8;nj++){
      float2 vA = *(const float2*)(bA + nj*8 + cb2);
      float2 vB = *(const float2*)(bB + nj*8 + cb2);
      s[nj][0] = s[nj][0]*scl + vA.x;
      s[nj][1] = s[nj][1]*scl + vA.y;
      s[nj][2] = s[nj][2]*scl + vB.x;
      s[nj][3] = s[nj][3]*scl + vB.y;
      mxA = fmaxf(mxA, fmaxf(s[nj][0], s[nj][1]));
      mxB = fmaxf(mxB, fmaxf(s[nj][2], s[nj][3]));
    }
    mxA = fmaxf(mxA, __shfl_xor_sync(0xffffffffu, mxA, 1));
    mxA = fmaxf(mxA, __shfl_xor_sync(0xffffffffu, mxA, 2));
    mxB = fmaxf(mxB, __shfl_xor_sync(0xffffffffu, mxB, 1));
    mxB = fmaxf(mxB, __shfl_xor_sync(0xffffffffu, mxB, 2));
    float smA = 0.f, smB = 0.f;
    #pragma unroll
    for (int nj=0;nj<8;nj++){
      s[nj][0] = __expf(s[nj][0]-mxA); s[nj][1] = __expf(s[nj][1]-mxA);
      s[nj][2] = __expf(s[nj][2]-mxB); s[nj][3] = __expf(s[nj][3]-mxB);
      smA += s[nj][0]+s[nj][1];
      smB += s[nj][2]+s[nj][3];
    }
    smA += __shfl_xor_sync(0xffffffffu, smA, 1);
    smA += __shfl_xor_sync(0xffffffffu, smA, 2);
    smB += __shfl_xor_sync(0xffffffffu, smB, 1);
    smB += __shfl_xor_sync(0xffffffffu, smB, 2);
    float invA = 1.f/smA, invB = 1.f/smB;

    // ---- PV: O[m16][n32] over k=64, P from accumulators ----
    float o[4][4];
    #pragma unroll
    for (int nj=0;nj<4;nj++){ o[nj][0]=0.f; o[nj][1]=0.f; o[nj][2]=0.f; o[nj][3]=0.f; }
    #pragma unroll
    for (int kt=0; kt<4; kt++){
      unsigned pa[4];
      pa[0] = bf2u(s[2*kt  ][0], s[2*kt  ][1]);
      pa[1] = bf2u(s[2*kt  ][2], s[2*kt  ][3]);
      pa[2] = bf2u(s[2*kt+1][0], s[2*kt+1][1]);
      pa[3] = bf2u(s[2*kt+1][2], s[2*kt+1][3]);
      unsigned bv[2][4];
      #pragma unroll
      for (int p=0;p<2;p++)
        ldsm_x4(addrV0 + p*16*144 + kt*32, bv[p][0],bv[p][1],bv[p][2],bv[p][3]);
      #pragma unroll
      for (int nj=0;nj<4;nj++)
        mma16816(o[nj], pa, &bv[nj>>1][(nj&1)*2]);
    }

    // ---- writeout ----
    {
      int hwA = (r0 + (mA>>3))*256 + c0 + (mA&7);
      int hwB = (r0 + (mB>>3))*256 + c0 + (mB&7);
      __nv_bfloat16* dA = g_attn + ((size_t)b*HW + hwA)*96 + h*32;
      __nv_bfloat16* dB = g_attn + ((size_t)b*HW + hwB)*96 + h*32;
      #pragma unroll
      for (int nj=0;nj<4;nj++){
        *(unsigned*)(dA + nj*8 + cb2) = bf2u(o[nj][0]*invA, o[nj][1]*invA);
        *(unsigned*)(dB + nj*8 + cb2) = bf2u(o[nj][2]*invB, o[nj][3]*invB);
      }
    }
    __syncthreads();
  }
}

// ---------------- host launch ----------------
extern "C" void kernel_launch(void* const* d_in, const int* in_sizes, int n_in,
                              void* d_out, int out_size){
  const float* x       = (const float*)d_in[0];
  const float* agn_w   = (const float*)d_in[1];
  const float* agn_b   = (const float*)d_in[2];
  const float* meta1_w = (const float*)d_in[3];
  const float* meta1_b = (const float*)d_in[4];
  const float* meta2_w = (const float*)d_in[5];
  const float* meta2_b = (const float*)d_in[6];
  const float* la1_w   = (const float*)d_in[7];
  const float* la1_b   = (const float*)d_in[8];
  const float* la2_w   = (const float*)d_in[9];
  const float* la2_b   = (const float*)d_in[10];
  const float* ta1_w   = (const float*)d_in[11];
  const float* ta1_b   = (const float*)d_in[12];
  const float* ta2_w   = (const float*)d_in[13];
  const float* ta2_b   = (const float*)d_in[14];
  const float* q_w     = (const float*)d_in[15];
  const float* q_b     = (const float*)d_in[16];
  const float* kv_w    = (const float*)d_in[17];
  const float* kv_b    = (const float*)d_in[18];
  const float* dw_w    = (const float*)d_in[19];
  const float* dw_b    = (const float*)d_in[20];
  const float* proj_w  = (const float*)d_in[21];
  const float* proj_b  = (const float*)d_in[22];
  const float* logit_s = (const float*)d_in[23];
  const float* rp_w1   = (const float*)d_in[24];
  const float* rp_b1   = (const float*)d_in[25];
  const float* rp_w2   = (const float*)d_in[26];
  const float* rp_b2   = (const float*)d_in[27];
  const float* m1_w    = (const float*)d_in[28];
  const float* m1_b    = (const float*)d_in[29];
  const float* m2_w    = (const float*)d_in[30];
  const float* m2_b    = (const float*)d_in[31];
  float* out = (float*)d_out;

  cudaFuncSetAttribute(k_mma_qkv, cudaFuncAttributeMaxDynamicSharedMemorySize, SMEM_MMA);
  cudaFuncSetAttribute(k_mma_proj,cudaFuncAttributeMaxDynamicSharedMemorySize, SMEM_MMA);
  cudaFuncSetAttribute(k_mma_m1,  cudaFuncAttributeMaxDynamicSharedMemorySize, SMEM_MMA);
  cudaFuncSetAttribute(k_mma_m2,  cudaFuncAttributeMaxDynamicSharedMemorySize, SMEM_MMA);

  // 1. stats + bias table
  k_reduce_partial<<<dim3(192,BATCH), 256>>>(x);
  k_finalize<<<BATCH, 256>>>(meta1_w, meta1_b, meta2_w, meta2_b);
  k_bias<<<64, 64>>>(rp_w1, rp_b1, rp_w2, rp_b2);

  // 2. fused AGN (writes bf16 g_y)
  dim3 agrid(IMG/128, IMG/8, BATCH*CB);
  k_agn_fused<<<agrid, 256>>>(x, agn_w, agn_b, la1_w, la1_b, la2_w, la2_b,
                              ta1_w, ta1_b, ta2_w, ta2_b);

  // 3. QKV projections
  k_mma_qkv<<<dim3(512,3,BATCH), 256, SMEM_MMA>>>(q_w, q_b, kv_w, kv_b);

  // 4. reflect 5x5 dwconv on Q, then tensor-core window attention
  dim3 cgrid(IMG/32, IMG/8, BATCH*CB), cblk(32, 8);
  k_co5<<<cgrid, cblk>>>(dw_w, dw_b);
  k_attn<<<4096, 128>>>(logit_s);

  // 5. proj + residual/rescale/rebias -> g_x2 (fp32)
  k_mma_proj<<<dim3(512,1,BATCH), 256, SMEM_MMA>>>(proj_w, proj_b, x);

  // 6. MLP
  k_mma_m1<<<dim3(512,4,BATCH), 256, SMEM_MMA>>>(m1_w, m1_b);
  k_mma_m2<<<dim3(512,1,BATCH), 256, SMEM_MMA>>>(m2_w, m2_b, out);
}